// round 1
// baseline (speedup 1.0000x reference)
#include <cuda_runtime.h>
#include <math.h>

// Problem constants
#define BB   2
#define NN   2048
#define LL   2048
#define DQ   1024
#define HH   16
#define HD   64
#define MROWS (BB*NN)          // 4096
#define DFF  (4*DQ)            // 4096

// ---------------------------------------------------------------------------
// Scratch: one big __device__ global (no allocation allowed in kernel_launch)
// layout (floats): xqn 4M | xkvn 4M | q 4M | k 4M | v 4M | att 4M | h 16M
// ---------------------------------------------------------------------------
#define MB4 (4u*1024u*1024u)
__device__ float g_scratch[40u*1024u*1024u];

// ---------------------------------------------------------------------------
// LayerNorm: one block per row of 1024, 256 threads
// ---------------------------------------------------------------------------
__global__ void ln_kernel(const float* __restrict__ x,
                          const float* __restrict__ g,
                          const float* __restrict__ b,
                          float* __restrict__ y) {
    int row = blockIdx.x;
    const float* xr = x + (size_t)row * DQ;
    float v[4];
    float s = 0.f, s2 = 0.f;
#pragma unroll
    for (int i = 0; i < 4; i++) {
        float t = xr[threadIdx.x + i * 256];
        v[i] = t; s += t; s2 += t * t;
    }
#pragma unroll
    for (int o = 16; o > 0; o >>= 1) {
        s  += __shfl_xor_sync(0xffffffffu, s,  o);
        s2 += __shfl_xor_sync(0xffffffffu, s2, o);
    }
    __shared__ float ws[8], ws2[8];
    int w = threadIdx.x >> 5, lane = threadIdx.x & 31;
    if (lane == 0) { ws[w] = s; ws2[w] = s2; }
    __syncthreads();
    if (w == 0) {
        s  = (lane < 8) ? ws[lane]  : 0.f;
        s2 = (lane < 8) ? ws2[lane] : 0.f;
#pragma unroll
        for (int o = 4; o > 0; o >>= 1) {
            s  += __shfl_xor_sync(0xffffffffu, s,  o);
            s2 += __shfl_xor_sync(0xffffffffu, s2, o);
        }
        if (lane == 0) { ws[0] = s; ws2[0] = s2; }
    }
    __syncthreads();
    float mean = ws[0] * (1.f / DQ);
    float var  = ws2[0] * (1.f / DQ) - mean * mean;
    float rstd = rsqrtf(var + 1e-5f);
    float* yr = y + (size_t)row * DQ;
#pragma unroll
    for (int i = 0; i < 4; i++) {
        int c = threadIdx.x + i * 256;
        yr[c] = (v[i] - mean) * rstd * g[c] + b[c];
    }
}

// ---------------------------------------------------------------------------
// SGEMM: C[M,N] = A[M,K] @ W[N,K]^T + bias[N]  (+ epilogue)
// EPI: 0 = bias, 1 = bias + res[m,n], 2 = bias + exact GELU, 3 = bias + C (rmw)
// BM=BN=128, BK=16, 256 threads, 8x8 per thread. M,N,K all multiples of 128/16.
// ---------------------------------------------------------------------------
__device__ __forceinline__ float gelu_exact(float x) {
    return 0.5f * x * (1.f + erff(x * 0.7071067811865476f));
}

template <int EPI>
__global__ void __launch_bounds__(256, 2)
sgemm_kernel(const float* __restrict__ A, const float* __restrict__ W,
             const float* __restrict__ bias, const float* __restrict__ res,
             float* __restrict__ C, int M, int N, int K) {
    __shared__ float As[16][128];
    __shared__ float Ws[16][128];
    const int tid = threadIdx.x;
    const int tx = tid & 15, ty = tid >> 4;
    const int bx = blockIdx.x, by = blockIdx.y;

    const float* Ablk = A + (size_t)(by * 128) * K;
    const float* Wblk = W + (size_t)(bx * 128) * K;
    const int lrow = tid >> 1;
    const int lk   = (tid & 1) * 8;

    float c[8][8];
#pragma unroll
    for (int i = 0; i < 8; i++)
#pragma unroll
        for (int j = 0; j < 8; j++) c[i][j] = 0.f;

    for (int kt = 0; kt < K; kt += 16) {
        float4 a0 = *(const float4*)(Ablk + (size_t)lrow * K + kt + lk);
        float4 a1 = *(const float4*)(Ablk + (size_t)lrow * K + kt + lk + 4);
        float4 w0 = *(const float4*)(Wblk + (size_t)lrow * K + kt + lk);
        float4 w1 = *(const float4*)(Wblk + (size_t)lrow * K + kt + lk + 4);
        __syncthreads();
        As[lk + 0][lrow] = a0.x; As[lk + 1][lrow] = a0.y;
        As[lk + 2][lrow] = a0.z; As[lk + 3][lrow] = a0.w;
        As[lk + 4][lrow] = a1.x; As[lk + 5][lrow] = a1.y;
        As[lk + 6][lrow] = a1.z; As[lk + 7][lrow] = a1.w;
        Ws[lk + 0][lrow] = w0.x; Ws[lk + 1][lrow] = w0.y;
        Ws[lk + 2][lrow] = w0.z; Ws[lk + 3][lrow] = w0.w;
        Ws[lk + 4][lrow] = w1.x; Ws[lk + 5][lrow] = w1.y;
        Ws[lk + 6][lrow] = w1.z; Ws[lk + 7][lrow] = w1.w;
        __syncthreads();
#pragma unroll
        for (int k = 0; k < 16; k++) {
            float4 av0 = *(const float4*)&As[k][ty * 4];
            float4 av1 = *(const float4*)&As[k][ty * 4 + 64];
            float4 bv0 = *(const float4*)&Ws[k][tx * 4];
            float4 bv1 = *(const float4*)&Ws[k][tx * 4 + 64];
            float a[8] = {av0.x, av0.y, av0.z, av0.w, av1.x, av1.y, av1.z, av1.w};
            float b[8] = {bv0.x, bv0.y, bv0.z, bv0.w, bv1.x, bv1.y, bv1.z, bv1.w};
#pragma unroll
            for (int i = 0; i < 8; i++)
#pragma unroll
                for (int j = 0; j < 8; j++) c[i][j] = fmaf(a[i], b[j], c[i][j]);
        }
    }

#pragma unroll
    for (int i = 0; i < 8; i++) {
        int row = by * 128 + ((i < 4) ? (ty * 4 + i) : (64 + ty * 4 + i - 4));
#pragma unroll
        for (int j = 0; j < 8; j++) {
            int col = bx * 128 + ((j < 4) ? (tx * 4 + j) : (64 + tx * 4 + j - 4));
            size_t idx = (size_t)row * N + col;
            float v = c[i][j] + bias[col];
            if (EPI == 1) v += res[idx];
            if (EPI == 2) v = gelu_exact(v);
            if (EPI == 3) v += C[idx];
            C[idx] = v;
        }
    }
}

// ---------------------------------------------------------------------------
// Flash attention with softmax-1 (implicit zero logit): init m=0, l=1.
// Block: 256 threads, tile 64 q-rows x 64 kv-cols, HD=64.
// grid: (N/64, H, B)
// ---------------------------------------------------------------------------
#define SMEM_ATTN ((3 * 64 * 64 + 64 * 65) * 4)

__global__ void __launch_bounds__(256)
attn_kernel(const float* __restrict__ q, const float* __restrict__ k,
            const float* __restrict__ v, float* __restrict__ o) {
    extern __shared__ float sm[];
    float* Qts = sm;                 // [64 d][64 row]
    float* Kts = sm + 4096;          // [64 d][64 col]
    float* Vs  = sm + 8192;          // [64 j][64 d]
    float* Ps  = sm + 12288;         // [64 row][65]

    const int tid = threadIdx.x;
    const int tx = tid & 15, ty = tid >> 4;
    const int b = blockIdx.z, h = blockIdx.y, n0 = blockIdx.x * 64;
    const int lj = tid >> 2;            // 0..63
    const int ld = (tid & 3) * 16;      // 0,16,32,48
    const float scale = 0.125f;         // 1/sqrt(64)

    // Load + transpose + scale Q tile
    {
        const float* qp = q + ((size_t)(b * NN + n0 + lj)) * DQ + h * HD + ld;
#pragma unroll
        for (int p = 0; p < 16; p += 4) {
            float4 t = *(const float4*)(qp + p);
            Qts[(ld + p + 0) * 64 + lj] = t.x * scale;
            Qts[(ld + p + 1) * 64 + lj] = t.y * scale;
            Qts[(ld + p + 2) * 64 + lj] = t.z * scale;
            Qts[(ld + p + 3) * 64 + lj] = t.w * scale;
        }
    }

    float m_[4], l_[4], acc[4][4];
#pragma unroll
    for (int i = 0; i < 4; i++) {
        m_[i] = 0.f; l_[i] = 1.f;
#pragma unroll
        for (int j = 0; j < 4; j++) acc[i][j] = 0.f;
    }

    for (int l0 = 0; l0 < LL; l0 += 64) {
        __syncthreads();
        {
            const float* kp = k + ((size_t)(b * LL + l0 + lj)) * DQ + h * HD + ld;
            const float* vp = v + ((size_t)(b * LL + l0 + lj)) * DQ + h * HD + ld;
#pragma unroll
            for (int p = 0; p < 16; p += 4) {
                float4 t = *(const float4*)(kp + p);
                Kts[(ld + p + 0) * 64 + lj] = t.x;
                Kts[(ld + p + 1) * 64 + lj] = t.y;
                Kts[(ld + p + 2) * 64 + lj] = t.z;
                Kts[(ld + p + 3) * 64 + lj] = t.w;
                float4 u = *(const float4*)(vp + p);
                *(float4*)&Vs[lj * 64 + ld + p] = u;
            }
        }
        __syncthreads();

        // S = Q K^T (scaled)
        float s[4][4];
#pragma unroll
        for (int i = 0; i < 4; i++)
#pragma unroll
            for (int j = 0; j < 4; j++) s[i][j] = 0.f;
#pragma unroll 8
        for (int d = 0; d < 64; d++) {
            float4 qa = *(const float4*)&Qts[d * 64 + ty * 4];
            float4 kb = *(const float4*)&Kts[d * 64 + tx * 4];
            float a[4] = {qa.x, qa.y, qa.z, qa.w};
            float bv[4] = {kb.x, kb.y, kb.z, kb.w};
#pragma unroll
            for (int i = 0; i < 4; i++)
#pragma unroll
                for (int j = 0; j < 4; j++) s[i][j] = fmaf(a[i], bv[j], s[i][j]);
        }

        // Online softmax-1 update (rows owned by 16 lanes sharing ty)
#pragma unroll
        for (int i = 0; i < 4; i++) {
            float mx = fmaxf(fmaxf(s[i][0], s[i][1]), fmaxf(s[i][2], s[i][3]));
#pragma unroll
            for (int o2 = 1; o2 < 16; o2 <<= 1)
                mx = fmaxf(mx, __shfl_xor_sync(0xffffffffu, mx, o2));
            float mn = fmaxf(m_[i], mx);
            float corr = __expf(m_[i] - mn);
            float ps = 0.f;
#pragma unroll
            for (int j = 0; j < 4; j++) {
                float p = __expf(s[i][j] - mn);
                s[i][j] = p; ps += p;
            }
#pragma unroll
            for (int o2 = 1; o2 < 16; o2 <<= 1)
                ps += __shfl_xor_sync(0xffffffffu, ps, o2);
            l_[i] = l_[i] * corr + ps;
            m_[i] = mn;
#pragma unroll
            for (int j = 0; j < 4; j++) acc[i][j] *= corr;
#pragma unroll
            for (int j = 0; j < 4; j++) Ps[(ty * 4 + i) * 65 + tx * 4 + j] = s[i][j];
        }
        __syncthreads();

        // acc += P @ V
#pragma unroll 4
        for (int kk = 0; kk < 64; kk++) {
            float4 vv = *(const float4*)&Vs[kk * 64 + tx * 4];
#pragma unroll
            for (int i = 0; i < 4; i++) {
                float p = Ps[(ty * 4 + i) * 65 + kk];
                acc[i][0] = fmaf(p, vv.x, acc[i][0]);
                acc[i][1] = fmaf(p, vv.y, acc[i][1]);
                acc[i][2] = fmaf(p, vv.z, acc[i][2]);
                acc[i][3] = fmaf(p, vv.w, acc[i][3]);
            }
        }
    }

    // epilogue: o = acc / l
#pragma unroll
    for (int i = 0; i < 4; i++) {
        float inv = 1.f / l_[i];
        int row = n0 + ty * 4 + i;
        float4 out;
        out.x = acc[i][0] * inv; out.y = acc[i][1] * inv;
        out.z = acc[i][2] * inv; out.w = acc[i][3] * inv;
        *(float4*)(o + ((size_t)(b * NN) + row) * DQ + h * HD + tx * 4) = out;
    }
}

// ---------------------------------------------------------------------------
// kernel_launch
// inputs: x_q, x_kv, qn_g, qn_b, kvn_g, kvn_b, Wq, bq, Wk, bk, Wv, bv,
//         Wo, bo, n2_g, n2_b, W1, b1, W2, b2
// ---------------------------------------------------------------------------
extern "C" void kernel_launch(void* const* d_in, const int* in_sizes, int n_in,
                              void* d_out, int out_size) {
    const float* x_q   = (const float*)d_in[0];
    const float* x_kv  = (const float*)d_in[1];
    const float* qn_g  = (const float*)d_in[2];
    const float* qn_b  = (const float*)d_in[3];
    const float* kvn_g = (const float*)d_in[4];
    const float* kvn_b = (const float*)d_in[5];
    const float* Wq    = (const float*)d_in[6];
    const float* bq    = (const float*)d_in[7];
    const float* Wk    = (const float*)d_in[8];
    const float* bk    = (const float*)d_in[9];
    const float* Wv    = (const float*)d_in[10];
    const float* bv    = (const float*)d_in[11];
    const float* Wo    = (const float*)d_in[12];
    const float* bo    = (const float*)d_in[13];
    const float* n2_g  = (const float*)d_in[14];
    const float* n2_b  = (const float*)d_in[15];
    const float* W1    = (const float*)d_in[16];
    const float* b1    = (const float*)d_in[17];
    const float* W2    = (const float*)d_in[18];
    const float* b2    = (const float*)d_in[19];
    float* out = (float*)d_out;

    float* base = nullptr;
    cudaGetSymbolAddress((void**)&base, g_scratch);
    float* xqn  = base;
    float* xkvn = base + 1 * MB4;
    float* qb   = base + 2 * MB4;
    float* kb2  = base + 3 * MB4;
    float* vb   = base + 4 * MB4;
    float* att  = base + 5 * MB4;
    float* hbuf = base + 6 * MB4;   // 16M floats

    cudaFuncSetAttribute(attn_kernel,
                         cudaFuncAttributeMaxDynamicSharedMemorySize, SMEM_ATTN);

    // 1) LayerNorms of inputs
    ln_kernel<<<MROWS, 256>>>(x_q, qn_g, qn_b, xqn);
    ln_kernel<<<MROWS, 256>>>(x_kv, kvn_g, kvn_b, xkvn);

    // 2) Q/K/V projections
    sgemm_kernel<0><<<dim3(DQ / 128, MROWS / 128), 256>>>(xqn,  Wq, bq, nullptr, qb,  MROWS, DQ, DQ);
    sgemm_kernel<0><<<dim3(DQ / 128, MROWS / 128), 256>>>(xkvn, Wk, bk, nullptr, kb2, MROWS, DQ, DQ);
    sgemm_kernel<0><<<dim3(DQ / 128, MROWS / 128), 256>>>(xkvn, Wv, bv, nullptr, vb,  MROWS, DQ, DQ);

    // 3) attention (softmax-1)
    attn_kernel<<<dim3(NN / 64, HH, BB), 256, SMEM_ATTN>>>(qb, kb2, vb, att);

    // 4) out projection + residual with x_q  -> d_out holds x
    sgemm_kernel<1><<<dim3(DQ / 128, MROWS / 128), 256>>>(att, Wo, bo, x_q, out, MROWS, DQ, DQ);

    // 5) LN2
    ln_kernel<<<MROWS, 256>>>(out, n2_g, n2_b, xqn);

    // 6) MLP up + GELU
    sgemm_kernel<2><<<dim3(DFF / 128, MROWS / 128), 256>>>(xqn, W1, b1, nullptr, hbuf, MROWS, DFF, DQ);

    // 7) MLP down + residual into d_out
    sgemm_kernel<3><<<dim3(DQ / 128, MROWS / 128), 256>>>(hbuf, W2, b2, nullptr, out, MROWS, DQ, DFF);
}

// round 3
// speedup vs baseline: 1.5655x; 1.5655x over previous
#include <cuda_runtime.h>
#include <cuda_bf16.h>
#include <math.h>
#include <stdint.h>

#define BB   2
#define NN   2048
#define LL   2048
#define DQ   1024
#define HH   16
#define HD   64
#define MROWS 4096
#define DFF  4096

typedef __nv_bfloat16 bf;

// ---------------------------------------------------------------------------
// Static scratch
// ---------------------------------------------------------------------------
#define EM (1024u*1024u)
__device__ __align__(256) bf    g_bf[88u * EM];
__device__ __align__(256) float g_f32[12u * EM];

#define O_XQH 0
#define O_XQL 4
#define O_XKVH 8
#define O_XKVL 12
#define O_ATTH 16
#define O_ATTL 20
#define O_X2H 24
#define O_X2L 28
#define O_HH  32
#define O_HL  48
#define O_WQH 64
#define O_WQL 65
#define O_WKH 66
#define O_WKL 67
#define O_WVH 68
#define O_WVL 69
#define O_WOH 70
#define O_WOL 71
#define O_W1H 72
#define O_W1L 76
#define O_W2H 80
#define O_W2L 84

// ---------------------------------------------------------------------------
// helpers
// ---------------------------------------------------------------------------
__device__ __forceinline__ uint32_t smem_u32(const void* p) {
    uint32_t a;
    asm("{ .reg .u64 t; cvta.to.shared.u64 t, %1; cvt.u32.u64 %0, t; }" : "=r"(a) : "l"(p));
    return a;
}

__device__ __forceinline__ void ldmx4(uint32_t& r0, uint32_t& r1, uint32_t& r2,
                                      uint32_t& r3, uint32_t a) {
    asm volatile("ldmatrix.sync.aligned.m8n8.x4.shared.b16 {%0,%1,%2,%3}, [%4];"
                 : "=r"(r0), "=r"(r1), "=r"(r2), "=r"(r3) : "r"(a));
}
__device__ __forceinline__ void ldmx2(uint32_t& r0, uint32_t& r1, uint32_t a) {
    asm volatile("ldmatrix.sync.aligned.m8n8.x2.shared.b16 {%0,%1}, [%2];"
                 : "=r"(r0), "=r"(r1) : "r"(a));
}
__device__ __forceinline__ void mma16816(float* d, const uint32_t* a,
                                         uint32_t b0, uint32_t b1) {
    asm volatile(
        "mma.sync.aligned.m16n8k16.row.col.f32.bf16.bf16.f32 "
        "{%0,%1,%2,%3}, {%4,%5,%6,%7}, {%8,%9}, {%0,%1,%2,%3};"
        : "+f"(d[0]), "+f"(d[1]), "+f"(d[2]), "+f"(d[3])
        : "r"(a[0]), "r"(a[1]), "r"(a[2]), "r"(a[3]), "r"(b0), "r"(b1));
}
__device__ __forceinline__ void cp16(uint32_t dst, const void* src) {
    asm volatile("cp.async.cg.shared.global [%0], [%1], 16;" :: "r"(dst), "l"(src));
}
#define CP_COMMIT() asm volatile("cp.async.commit_group;" ::: "memory")
#define CP_WAIT0()  asm volatile("cp.async.wait_group 0;" ::: "memory")

__device__ __forceinline__ float gelu_exact(float x) {
    return 0.5f * x * (1.f + erff(x * 0.7071067811865476f));
}
__device__ __forceinline__ void split_bf16(float x, bf& h, bf& l) {
    h = __float2bfloat16(x);
    l = __float2bfloat16(x - __bfloat162float(h));
}

// ---------------------------------------------------------------------------
// LayerNorm -> bf16 hi/lo split
// ---------------------------------------------------------------------------
__global__ void ln_bf16_kernel(const float* __restrict__ x,
                               const float* __restrict__ g,
                               const float* __restrict__ b,
                               bf* __restrict__ yh, bf* __restrict__ yl) {
    int row = blockIdx.x;
    const float* xr = x + (size_t)row * DQ;
    float v[4];
    float s = 0.f, s2 = 0.f;
#pragma unroll
    for (int i = 0; i < 4; i++) {
        float t = xr[threadIdx.x + i * 256];
        v[i] = t; s += t; s2 += t * t;
    }
#pragma unroll
    for (int o = 16; o > 0; o >>= 1) {
        s  += __shfl_xor_sync(0xffffffffu, s,  o);
        s2 += __shfl_xor_sync(0xffffffffu, s2, o);
    }
    __shared__ float ws[8], ws2[8];
    int w = threadIdx.x >> 5, lane = threadIdx.x & 31;
    if (lane == 0) { ws[w] = s; ws2[w] = s2; }
    __syncthreads();
    if (w == 0) {
        s  = (lane < 8) ? ws[lane]  : 0.f;
        s2 = (lane < 8) ? ws2[lane] : 0.f;
#pragma unroll
        for (int o = 4; o > 0; o >>= 1) {
            s  += __shfl_xor_sync(0xffffffffu, s,  o);
            s2 += __shfl_xor_sync(0xffffffffu, s2, o);
        }
        if (lane == 0) { ws[0] = s; ws2[0] = s2; }
    }
    __syncthreads();
    float mean = ws[0] * (1.f / DQ);
    float var  = ws2[0] * (1.f / DQ) - mean * mean;
    float rstd = rsqrtf(var + 1e-5f);
    size_t base = (size_t)row * DQ;
#pragma unroll
    for (int i = 0; i < 4; i++) {
        int c = threadIdx.x + i * 256;
        float yv = (v[i] - mean) * rstd * g[c] + b[c];
        bf h, l; split_bf16(yv, h, l);
        yh[base + c] = h;
        yl[base + c] = l;
    }
}

// ---------------------------------------------------------------------------
// Weight fp32 -> bf16 hi/lo split
// ---------------------------------------------------------------------------
__global__ void convert_split_kernel(const float* __restrict__ x,
                                     bf* __restrict__ h, bf* __restrict__ l, int n4) {
    int i = blockIdx.x * blockDim.x + threadIdx.x;
    if (i >= n4) return;
    float4 v = ((const float4*)x)[i];
    bf h0, l0, h1, l1, h2, l2, h3, l3;
    split_bf16(v.x, h0, l0); split_bf16(v.y, h1, l1);
    split_bf16(v.z, h2, l2); split_bf16(v.w, h3, l3);
    __nv_bfloat162* hp = (__nv_bfloat162*)(h + (size_t)i * 4);
    __nv_bfloat162* lp = (__nv_bfloat162*)(l + (size_t)i * 4);
    hp[0] = __nv_bfloat162(h0, h1); hp[1] = __nv_bfloat162(h2, h3);
    lp[0] = __nv_bfloat162(l0, l1); lp[1] = __nv_bfloat162(l2, l3);
}

// ---------------------------------------------------------------------------
// HMMA GEMM: C[M,N] = A[M,K] @ W[N,K]^T via bf16x3 split (Ah*Bh + Ah*Bl + Al*Bh)
// CTA tile 128x128, BK=32, 8 warps (2x4), warp tile 64x32, cp.async 2-stage.
// EPI: 0 = bias -> fp32; 1 = bias+res -> fp32; 2 = gelu -> bf16 hi/lo;
//      3 = bias + C (rmw)
// ---------------------------------------------------------------------------
#define PITCHB 80                    // smem row pitch bytes (32 bf16 + 8 pad)
#define MAT_BYTES (128 * PITCHB)     // 10240
#define STAGE_BYTES (4 * MAT_BYTES)  // 40960
#define GEMM_SMEM (2 * STAGE_BYTES)  // 81920

template <int EPI>
__global__ void __launch_bounds__(256, 1)
gemm_mma(const bf* __restrict__ Ah, const bf* __restrict__ Al,
         const bf* __restrict__ Bh, const bf* __restrict__ Bl,
         const float* __restrict__ bias, const float* __restrict__ res,
         float* __restrict__ C, bf* __restrict__ Ho, bf* __restrict__ Lo,
         int M, int N, int K) {
    extern __shared__ char smc[];
    const int tid = threadIdx.x, lane = tid & 31, wid = tid >> 5;
    const int wm = wid & 1, wn = wid >> 1;
    const size_t m0 = (size_t)blockIdx.y * 128;
    const size_t n0 = (size_t)blockIdx.x * 128;
    const uint32_t sbase = smem_u32(smc);

    const bf* gsrc0 = Ah + m0 * K;
    const bf* gsrc1 = Al + m0 * K;
    const bf* gsrc2 = Bh + n0 * K;
    const bf* gsrc3 = Bl + n0 * K;

    auto load_stage = [&](int s, int kt) {
        uint32_t base = sbase + s * STAGE_BYTES;
#pragma unroll
        for (int i = 0; i < 8; i++) {
            const int t = i >> 1;                     // matrix 0..3 (compile-time)
            int idx = tid + (i & 1) * 256;            // 0..511
            int row = idx >> 2, seg = idx & 3;
            const bf* src = (t == 0 ? gsrc0 : t == 1 ? gsrc1 : t == 2 ? gsrc2 : gsrc3);
            cp16(base + t * MAT_BYTES + row * PITCHB + seg * 16,
                 src + (size_t)row * K + kt + seg * 8);
        }
    };

    float acc[4][4][4];
#pragma unroll
    for (int a = 0; a < 4; a++)
#pragma unroll
        for (int b = 0; b < 4; b++)
#pragma unroll
            for (int c = 0; c < 4; c++) acc[a][b][c] = 0.f;

    const int nk = K >> 5;
    load_stage(0, 0);
    CP_COMMIT();

    for (int cc = 0; cc < nk; cc++) {
        CP_WAIT0();
        __syncthreads();
        if (cc + 1 < nk) { load_stage((cc + 1) & 1, (cc + 1) << 5); CP_COMMIT(); }

        uint32_t st = sbase + (cc & 1) * STAGE_BYTES;
        uint32_t sAh = st, sAl = st + MAT_BYTES;
        uint32_t sBh = st + 2 * MAT_BYTES, sBl = st + 3 * MAT_BYTES;

#pragma unroll
        for (int k16 = 0; k16 < 2; k16++) {
            uint32_t acol = (uint32_t)(k16 * 16 + ((lane >> 4) << 3)) * 2;
            uint32_t arow = (uint32_t)(wm * 64 + (lane & 15));
            uint32_t ah[4][4], al[4][4];
#pragma unroll
            for (int mt = 0; mt < 4; mt++) {
                uint32_t ao = (arow + mt * 16) * PITCHB + acol;
                ldmx4(ah[mt][0], ah[mt][1], ah[mt][2], ah[mt][3], sAh + ao);
                ldmx4(al[mt][0], al[mt][1], al[mt][2], al[mt][3], sAl + ao);
            }
            uint32_t bcol = (uint32_t)(k16 * 16 + (((lane >> 3) & 1) << 3)) * 2;
            uint32_t brow = (uint32_t)(wn * 32 + (lane & 7));
#pragma unroll
            for (int nt = 0; nt < 4; nt++) {
                uint32_t bo = (brow + nt * 8) * PITCHB + bcol;
                uint32_t bh0, bh1, bl0, bl1;
                ldmx2(bh0, bh1, sBh + bo);
                ldmx2(bl0, bl1, sBl + bo);
#pragma unroll
                for (int mt = 0; mt < 4; mt++) {
                    mma16816(acc[mt][nt], ah[mt], bh0, bh1);
                    mma16816(acc[mt][nt], ah[mt], bl0, bl1);
                    mma16816(acc[mt][nt], al[mt], bh0, bh1);
                }
            }
        }
    }

    // ---- epilogue: direct stores ----
#pragma unroll
    for (int mt = 0; mt < 4; mt++) {
        int r0 = wm * 64 + mt * 16 + (lane >> 2);
#pragma unroll
        for (int nt = 0; nt < 4; nt++) {
            size_t gcol = n0 + wn * 32 + nt * 8 + (lane & 3) * 2;
            float2 bb = *(const float2*)(bias + gcol);
#pragma unroll
            for (int h = 0; h < 2; h++) {
                size_t grow = m0 + r0 + h * 8;
                size_t idx = grow * (size_t)N + gcol;
                float v0 = acc[mt][nt][h * 2 + 0] + bb.x;
                float v1 = acc[mt][nt][h * 2 + 1] + bb.y;
                if (EPI == 1) {
                    float2 rr = *(const float2*)(res + idx);
                    v0 += rr.x; v1 += rr.y;
                }
                if (EPI == 3) {
                    float2 rr = *(const float2*)(C + idx);
                    v0 += rr.x; v1 += rr.y;
                }
                if (EPI == 2) {
                    v0 = gelu_exact(v0); v1 = gelu_exact(v1);
                    bf h0, l0, h1, l1;
                    split_bf16(v0, h0, l0); split_bf16(v1, h1, l1);
                    *(__nv_bfloat162*)(Ho + idx) = __nv_bfloat162(h0, h1);
                    *(__nv_bfloat162*)(Lo + idx) = __nv_bfloat162(l0, l1);
                } else {
                    float2 o; o.x = v0; o.y = v1;
                    *(float2*)(C + idx) = o;
                }
            }
        }
    }
}

// ---------------------------------------------------------------------------
// Flash attention, softmax-1, fp32 — epilogue emits bf16 hi/lo
// ---------------------------------------------------------------------------
#define SMEM_ATTN ((3 * 64 * 64 + 64 * 65) * 4)

__global__ void __launch_bounds__(256)
attn_kernel(const float* __restrict__ q, const float* __restrict__ k,
            const float* __restrict__ v, bf* __restrict__ oh, bf* __restrict__ ol) {
    extern __shared__ float sm[];
    float* Qts = sm;
    float* Kts = sm + 4096;
    float* Vs  = sm + 8192;
    float* Ps  = sm + 12288;

    const int tid = threadIdx.x;
    const int tx = tid & 15, ty = tid >> 4;
    const int b = blockIdx.z, h = blockIdx.y, n0 = blockIdx.x * 64;
    const int lj = tid >> 2;
    const int ld = (tid & 3) * 16;
    const float scale = 0.125f;

    {
        const float* qp = q + ((size_t)(b * NN + n0 + lj)) * DQ + h * HD + ld;
#pragma unroll
        for (int p = 0; p < 16; p += 4) {
            float4 t = *(const float4*)(qp + p);
            Qts[(ld + p + 0) * 64 + lj] = t.x * scale;
            Qts[(ld + p + 1) * 64 + lj] = t.y * scale;
            Qts[(ld + p + 2) * 64 + lj] = t.z * scale;
            Qts[(ld + p + 3) * 64 + lj] = t.w * scale;
        }
    }

    float m_[4], l_[4], acc[4][4];
#pragma unroll
    for (int i = 0; i < 4; i++) {
        m_[i] = 0.f; l_[i] = 1.f;
#pragma unroll
        for (int j = 0; j < 4; j++) acc[i][j] = 0.f;
    }

    for (int l0 = 0; l0 < LL; l0 += 64) {
        __syncthreads();
        {
            const float* kp = k + ((size_t)(b * LL + l0 + lj)) * DQ + h * HD + ld;
            const float* vp = v + ((size_t)(b * LL + l0 + lj)) * DQ + h * HD + ld;
#pragma unroll
            for (int p = 0; p < 16; p += 4) {
                float4 t = *(const float4*)(kp + p);
                Kts[(ld + p + 0) * 64 + lj] = t.x;
                Kts[(ld + p + 1) * 64 + lj] = t.y;
                Kts[(ld + p + 2) * 64 + lj] = t.z;
                Kts[(ld + p + 3) * 64 + lj] = t.w;
                float4 u = *(const float4*)(vp + p);
                *(float4*)&Vs[lj * 64 + ld + p] = u;
            }
        }
        __syncthreads();

        float s[4][4];
#pragma unroll
        for (int i = 0; i < 4; i++)
#pragma unroll
            for (int j = 0; j < 4; j++) s[i][j] = 0.f;
#pragma unroll 8
        for (int d = 0; d < 64; d++) {
            float4 qa = *(const float4*)&Qts[d * 64 + ty * 4];
            float4 kb = *(const float4*)&Kts[d * 64 + tx * 4];
            float a[4] = {qa.x, qa.y, qa.z, qa.w};
            float bv[4] = {kb.x, kb.y, kb.z, kb.w};
#pragma unroll
            for (int i = 0; i < 4; i++)
#pragma unroll
                for (int j = 0; j < 4; j++) s[i][j] = fmaf(a[i], bv[j], s[i][j]);
        }

#pragma unroll
        for (int i = 0; i < 4; i++) {
            float mx = fmaxf(fmaxf(s[i][0], s[i][1]), fmaxf(s[i][2], s[i][3]));
#pragma unroll
            for (int o2 = 1; o2 < 16; o2 <<= 1)
                mx = fmaxf(mx, __shfl_xor_sync(0xffffffffu, mx, o2));
            float mn = fmaxf(m_[i], mx);
            float corr = __expf(m_[i] - mn);
            float ps = 0.f;
#pragma unroll
            for (int j = 0; j < 4; j++) {
                float p = __expf(s[i][j] - mn);
                s[i][j] = p; ps += p;
            }
#pragma unroll
            for (int o2 = 1; o2 < 16; o2 <<= 1)
                ps += __shfl_xor_sync(0xffffffffu, ps, o2);
            l_[i] = l_[i] * corr + ps;
            m_[i] = mn;
#pragma unroll
            for (int j = 0; j < 4; j++) acc[i][j] *= corr;
#pragma unroll
            for (int j = 0; j < 4; j++) Ps[(ty * 4 + i) * 65 + tx * 4 + j] = s[i][j];
        }
        __syncthreads();

#pragma unroll 4
        for (int kk = 0; kk < 64; kk++) {
            float4 vv = *(const float4*)&Vs[kk * 64 + tx * 4];
#pragma unroll
            for (int i = 0; i < 4; i++) {
                float p = Ps[(ty * 4 + i) * 65 + kk];
                acc[i][0] = fmaf(p, vv.x, acc[i][0]);
                acc[i][1] = fmaf(p, vv.y, acc[i][1]);
                acc[i][2] = fmaf(p, vv.z, acc[i][2]);
                acc[i][3] = fmaf(p, vv.w, acc[i][3]);
            }
        }
    }

#pragma unroll
    for (int i = 0; i < 4; i++) {
        float inv = 1.f / l_[i];
        int row = n0 + ty * 4 + i;
        size_t base = ((size_t)(b * NN) + row) * DQ + h * HD + tx * 4;
        float f0 = acc[i][0] * inv, f1 = acc[i][1] * inv;
        float f2 = acc[i][2] * inv, f3 = acc[i][3] * inv;
        bf h0, l0, h1, l1, h2, l2, h3, l3;
        split_bf16(f0, h0, l0); split_bf16(f1, h1, l1);
        split_bf16(f2, h2, l2); split_bf16(f3, h3, l3);
        __nv_bfloat162* hp = (__nv_bfloat162*)(oh + base);
        __nv_bfloat162* lp = (__nv_bfloat162*)(ol + base);
        hp[0] = __nv_bfloat162(h0, h1); hp[1] = __nv_bfloat162(h2, h3);
        lp[0] = __nv_bfloat162(l0, l1); lp[1] = __nv_bfloat162(l2, l3);
    }
}

// ---------------------------------------------------------------------------
// kernel_launch
// ---------------------------------------------------------------------------
extern "C" void kernel_launch(void* const* d_in, const int* in_sizes, int n_in,
                              void* d_out, int out_size) {
    const float* x_q   = (const float*)d_in[0];
    const float* x_kv  = (const float*)d_in[1];
    const float* qn_g  = (const float*)d_in[2];
    const float* qn_b  = (const float*)d_in[3];
    const float* kvn_g = (const float*)d_in[4];
    const float* kvn_b = (const float*)d_in[5];
    const float* Wq    = (const float*)d_in[6];
    const float* bq    = (const float*)d_in[7];
    const float* Wk    = (const float*)d_in[8];
    const float* bk    = (const float*)d_in[9];
    const float* Wv    = (const float*)d_in[10];
    const float* bv    = (const float*)d_in[11];
    const float* Wo    = (const float*)d_in[12];
    const float* bo    = (const float*)d_in[13];
    const float* n2_g  = (const float*)d_in[14];
    const float* n2_b  = (const float*)d_in[15];
    const float* W1    = (const float*)d_in[16];
    const float* b1    = (const float*)d_in[17];
    const float* W2    = (const float*)d_in[18];
    const float* b2    = (const float*)d_in[19];
    float* out = (float*)d_out;

    bf* bfb = nullptr;
    float* f32b = nullptr;
    cudaGetSymbolAddress((void**)&bfb, g_bf);
    cudaGetSymbolAddress((void**)&f32b, g_f32);

    bf* XQH = bfb + (size_t)O_XQH * EM;  bf* XQL = bfb + (size_t)O_XQL * EM;
    bf* XKVH = bfb + (size_t)O_XKVH * EM; bf* XKVL = bfb + (size_t)O_XKVL * EM;
    bf* ATTH = bfb + (size_t)O_ATTH * EM; bf* ATTL = bfb + (size_t)O_ATTL * EM;
    bf* X2H = bfb + (size_t)O_X2H * EM;  bf* X2L = bfb + (size_t)O_X2L * EM;
    bf* Hh  = bfb + (size_t)O_HH * EM;   bf* Hl  = bfb + (size_t)O_HL * EM;
    bf* WQH = bfb + (size_t)O_WQH * EM;  bf* WQL = bfb + (size_t)O_WQL * EM;
    bf* WKH = bfb + (size_t)O_WKH * EM;  bf* WKL = bfb + (size_t)O_WKL * EM;
    bf* WVH = bfb + (size_t)O_WVH * EM;  bf* WVL = bfb + (size_t)O_WVL * EM;
    bf* WOH = bfb + (size_t)O_WOH * EM;  bf* WOL = bfb + (size_t)O_WOL * EM;
    bf* W1H = bfb + (size_t)O_W1H * EM;  bf* W1L = bfb + (size_t)O_W1L * EM;
    bf* W2H = bfb + (size_t)O_W2H * EM;  bf* W2L = bfb + (size_t)O_W2L * EM;

    float* qb = f32b;
    float* kb = f32b + 4 * EM;
    float* vb = f32b + 8 * EM;

    cudaFuncSetAttribute(gemm_mma<0>, cudaFuncAttributeMaxDynamicSharedMemorySize, GEMM_SMEM);
    cudaFuncSetAttribute(gemm_mma<1>, cudaFuncAttributeMaxDynamicSharedMemorySize, GEMM_SMEM);
    cudaFuncSetAttribute(gemm_mma<2>, cudaFuncAttributeMaxDynamicSharedMemorySize, GEMM_SMEM);
    cudaFuncSetAttribute(gemm_mma<3>, cudaFuncAttributeMaxDynamicSharedMemorySize, GEMM_SMEM);
    cudaFuncSetAttribute(attn_kernel, cudaFuncAttributeMaxDynamicSharedMemorySize, SMEM_ATTN);

    // weight splits
    convert_split_kernel<<<1024, 256>>>(Wq, WQH, WQL, 1 * EM / 4);
    convert_split_kernel<<<1024, 256>>>(Wk, WKH, WKL, 1 * EM / 4);
    convert_split_kernel<<<1024, 256>>>(Wv, WVH, WVL, 1 * EM / 4);
    convert_split_kernel<<<1024, 256>>>(Wo, WOH, WOL, 1 * EM / 4);
    convert_split_kernel<<<4096, 256>>>(W1, W1H, W1L, EM);
    convert_split_kernel<<<4096, 256>>>(W2, W2H, W2L, EM);

    // LN + split
    ln_bf16_kernel<<<MROWS, 256>>>(x_q, qn_g, qn_b, XQH, XQL);
    ln_bf16_kernel<<<MROWS, 256>>>(x_kv, kvn_g, kvn_b, XKVH, XKVL);

    // Q/K/V projections (fp32 outputs)
    gemm_mma<0><<<dim3(DQ / 128, MROWS / 128), 256, GEMM_SMEM>>>(
        XQH, XQL, WQH, WQL, bq, nullptr, qb, nullptr, nullptr, MROWS, DQ, DQ);
    gemm_mma<0><<<dim3(DQ / 128, MROWS / 128), 256, GEMM_SMEM>>>(
        XKVH, XKVL, WKH, WKL, bk, nullptr, kb, nullptr, nullptr, MROWS, DQ, DQ);
    gemm_mma<0><<<dim3(DQ / 128, MROWS / 128), 256, GEMM_SMEM>>>(
        XKVH, XKVL, WVH, WVL, bv, nullptr, vb, nullptr, nullptr, MROWS, DQ, DQ);

    // attention
    attn_kernel<<<dim3(NN / 64, HH, BB), 256, SMEM_ATTN>>>(qb, kb, vb, ATTH, ATTL);

    // out projection + residual with x_q
    gemm_mma<1><<<dim3(DQ / 128, MROWS / 128), 256, GEMM_SMEM>>>(
        ATTH, ATTL, WOH, WOL, bo, x_q, out, nullptr, nullptr, MROWS, DQ, DQ);

    // LN2 + split
    ln_bf16_kernel<<<MROWS, 256>>>(out, n2_g, n2_b, X2H, X2L);

    // MLP up + GELU -> bf16 split
    gemm_mma<2><<<dim3(DFF / 128, MROWS / 128), 256, GEMM_SMEM>>>(
        X2H, X2L, W1H, W1L, b1, nullptr, nullptr, Hh, Hl, MROWS, DFF, DQ);

    // MLP down + residual accumulate into d_out
    gemm_mma<3><<<dim3(DQ / 128, MROWS / 128), 256, GEMM_SMEM>>>(
        Hh, Hl, W2H, W2L, b2, nullptr, out, nullptr, nullptr, MROWS, DQ, DFF);
}

// round 4
// speedup vs baseline: 2.3496x; 1.5008x over previous
#include <cuda_runtime.h>
#include <cuda_bf16.h>
#include <math.h>
#include <stdint.h>

#define BB   2
#define NN   2048
#define LL   2048
#define DQ   1024
#define HH   16
#define HD   64
#define MROWS 4096
#define DFF  4096

typedef __nv_bfloat16 bf;

// ---------------------------------------------------------------------------
// Static scratch
// ---------------------------------------------------------------------------
#define EM (1024u*1024u)
__device__ __align__(256) bf g_bf[112u * EM];

#define O_XQH 0
#define O_XQL 4
#define O_XKVH 8
#define O_XKVL 12
#define O_ATTH 16
#define O_ATTL 20
#define O_X2H 24
#define O_X2L 28
#define O_HH  32
#define O_HL  48
#define O_WQH 64
#define O_WQL 65
#define O_WKH 66
#define O_WKL 67
#define O_WVH 68
#define O_WVL 69
#define O_WOH 70
#define O_WOL 71
#define O_W1H 72
#define O_W1L 76
#define O_W2H 80
#define O_W2L 84
#define O_QH  88
#define O_QL  92
#define O_KH  96
#define O_KL  100
#define O_VH  104
#define O_VL  108

// ---------------------------------------------------------------------------
// helpers
// ---------------------------------------------------------------------------
__device__ __forceinline__ uint32_t smem_u32(const void* p) {
    uint32_t a;
    asm("{ .reg .u64 t; cvta.to.shared.u64 t, %1; cvt.u32.u64 %0, t; }" : "=r"(a) : "l"(p));
    return a;
}
__device__ __forceinline__ void ldmx4(uint32_t& r0, uint32_t& r1, uint32_t& r2,
                                      uint32_t& r3, uint32_t a) {
    asm volatile("ldmatrix.sync.aligned.m8n8.x4.shared.b16 {%0,%1,%2,%3}, [%4];"
                 : "=r"(r0), "=r"(r1), "=r"(r2), "=r"(r3) : "r"(a));
}
__device__ __forceinline__ void ldmx2(uint32_t& r0, uint32_t& r1, uint32_t a) {
    asm volatile("ldmatrix.sync.aligned.m8n8.x2.shared.b16 {%0,%1}, [%2];"
                 : "=r"(r0), "=r"(r1) : "r"(a));
}
__device__ __forceinline__ void ldmx2t(uint32_t& r0, uint32_t& r1, uint32_t a) {
    asm volatile("ldmatrix.sync.aligned.m8n8.x2.trans.shared.b16 {%0,%1}, [%2];"
                 : "=r"(r0), "=r"(r1) : "r"(a));
}
__device__ __forceinline__ void mma16816(float* d, const uint32_t* a,
                                         uint32_t b0, uint32_t b1) {
    asm volatile(
        "mma.sync.aligned.m16n8k16.row.col.f32.bf16.bf16.f32 "
        "{%0,%1,%2,%3}, {%4,%5,%6,%7}, {%8,%9}, {%0,%1,%2,%3};"
        : "+f"(d[0]), "+f"(d[1]), "+f"(d[2]), "+f"(d[3])
        : "r"(a[0]), "r"(a[1]), "r"(a[2]), "r"(a[3]), "r"(b0), "r"(b1));
}
__device__ __forceinline__ void cp16(uint32_t dst, const void* src) {
    asm volatile("cp.async.cg.shared.global [%0], [%1], 16;" :: "r"(dst), "l"(src));
}
#define CP_COMMIT() asm volatile("cp.async.commit_group;" ::: "memory")
#define CP_WAIT0()  asm volatile("cp.async.wait_group 0;" ::: "memory")
#define CP_WAIT1()  asm volatile("cp.async.wait_group 1;" ::: "memory")

__device__ __forceinline__ float gelu_exact(float x) {
    return 0.5f * x * (1.f + erff(x * 0.7071067811865476f));
}
__device__ __forceinline__ void split_bf16(float x, bf& h, bf& l) {
    h = __float2bfloat16(x);
    l = __float2bfloat16(x - __bfloat162float(h));
}
__device__ __forceinline__ void split2pack(float a, float b, uint32_t& hi, uint32_t& lo) {
    bf ha = __float2bfloat16(a), hb = __float2bfloat16(b);
    float ra = a - __bfloat162float(ha), rb = b - __bfloat162float(hb);
    __nv_bfloat162 H(ha, hb);
    __nv_bfloat162 L(__float2bfloat16(ra), __float2bfloat16(rb));
    hi = *(uint32_t*)&H;
    lo = *(uint32_t*)&L;
}

// ---------------------------------------------------------------------------
// LayerNorm -> bf16 hi/lo split
// ---------------------------------------------------------------------------
__global__ void ln_bf16_kernel(const float* __restrict__ x,
                               const float* __restrict__ g,
                               const float* __restrict__ b,
                               bf* __restrict__ yh, bf* __restrict__ yl) {
    int row = blockIdx.x;
    const float* xr = x + (size_t)row * DQ;
    float v[4];
    float s = 0.f, s2 = 0.f;
#pragma unroll
    for (int i = 0; i < 4; i++) {
        float t = xr[threadIdx.x + i * 256];
        v[i] = t; s += t; s2 += t * t;
    }
#pragma unroll
    for (int o = 16; o > 0; o >>= 1) {
        s  += __shfl_xor_sync(0xffffffffu, s,  o);
        s2 += __shfl_xor_sync(0xffffffffu, s2, o);
    }
    __shared__ float ws[8], ws2[8];
    int w = threadIdx.x >> 5, lane = threadIdx.x & 31;
    if (lane == 0) { ws[w] = s; ws2[w] = s2; }
    __syncthreads();
    if (w == 0) {
        s  = (lane < 8) ? ws[lane]  : 0.f;
        s2 = (lane < 8) ? ws2[lane] : 0.f;
#pragma unroll
        for (int o = 4; o > 0; o >>= 1) {
            s  += __shfl_xor_sync(0xffffffffu, s,  o);
            s2 += __shfl_xor_sync(0xffffffffu, s2, o);
        }
        if (lane == 0) { ws[0] = s; ws2[0] = s2; }
    }
    __syncthreads();
    float mean = ws[0] * (1.f / DQ);
    float var  = ws2[0] * (1.f / DQ) - mean * mean;
    float rstd = rsqrtf(var + 1e-5f);
    size_t base = (size_t)row * DQ;
#pragma unroll
    for (int i = 0; i < 4; i++) {
        int c = threadIdx.x + i * 256;
        float yv = (v[i] - mean) * rstd * g[c] + b[c];
        bf h, l; split_bf16(yv, h, l);
        yh[base + c] = h;
        yl[base + c] = l;
    }
}

// ---------------------------------------------------------------------------
// Weight fp32 -> bf16 hi/lo split
// ---------------------------------------------------------------------------
__global__ void convert_split_kernel(const float* __restrict__ x,
                                     bf* __restrict__ h, bf* __restrict__ l, int n4) {
    int i = blockIdx.x * blockDim.x + threadIdx.x;
    if (i >= n4) return;
    float4 v = ((const float4*)x)[i];
    bf h0, l0, h1, l1, h2, l2, h3, l3;
    split_bf16(v.x, h0, l0); split_bf16(v.y, h1, l1);
    split_bf16(v.z, h2, l2); split_bf16(v.w, h3, l3);
    __nv_bfloat162* hp = (__nv_bfloat162*)(h + (size_t)i * 4);
    __nv_bfloat162* lp = (__nv_bfloat162*)(l + (size_t)i * 4);
    hp[0] = __nv_bfloat162(h0, h1); hp[1] = __nv_bfloat162(h2, h3);
    lp[0] = __nv_bfloat162(l0, l1); lp[1] = __nv_bfloat162(l2, l3);
}

// ---------------------------------------------------------------------------
// HMMA GEMM (bf16x3 split). EPI: 0 bias->fp32; 1 bias+res->fp32;
// 2 gelu->bf16 hi/lo; 3 bias+C rmw; 4 (acc+bias)*alpha -> bf16 hi/lo
// ---------------------------------------------------------------------------
#define PITCHB 80
#define MAT_BYTES (128 * PITCHB)
#define STAGE_BYTES (4 * MAT_BYTES)
#define GEMM_SMEM (2 * STAGE_BYTES)

template <int EPI>
__global__ void __launch_bounds__(256, 1)
gemm_mma(const bf* __restrict__ Ah, const bf* __restrict__ Al,
         const bf* __restrict__ Bh, const bf* __restrict__ Bl,
         const float* __restrict__ bias, const float* __restrict__ res,
         float* __restrict__ C, bf* __restrict__ Ho, bf* __restrict__ Lo,
         int M, int N, int K, float alpha) {
    extern __shared__ char smc[];
    const int tid = threadIdx.x, lane = tid & 31, wid = tid >> 5;
    const int wm = wid & 1, wn = wid >> 1;
    const size_t m0 = (size_t)blockIdx.y * 128;
    const size_t n0 = (size_t)blockIdx.x * 128;
    const uint32_t sbase = smem_u32(smc);

    const bf* gsrc0 = Ah + m0 * K;
    const bf* gsrc1 = Al + m0 * K;
    const bf* gsrc2 = Bh + n0 * K;
    const bf* gsrc3 = Bl + n0 * K;

    auto load_stage = [&](int s, int kt) {
        uint32_t base = sbase + s * STAGE_BYTES;
#pragma unroll
        for (int i = 0; i < 8; i++) {
            const int t = i >> 1;
            int idx = tid + (i & 1) * 256;
            int row = idx >> 2, seg = idx & 3;
            const bf* src = (t == 0 ? gsrc0 : t == 1 ? gsrc1 : t == 2 ? gsrc2 : gsrc3);
            cp16(base + t * MAT_BYTES + row * PITCHB + seg * 16,
                 src + (size_t)row * K + kt + seg * 8);
        }
    };

    float acc[4][4][4];
#pragma unroll
    for (int a = 0; a < 4; a++)
#pragma unroll
        for (int b = 0; b < 4; b++)
#pragma unroll
            for (int c = 0; c < 4; c++) acc[a][b][c] = 0.f;

    const int nk = K >> 5;
    load_stage(0, 0);
    CP_COMMIT();

    for (int cc = 0; cc < nk; cc++) {
        CP_WAIT0();
        __syncthreads();
        if (cc + 1 < nk) { load_stage((cc + 1) & 1, (cc + 1) << 5); CP_COMMIT(); }

        uint32_t st = sbase + (cc & 1) * STAGE_BYTES;
        uint32_t sAh = st, sAl = st + MAT_BYTES;
        uint32_t sBh = st + 2 * MAT_BYTES, sBl = st + 3 * MAT_BYTES;

#pragma unroll
        for (int k16 = 0; k16 < 2; k16++) {
            uint32_t acol = (uint32_t)(k16 * 16 + ((lane >> 4) << 3)) * 2;
            uint32_t arow = (uint32_t)(wm * 64 + (lane & 15));
            uint32_t ah[4][4], al[4][4];
#pragma unroll
            for (int mt = 0; mt < 4; mt++) {
                uint32_t ao = (arow + mt * 16) * PITCHB + acol;
                ldmx4(ah[mt][0], ah[mt][1], ah[mt][2], ah[mt][3], sAh + ao);
                ldmx4(al[mt][0], al[mt][1], al[mt][2], al[mt][3], sAl + ao);
            }
            uint32_t bcol = (uint32_t)(k16 * 16 + (((lane >> 3) & 1) << 3)) * 2;
            uint32_t brow = (uint32_t)(wn * 32 + (lane & 7));
#pragma unroll
            for (int nt = 0; nt < 4; nt++) {
                uint32_t bo = (brow + nt * 8) * PITCHB + bcol;
                uint32_t bh0, bh1, bl0, bl1;
                ldmx2(bh0, bh1, sBh + bo);
                ldmx2(bl0, bl1, sBl + bo);
#pragma unroll
                for (int mt = 0; mt < 4; mt++) {
                    mma16816(acc[mt][nt], ah[mt], bh0, bh1);
                    mma16816(acc[mt][nt], ah[mt], bl0, bl1);
                    mma16816(acc[mt][nt], al[mt], bh0, bh1);
                }
            }
        }
    }

#pragma unroll
    for (int mt = 0; mt < 4; mt++) {
        int r0 = wm * 64 + mt * 16 + (lane >> 2);
#pragma unroll
        for (int nt = 0; nt < 4; nt++) {
            size_t gcol = n0 + wn * 32 + nt * 8 + (lane & 3) * 2;
            float2 bb = *(const float2*)(bias + gcol);
#pragma unroll
            for (int h = 0; h < 2; h++) {
                size_t grow = m0 + r0 + h * 8;
                size_t idx = grow * (size_t)N + gcol;
                float v0 = acc[mt][nt][h * 2 + 0] + bb.x;
                float v1 = acc[mt][nt][h * 2 + 1] + bb.y;
                if (EPI == 1) {
                    float2 rr = *(const float2*)(res + idx);
                    v0 += rr.x; v1 += rr.y;
                }
                if (EPI == 3) {
                    float2 rr = *(const float2*)(C + idx);
                    v0 += rr.x; v1 += rr.y;
                }
                if (EPI == 2 || EPI == 4) {
                    if (EPI == 2) { v0 = gelu_exact(v0); v1 = gelu_exact(v1); }
                    else          { v0 *= alpha; v1 *= alpha; }
                    bf h0, l0, h1, l1;
                    split_bf16(v0, h0, l0); split_bf16(v1, h1, l1);
                    *(__nv_bfloat162*)(Ho + idx) = __nv_bfloat162(h0, h1);
                    *(__nv_bfloat162*)(Lo + idx) = __nv_bfloat162(l0, l1);
                } else {
                    float2 o; o.x = v0; o.y = v1;
                    *(float2*)(C + idx) = o;
                }
            }
        }
    }
}

// ---------------------------------------------------------------------------
// Tensor-core flash attention, softmax-1.
// 256 threads, 8 warps x 16 q-rows = 128 q-rows/CTA, kv tiles of 64.
// Q/K hi/lo 3-term for S; P hi/lo + V hi/lo 3-term for PV.
// ---------------------------------------------------------------------------
#define AP 72                      // smem pitch in bf16
#define APB 144                    // pitch bytes
#define KV_MAT (64 * APB)          // 9216 bytes per matrix
#define KV_STAGE (4 * KV_MAT)      // 36864
#define ATTN_SMEM (2 * KV_STAGE)   // 73728

__global__ void __launch_bounds__(256, 1)
attn_mma(const bf* __restrict__ QHp, const bf* __restrict__ QLp,
         const bf* __restrict__ KHp, const bf* __restrict__ KLp,
         const bf* __restrict__ VHp, const bf* __restrict__ VLp,
         bf* __restrict__ OHp, bf* __restrict__ OLp) {
    extern __shared__ char smc[];
    const uint32_t sb = smem_u32(smc);
    const int tid = threadIdx.x, lane = tid & 31, wid = tid >> 5;
    const int b = blockIdx.z, h = blockIdx.y;
    const int n0 = blockIdx.x * 128;
    const size_t qrow0 = (size_t)b * NN + n0;
    const size_t col0 = (size_t)h * HD;

    // ---- stage Q (hi/lo) through smem into A-fragments ----
    {
        const bf* s0 = QHp + qrow0 * DQ + col0;
        const bf* s1 = QLp + qrow0 * DQ + col0;
#pragma unroll
        for (int it = 0; it < 8; it++) {
            int g = it * 256 + tid;            // 0..2047
            int m = g >> 10;                   // 0..1
            int r = (g & 1023) >> 3, c = g & 7;
            const bf* src = m == 0 ? s0 : s1;
            cp16(sb + m * (128 * APB) + r * APB + c * 16, src + (size_t)r * DQ + c * 8);
        }
    }
    CP_COMMIT();
    CP_WAIT0();
    __syncthreads();

    uint32_t qh[4][4], ql[4][4];
#pragma unroll
    for (int k16 = 0; k16 < 4; k16++) {
        uint32_t ao = (uint32_t)(wid * 16 + (lane & 15)) * APB
                    + (uint32_t)(k16 * 16 + (lane >> 4) * 8) * 2;
        ldmx4(qh[k16][0], qh[k16][1], qh[k16][2], qh[k16][3], sb + ao);
        ldmx4(ql[k16][0], ql[k16][1], ql[k16][2], ql[k16][3], sb + 128 * APB + ao);
    }
    __syncthreads();

    // KV tile loader
    const bf* kvsrc[4] = {
        KHp + ((size_t)b * LL) * DQ + col0,
        KLp + ((size_t)b * LL) * DQ + col0,
        VHp + ((size_t)b * LL) * DQ + col0,
        VLp + ((size_t)b * LL) * DQ + col0
    };
    auto load_kv = [&](int blk, int s) {
        uint32_t base = sb + s * KV_STAGE;
        size_t roff = (size_t)blk * 64;
#pragma unroll
        for (int it = 0; it < 8; it++) {
            int g = it * 256 + tid;            // 0..2047
            int m = g >> 9;                    // 0..3
            int r = (g & 511) >> 3, c = g & 7;
            cp16(base + m * KV_MAT + r * APB + c * 16,
                 kvsrc[m] + (roff + r) * DQ + c * 8);
        }
    };

    float m_[2] = {0.f, 0.f}, l_[2] = {1.f, 1.f};
    float o_[8][4];
#pragma unroll
    for (int d = 0; d < 8; d++)
#pragma unroll
        for (int j = 0; j < 4; j++) o_[d][j] = 0.f;

    load_kv(0, 0);
    CP_COMMIT();

    const int NBLK = LL / 64;
    for (int i = 0; i < NBLK; i++) {
        if (i + 1 < NBLK) { load_kv(i + 1, (i + 1) & 1); CP_COMMIT(); CP_WAIT1(); }
        else CP_WAIT0();
        __syncthreads();

        uint32_t stg = sb + (i & 1) * KV_STAGE;

        // ---- S = Q K^T ----
        float s_[8][4];
#pragma unroll
        for (int nt = 0; nt < 8; nt++)
#pragma unroll
            for (int j = 0; j < 4; j++) s_[nt][j] = 0.f;

#pragma unroll
        for (int k16 = 0; k16 < 4; k16++) {
            uint32_t bcol = (uint32_t)(k16 * 16 + ((lane >> 3) & 1) * 8) * 2;
            uint32_t brow = (uint32_t)(lane & 7);
#pragma unroll
            for (int nt = 0; nt < 8; nt++) {
                uint32_t bo = (brow + nt * 8) * APB + bcol;
                uint32_t kh0, kh1, kl0, kl1;
                ldmx2(kh0, kh1, stg + bo);
                ldmx2(kl0, kl1, stg + KV_MAT + bo);
                mma16816(s_[nt], qh[k16], kh0, kh1);
                mma16816(s_[nt], qh[k16], kl0, kl1);
                mma16816(s_[nt], ql[k16], kh0, kh1);
            }
        }

        // ---- online softmax-1 ----
#pragma unroll
        for (int hh = 0; hh < 2; hh++) {
            float mx = s_[0][hh * 2];
#pragma unroll
            for (int nt = 0; nt < 8; nt++)
                mx = fmaxf(mx, fmaxf(s_[nt][hh * 2], s_[nt][hh * 2 + 1]));
            mx = fmaxf(mx, __shfl_xor_sync(0xffffffffu, mx, 1));
            mx = fmaxf(mx, __shfl_xor_sync(0xffffffffu, mx, 2));
            float mn = fmaxf(m_[hh], mx);
            float corr = __expf(m_[hh] - mn);
            m_[hh] = mn;
            float sum = 0.f;
#pragma unroll
            for (int nt = 0; nt < 8; nt++) {
                float p0 = __expf(s_[nt][hh * 2] - mn);
                float p1 = __expf(s_[nt][hh * 2 + 1] - mn);
                s_[nt][hh * 2] = p0; s_[nt][hh * 2 + 1] = p1;
                sum += p0 + p1;
            }
            sum += __shfl_xor_sync(0xffffffffu, sum, 1);
            sum += __shfl_xor_sync(0xffffffffu, sum, 2);
            l_[hh] = l_[hh] * corr + sum;
#pragma unroll
            for (int d = 0; d < 8; d++) {
                o_[d][hh * 2] *= corr; o_[d][hh * 2 + 1] *= corr;
            }
        }

        // ---- pack P into A-frags (hi/lo) ----
        uint32_t ph[4][4], pl[4][4];
#pragma unroll
        for (int j = 0; j < 4; j++) {
            split2pack(s_[2 * j][0], s_[2 * j][1], ph[j][0], pl[j][0]);
            split2pack(s_[2 * j][2], s_[2 * j][3], ph[j][1], pl[j][1]);
            split2pack(s_[2 * j + 1][0], s_[2 * j + 1][1], ph[j][2], pl[j][2]);
            split2pack(s_[2 * j + 1][2], s_[2 * j + 1][3], ph[j][3], pl[j][3]);
        }

        // ---- O += P V ----
        uint32_t vbase = stg + 2 * KV_MAT;
#pragma unroll
        for (int j = 0; j < 4; j++) {
            uint32_t vrow = (uint32_t)(j * 16 + (lane & 15)) * APB;
#pragma unroll
            for (int dt = 0; dt < 8; dt++) {
                uint32_t vo = vrow + dt * 16;
                uint32_t vh0, vh1, vl0, vl1;
                ldmx2t(vh0, vh1, vbase + vo);
                ldmx2t(vl0, vl1, vbase + KV_MAT + vo);
                mma16816(o_[dt], ph[j], vh0, vh1);
                mma16816(o_[dt], ph[j], vl0, vl1);
                mma16816(o_[dt], pl[j], vh0, vh1);
            }
        }
        __syncthreads();
    }

    // ---- epilogue: normalize, split to bf16 hi/lo ----
    float inv0 = 1.f / l_[0], inv1 = 1.f / l_[1];
#pragma unroll
    for (int hh = 0; hh < 2; hh++) {
        float inv = hh == 0 ? inv0 : inv1;
        size_t grow = qrow0 + wid * 16 + (lane >> 2) + hh * 8;
#pragma unroll
        for (int dt = 0; dt < 8; dt++) {
            size_t idx = grow * DQ + col0 + dt * 8 + (lane & 3) * 2;
            float f0 = o_[dt][hh * 2] * inv;
            float f1 = o_[dt][hh * 2 + 1] * inv;
            bf h0, l0, h1, l1;
            split_bf16(f0, h0, l0); split_bf16(f1, h1, l1);
            *(__nv_bfloat162*)(OHp + idx) = __nv_bfloat162(h0, h1);
            *(__nv_bfloat162*)(OLp + idx) = __nv_bfloat162(l0, l1);
        }
    }
}

// ---------------------------------------------------------------------------
// kernel_launch
// ---------------------------------------------------------------------------
extern "C" void kernel_launch(void* const* d_in, const int* in_sizes, int n_in,
                              void* d_out, int out_size) {
    const float* x_q   = (const float*)d_in[0];
    const float* x_kv  = (const float*)d_in[1];
    const float* qn_g  = (const float*)d_in[2];
    const float* qn_b  = (const float*)d_in[3];
    const float* kvn_g = (const float*)d_in[4];
    const float* kvn_b = (const float*)d_in[5];
    const float* Wq    = (const float*)d_in[6];
    const float* bq    = (const float*)d_in[7];
    const float* Wk    = (const float*)d_in[8];
    const float* bk    = (const float*)d_in[9];
    const float* Wv    = (const float*)d_in[10];
    const float* bv    = (const float*)d_in[11];
    const float* Wo    = (const float*)d_in[12];
    const float* bo    = (const float*)d_in[13];
    const float* n2_g  = (const float*)d_in[14];
    const float* n2_b  = (const float*)d_in[15];
    const float* W1    = (const float*)d_in[16];
    const float* b1    = (const float*)d_in[17];
    const float* W2    = (const float*)d_in[18];
    const float* b2    = (const float*)d_in[19];
    float* out = (float*)d_out;

    bf* bfb = nullptr;
    cudaGetSymbolAddress((void**)&bfb, g_bf);

    bf* XQH = bfb + (size_t)O_XQH * EM;   bf* XQL = bfb + (size_t)O_XQL * EM;
    bf* XKVH = bfb + (size_t)O_XKVH * EM; bf* XKVL = bfb + (size_t)O_XKVL * EM;
    bf* ATTH = bfb + (size_t)O_ATTH * EM; bf* ATTL = bfb + (size_t)O_ATTL * EM;
    bf* X2H = bfb + (size_t)O_X2H * EM;   bf* X2L = bfb + (size_t)O_X2L * EM;
    bf* Hh  = bfb + (size_t)O_HH * EM;    bf* Hl  = bfb + (size_t)O_HL * EM;
    bf* WQH = bfb + (size_t)O_WQH * EM;   bf* WQL = bfb + (size_t)O_WQL * EM;
    bf* WKH = bfb + (size_t)O_WKH * EM;   bf* WKL = bfb + (size_t)O_WKL * EM;
    bf* WVH = bfb + (size_t)O_WVH * EM;   bf* WVL = bfb + (size_t)O_WVL * EM;
    bf* WOH = bfb + (size_t)O_WOH * EM;   bf* WOL = bfb + (size_t)O_WOL * EM;
    bf* W1H = bfb + (size_t)O_W1H * EM;   bf* W1L = bfb + (size_t)O_W1L * EM;
    bf* W2H = bfb + (size_t)O_W2H * EM;   bf* W2L = bfb + (size_t)O_W2L * EM;
    bf* QH  = bfb + (size_t)O_QH * EM;    bf* QL  = bfb + (size_t)O_QL * EM;
    bf* KH  = bfb + (size_t)O_KH * EM;    bf* KL  = bfb + (size_t)O_KL * EM;
    bf* VH  = bfb + (size_t)O_VH * EM;    bf* VL  = bfb + (size_t)O_VL * EM;

    cudaFuncSetAttribute(gemm_mma<0>, cudaFuncAttributeMaxDynamicSharedMemorySize, GEMM_SMEM);
    cudaFuncSetAttribute(gemm_mma<1>, cudaFuncAttributeMaxDynamicSharedMemorySize, GEMM_SMEM);
    cudaFuncSetAttribute(gemm_mma<2>, cudaFuncAttributeMaxDynamicSharedMemorySize, GEMM_SMEM);
    cudaFuncSetAttribute(gemm_mma<3>, cudaFuncAttributeMaxDynamicSharedMemorySize, GEMM_SMEM);
    cudaFuncSetAttribute(gemm_mma<4>, cudaFuncAttributeMaxDynamicSharedMemorySize, GEMM_SMEM);
    cudaFuncSetAttribute(attn_mma, cudaFuncAttributeMaxDynamicSharedMemorySize, ATTN_SMEM);

    // weight splits
    convert_split_kernel<<<1024, 256>>>(Wq, WQH, WQL, EM / 4);
    convert_split_kernel<<<1024, 256>>>(Wk, WKH, WKL, EM / 4);
    convert_split_kernel<<<1024, 256>>>(Wv, WVH, WVL, EM / 4);
    convert_split_kernel<<<1024, 256>>>(Wo, WOH, WOL, EM / 4);
    convert_split_kernel<<<4096, 256>>>(W1, W1H, W1L, EM);
    convert_split_kernel<<<4096, 256>>>(W2, W2H, W2L, EM);

    // LN + split
    ln_bf16_kernel<<<MROWS, 256>>>(x_q, qn_g, qn_b, XQH, XQL);
    ln_bf16_kernel<<<MROWS, 256>>>(x_kv, kvn_g, kvn_b, XKVH, XKVL);

    // Q/K/V projections -> bf16 hi/lo (scale folded into Q)
    gemm_mma<4><<<dim3(DQ / 128, MROWS / 128), 256, GEMM_SMEM>>>(
        XQH, XQL, WQH, WQL, bq, nullptr, nullptr, QH, QL, MROWS, DQ, DQ, 0.125f);
    gemm_mma<4><<<dim3(DQ / 128, MROWS / 128), 256, GEMM_SMEM>>>(
        XKVH, XKVL, WKH, WKL, bk, nullptr, nullptr, KH, KL, MROWS, DQ, DQ, 1.0f);
    gemm_mma<4><<<dim3(DQ / 128, MROWS / 128), 256, GEMM_SMEM>>>(
        XKVH, XKVL, WVH, WVL, bv, nullptr, nullptr, VH, VL, MROWS, DQ, DQ, 1.0f);

    // tensor-core attention
    attn_mma<<<dim3(NN / 128, HH, BB), 256, ATTN_SMEM>>>(
        QH, QL, KH, KL, VH, VL, ATTH, ATTL);

    // out projection + residual with x_q
    gemm_mma<1><<<dim3(DQ / 128, MROWS / 128), 256, GEMM_SMEM>>>(
        ATTH, ATTL, WOH, WOL, bo, x_q, out, nullptr, nullptr, MROWS, DQ, DQ, 1.0f);

    // LN2 + split
    ln_bf16_kernel<<<MROWS, 256>>>(out, n2_g, n2_b, X2H, X2L);

    // MLP up + GELU -> bf16 split
    gemm_mma<2><<<dim3(DFF / 128, MROWS / 128), 256, GEMM_SMEM>>>(
        X2H, X2L, W1H, W1L, b1, nullptr, nullptr, Hh, Hl, MROWS, DFF, DQ, 1.0f);

    // MLP down + residual accumulate into d_out
    gemm_mma<3><<<dim3(DQ / 128, MROWS / 128), 256, GEMM_SMEM>>>(
        Hh, Hl, W2H, W2L, b2, nullptr, out, nullptr, nullptr, MROWS, DQ, DFF, 1.0f);
}

// round 5
// speedup vs baseline: 2.3602x; 1.0045x over previous
#include <cuda_runtime.h>
#include <cuda_bf16.h>
#include <math.h>
#include <stdint.h>

#define BB   2
#define NN   2048
#define LL   2048
#define DQ   1024
#define HH   16
#define HD   64
#define MROWS 4096
#define DFF  4096

typedef __nv_bfloat16 bf;

// ---------------------------------------------------------------------------
// Static scratch
// ---------------------------------------------------------------------------
#define EM (1024u*1024u)
__device__ __align__(256) bf g_bf[112u * EM];

#define O_XQH 0
#define O_XQL 4
#define O_XKVH 8
#define O_XKVL 12
#define O_ATTH 16
#define O_ATTL 20
#define O_X2H 24
#define O_X2L 28
#define O_HH  32
#define O_HL  48
#define O_WQH 64
#define O_WQL 65
#define O_WKH 66
#define O_WKL 67
#define O_WVH 68
#define O_WVL 69
#define O_WOH 70
#define O_WOL 71
#define O_W1H 72
#define O_W1L 76
#define O_W2H 80
#define O_W2L 84
#define O_QH  88
#define O_QL  92
#define O_KH  96
#define O_KL  100
#define O_VH  104
#define O_VL  108

// ---------------------------------------------------------------------------
// helpers
// ---------------------------------------------------------------------------
__device__ __forceinline__ uint32_t smem_u32(const void* p) {
    uint32_t a;
    asm("{ .reg .u64 t; cvta.to.shared.u64 t, %1; cvt.u32.u64 %0, t; }" : "=r"(a) : "l"(p));
    return a;
}
__device__ __forceinline__ void ldmx4(uint32_t& r0, uint32_t& r1, uint32_t& r2,
                                      uint32_t& r3, uint32_t a) {
    asm volatile("ldmatrix.sync.aligned.m8n8.x4.shared.b16 {%0,%1,%2,%3}, [%4];"
                 : "=r"(r0), "=r"(r1), "=r"(r2), "=r"(r3) : "r"(a));
}
__device__ __forceinline__ void ldmx2(uint32_t& r0, uint32_t& r1, uint32_t a) {
    asm volatile("ldmatrix.sync.aligned.m8n8.x2.shared.b16 {%0,%1}, [%2];"
                 : "=r"(r0), "=r"(r1) : "r"(a));
}
__device__ __forceinline__ void ldmx2t(uint32_t& r0, uint32_t& r1, uint32_t a) {
    asm volatile("ldmatrix.sync.aligned.m8n8.x2.trans.shared.b16 {%0,%1}, [%2];"
                 : "=r"(r0), "=r"(r1) : "r"(a));
}
__device__ __forceinline__ void mma16816(float* d, const uint32_t* a,
                                         uint32_t b0, uint32_t b1) {
    asm volatile(
        "mma.sync.aligned.m16n8k16.row.col.f32.bf16.bf16.f32 "
        "{%0,%1,%2,%3}, {%4,%5,%6,%7}, {%8,%9}, {%0,%1,%2,%3};"
        : "+f"(d[0]), "+f"(d[1]), "+f"(d[2]), "+f"(d[3])
        : "r"(a[0]), "r"(a[1]), "r"(a[2]), "r"(a[3]), "r"(b0), "r"(b1));
}
__device__ __forceinline__ void cp16(uint32_t dst, const void* src) {
    asm volatile("cp.async.cg.shared.global [%0], [%1], 16;" :: "r"(dst), "l"(src));
}
#define CP_COMMIT() asm volatile("cp.async.commit_group;" ::: "memory")
#define CP_WAIT0()  asm volatile("cp.async.wait_group 0;" ::: "memory")
#define CP_WAIT1()  asm volatile("cp.async.wait_group 1;" ::: "memory")

__device__ __forceinline__ float gelu_exact(float x) {
    return 0.5f * x * (1.f + erff(x * 0.7071067811865476f));
}
__device__ __forceinline__ void split_bf16(float x, bf& h, bf& l) {
    h = __float2bfloat16(x);
    l = __float2bfloat16(x - __bfloat162float(h));
}
__device__ __forceinline__ void split2pack(float a, float b, uint32_t& hi, uint32_t& lo) {
    bf ha = __float2bfloat16(a), hb = __float2bfloat16(b);
    float ra = a - __bfloat162float(ha), rb = b - __bfloat162float(hb);
    __nv_bfloat162 H(ha, hb);
    __nv_bfloat162 L(__float2bfloat16(ra), __float2bfloat16(rb));
    hi = *(uint32_t*)&H;
    lo = *(uint32_t*)&L;
}

// ---------------------------------------------------------------------------
// Fused LayerNorm (two tensors) -> bf16 hi/lo split
// ---------------------------------------------------------------------------
__global__ void ln2x_bf16_kernel(const float* __restrict__ xA,
                                 const float* __restrict__ gA,
                                 const float* __restrict__ bA,
                                 bf* __restrict__ yhA, bf* __restrict__ ylA,
                                 const float* __restrict__ xB,
                                 const float* __restrict__ gB,
                                 const float* __restrict__ bB,
                                 bf* __restrict__ yhB, bf* __restrict__ ylB) {
    int row = blockIdx.x;
    const float* x; const float* g; const float* b; bf* yh; bf* yl;
    if (row < MROWS) { x = xA; g = gA; b = bA; yh = yhA; yl = ylA; }
    else { x = xB; g = gB; b = bB; yh = yhB; yl = ylB; row -= MROWS; }

    const float* xr = x + (size_t)row * DQ;
    float v[4];
    float s = 0.f, s2 = 0.f;
#pragma unroll
    for (int i = 0; i < 4; i++) {
        float t = xr[threadIdx.x + i * 256];
        v[i] = t; s += t; s2 += t * t;
    }
#pragma unroll
    for (int o = 16; o > 0; o >>= 1) {
        s  += __shfl_xor_sync(0xffffffffu, s,  o);
        s2 += __shfl_xor_sync(0xffffffffu, s2, o);
    }
    __shared__ float ws[8], ws2[8];
    int w = threadIdx.x >> 5, lane = threadIdx.x & 31;
    if (lane == 0) { ws[w] = s; ws2[w] = s2; }
    __syncthreads();
    if (w == 0) {
        s  = (lane < 8) ? ws[lane]  : 0.f;
        s2 = (lane < 8) ? ws2[lane] : 0.f;
#pragma unroll
        for (int o = 4; o > 0; o >>= 1) {
            s  += __shfl_xor_sync(0xffffffffu, s,  o);
            s2 += __shfl_xor_sync(0xffffffffu, s2, o);
        }
        if (lane == 0) { ws[0] = s; ws2[0] = s2; }
    }
    __syncthreads();
    float mean = ws[0] * (1.f / DQ);
    float var  = ws2[0] * (1.f / DQ) - mean * mean;
    float rstd = rsqrtf(var + 1e-5f);
    size_t base = (size_t)row * DQ;
#pragma unroll
    for (int i = 0; i < 4; i++) {
        int c = threadIdx.x + i * 256;
        float yv = (v[i] - mean) * rstd * g[c] + b[c];
        bf h, l; split_bf16(yv, h, l);
        yh[base + c] = h;
        yl[base + c] = l;
    }
}

// single-tensor LN (for LN2)
__global__ void ln_bf16_kernel(const float* __restrict__ x,
                               const float* __restrict__ g,
                               const float* __restrict__ b,
                               bf* __restrict__ yh, bf* __restrict__ yl) {
    int row = blockIdx.x;
    const float* xr = x + (size_t)row * DQ;
    float v[4];
    float s = 0.f, s2 = 0.f;
#pragma unroll
    for (int i = 0; i < 4; i++) {
        float t = xr[threadIdx.x + i * 256];
        v[i] = t; s += t; s2 += t * t;
    }
#pragma unroll
    for (int o = 16; o > 0; o >>= 1) {
        s  += __shfl_xor_sync(0xffffffffu, s,  o);
        s2 += __shfl_xor_sync(0xffffffffu, s2, o);
    }
    __shared__ float ws[8], ws2[8];
    int w = threadIdx.x >> 5, lane = threadIdx.x & 31;
    if (lane == 0) { ws[w] = s; ws2[w] = s2; }
    __syncthreads();
    if (w == 0) {
        s  = (lane < 8) ? ws[lane]  : 0.f;
        s2 = (lane < 8) ? ws2[lane] : 0.f;
#pragma unroll
        for (int o = 4; o > 0; o >>= 1) {
            s  += __shfl_xor_sync(0xffffffffu, s,  o);
            s2 += __shfl_xor_sync(0xffffffffu, s2, o);
        }
        if (lane == 0) { ws[0] = s; ws2[0] = s2; }
    }
    __syncthreads();
    float mean = ws[0] * (1.f / DQ);
    float var  = ws2[0] * (1.f / DQ) - mean * mean;
    float rstd = rsqrtf(var + 1e-5f);
    size_t base = (size_t)row * DQ;
#pragma unroll
    for (int i = 0; i < 4; i++) {
        int c = threadIdx.x + i * 256;
        float yv = (v[i] - mean) * rstd * g[c] + b[c];
        bf h, l; split_bf16(yv, h, l);
        yh[base + c] = h;
        yl[base + c] = l;
    }
}

// ---------------------------------------------------------------------------
// Fused weight converts: 4 x 1M-elem tensors in one launch
// ---------------------------------------------------------------------------
__global__ void convert4_kernel(const float* __restrict__ w0, const float* __restrict__ w1,
                                const float* __restrict__ w2, const float* __restrict__ w3,
                                bf* __restrict__ h0, bf* __restrict__ l0,
                                bf* __restrict__ h1, bf* __restrict__ l1,
                                bf* __restrict__ h2, bf* __restrict__ l2,
                                bf* __restrict__ h3, bf* __restrict__ l3) {
    int i = blockIdx.x * blockDim.x + threadIdx.x;   // 0 .. 4*262144-1 (float4 idx)
    int seg = i >> 18;
    int off = i & 0x3FFFF;
    const float* w = seg == 0 ? w0 : seg == 1 ? w1 : seg == 2 ? w2 : w3;
    bf* h = seg == 0 ? h0 : seg == 1 ? h1 : seg == 2 ? h2 : h3;
    bf* l = seg == 0 ? l0 : seg == 1 ? l1 : seg == 2 ? l2 : l3;
    float4 v = ((const float4*)w)[off];
    bf a0, b0, a1, b1, a2, b2, a3, b3;
    split_bf16(v.x, a0, b0); split_bf16(v.y, a1, b1);
    split_bf16(v.z, a2, b2); split_bf16(v.w, a3, b3);
    __nv_bfloat162* hp = (__nv_bfloat162*)(h + (size_t)off * 4);
    __nv_bfloat162* lp = (__nv_bfloat162*)(l + (size_t)off * 4);
    hp[0] = __nv_bfloat162(a0, a1); hp[1] = __nv_bfloat162(a2, a3);
    lp[0] = __nv_bfloat162(b0, b1); lp[1] = __nv_bfloat162(b2, b3);
}

// 2 x 4M-elem tensors in one launch
__global__ void convert2_kernel(const float* __restrict__ w0, const float* __restrict__ w1,
                                bf* __restrict__ h0, bf* __restrict__ l0,
                                bf* __restrict__ h1, bf* __restrict__ l1) {
    int i = blockIdx.x * blockDim.x + threadIdx.x;   // 0 .. 2*1048576-1
    int seg = i >> 20;
    int off = i & 0xFFFFF;
    const float* w = seg == 0 ? w0 : w1;
    bf* h = seg == 0 ? h0 : h1;
    bf* l = seg == 0 ? l0 : l1;
    float4 v = ((const float4*)w)[off];
    bf a0, b0, a1, b1, a2, b2, a3, b3;
    split_bf16(v.x, a0, b0); split_bf16(v.y, a1, b1);
    split_bf16(v.z, a2, b2); split_bf16(v.w, a3, b3);
    __nv_bfloat162* hp = (__nv_bfloat162*)(h + (size_t)off * 4);
    __nv_bfloat162* lp = (__nv_bfloat162*)(l + (size_t)off * 4);
    hp[0] = __nv_bfloat162(a0, a1); hp[1] = __nv_bfloat162(a2, a3);
    lp[0] = __nv_bfloat162(b0, b1); lp[1] = __nv_bfloat162(b2, b3);
}

// ---------------------------------------------------------------------------
// HMMA GEMM (bf16x3 split), dependency-interleaved MMA order.
// EPI: 0 bias->fp32; 1 bias+res->fp32; 2 gelu->bf16 hi/lo; 3 bias+C rmw;
// 4 (acc+bias)*alpha -> bf16 hi/lo
// ---------------------------------------------------------------------------
#define PITCHB 80
#define MAT_BYTES (128 * PITCHB)
#define STAGE_BYTES (4 * MAT_BYTES)
#define GEMM_SMEM (2 * STAGE_BYTES)

template <int EPI>
__global__ void __launch_bounds__(256, 1)
gemm_mma(const bf* __restrict__ Ah, const bf* __restrict__ Al,
         const bf* __restrict__ Bh, const bf* __restrict__ Bl,
         const float* __restrict__ bias, const float* __restrict__ res,
         float* __restrict__ C, bf* __restrict__ Ho, bf* __restrict__ Lo,
         int M, int N, int K, float alpha) {
    extern __shared__ char smc[];
    const int tid = threadIdx.x, lane = tid & 31, wid = tid >> 5;
    const int wm = wid & 1, wn = wid >> 1;
    const size_t m0 = (size_t)blockIdx.y * 128;
    const size_t n0 = (size_t)blockIdx.x * 128;
    const uint32_t sbase = smem_u32(smc);

    const bf* gsrc0 = Ah + m0 * K;
    const bf* gsrc1 = Al + m0 * K;
    const bf* gsrc2 = Bh + n0 * K;
    const bf* gsrc3 = Bl + n0 * K;

    auto load_stage = [&](int s, int kt) {
        uint32_t base = sbase + s * STAGE_BYTES;
#pragma unroll
        for (int i = 0; i < 8; i++) {
            const int t = i >> 1;
            int idx = tid + (i & 1) * 256;
            int row = idx >> 2, seg = idx & 3;
            const bf* src = (t == 0 ? gsrc0 : t == 1 ? gsrc1 : t == 2 ? gsrc2 : gsrc3);
            cp16(base + t * MAT_BYTES + row * PITCHB + seg * 16,
                 src + (size_t)row * K + kt + seg * 8);
        }
    };

    float acc[4][4][4];
#pragma unroll
    for (int a = 0; a < 4; a++)
#pragma unroll
        for (int b = 0; b < 4; b++)
#pragma unroll
            for (int c = 0; c < 4; c++) acc[a][b][c] = 0.f;

    const int nk = K >> 5;
    load_stage(0, 0);
    CP_COMMIT();

    for (int cc = 0; cc < nk; cc++) {
        CP_WAIT0();
        __syncthreads();
        if (cc + 1 < nk) { load_stage((cc + 1) & 1, (cc + 1) << 5); CP_COMMIT(); }

        uint32_t st = sbase + (cc & 1) * STAGE_BYTES;
        uint32_t sAh = st, sAl = st + MAT_BYTES;
        uint32_t sBh = st + 2 * MAT_BYTES, sBl = st + 3 * MAT_BYTES;

#pragma unroll
        for (int k16 = 0; k16 < 2; k16++) {
            uint32_t acol = (uint32_t)(k16 * 16 + ((lane >> 4) << 3)) * 2;
            uint32_t arow = (uint32_t)(wm * 64 + (lane & 15));
            uint32_t ah[4][4], al[4][4];
#pragma unroll
            for (int mt = 0; mt < 4; mt++) {
                uint32_t ao = (arow + mt * 16) * PITCHB + acol;
                ldmx4(ah[mt][0], ah[mt][1], ah[mt][2], ah[mt][3], sAh + ao);
                ldmx4(al[mt][0], al[mt][1], al[mt][2], al[mt][3], sAl + ao);
            }
            uint32_t bcol = (uint32_t)(k16 * 16 + (((lane >> 3) & 1) << 3)) * 2;
            uint32_t brow = (uint32_t)(wn * 32 + (lane & 7));
#pragma unroll
            for (int nt = 0; nt < 4; nt++) {
                uint32_t bo = (brow + nt * 8) * PITCHB + bcol;
                uint32_t bh0, bh1, bl0, bl1;
                ldmx2(bh0, bh1, sBh + bo);
                ldmx2(bl0, bl1, sBl + bo);
                // term-major: same-acc MMAs are 4 apart (no RAW chains)
#pragma unroll
                for (int mt = 0; mt < 4; mt++) mma16816(acc[mt][nt], ah[mt], bh0, bh1);
#pragma unroll
                for (int mt = 0; mt < 4; mt++) mma16816(acc[mt][nt], ah[mt], bl0, bl1);
#pragma unroll
                for (int mt = 0; mt < 4; mt++) mma16816(acc[mt][nt], al[mt], bh0, bh1);
            }
        }
    }

#pragma unroll
    for (int mt = 0; mt < 4; mt++) {
        int r0 = wm * 64 + mt * 16 + (lane >> 2);
#pragma unroll
        for (int nt = 0; nt < 4; nt++) {
            size_t gcol = n0 + wn * 32 + nt * 8 + (lane & 3) * 2;
            float2 bb = *(const float2*)(bias + gcol);
#pragma unroll
            for (int h = 0; h < 2; h++) {
                size_t grow = m0 + r0 + h * 8;
                size_t idx = grow * (size_t)N + gcol;
                float v0 = acc[mt][nt][h * 2 + 0] + bb.x;
                float v1 = acc[mt][nt][h * 2 + 1] + bb.y;
                if (EPI == 1) {
                    float2 rr = *(const float2*)(res + idx);
                    v0 += rr.x; v1 += rr.y;
                }
                if (EPI == 3) {
                    float2 rr = *(const float2*)(C + idx);
                    v0 += rr.x; v1 += rr.y;
                }
                if (EPI == 2 || EPI == 4) {
                    if (EPI == 2) { v0 = gelu_exact(v0); v1 = gelu_exact(v1); }
                    else          { v0 *= alpha; v1 *= alpha; }
                    bf h0, l0, h1, l1;
                    split_bf16(v0, h0, l0); split_bf16(v1, h1, l1);
                    *(__nv_bfloat162*)(Ho + idx) = __nv_bfloat162(h0, h1);
                    *(__nv_bfloat162*)(Lo + idx) = __nv_bfloat162(l0, l1);
                } else {
                    float2 o; o.x = v0; o.y = v1;
                    *(float2*)(C + idx) = o;
                }
            }
        }
    }
}

// ---------------------------------------------------------------------------
// Tensor-core flash attention, softmax-1, pair-interleaved MMAs.
// ---------------------------------------------------------------------------
#define APB 144
#define KV_MAT (64 * APB)
#define KV_STAGE (4 * KV_MAT)
#define ATTN_SMEM (2 * KV_STAGE)

__global__ void __launch_bounds__(256, 1)
attn_mma(const bf* __restrict__ QHp, const bf* __restrict__ QLp,
         const bf* __restrict__ KHp, const bf* __restrict__ KLp,
         const bf* __restrict__ VHp, const bf* __restrict__ VLp,
         bf* __restrict__ OHp, bf* __restrict__ OLp) {
    extern __shared__ char smc[];
    const uint32_t sb = smem_u32(smc);
    const int tid = threadIdx.x, lane = tid & 31, wid = tid >> 5;
    const int b = blockIdx.z, h = blockIdx.y;
    const int n0 = blockIdx.x * 128;
    const size_t qrow0 = (size_t)b * NN + n0;
    const size_t col0 = (size_t)h * HD;

    // ---- stage Q (hi/lo) through smem into A-fragments ----
    {
        const bf* s0 = QHp + qrow0 * DQ + col0;
        const bf* s1 = QLp + qrow0 * DQ + col0;
#pragma unroll
        for (int it = 0; it < 8; it++) {
            int g = it * 256 + tid;
            int m = g >> 10;
            int r = (g & 1023) >> 3, c = g & 7;
            const bf* src = m == 0 ? s0 : s1;
            cp16(sb + m * (128 * APB) + r * APB + c * 16, src + (size_t)r * DQ + c * 8);
        }
    }
    CP_COMMIT();
    CP_WAIT0();
    __syncthreads();

    uint32_t qh[4][4], ql[4][4];
#pragma unroll
    for (int k16 = 0; k16 < 4; k16++) {
        uint32_t ao = (uint32_t)(wid * 16 + (lane & 15)) * APB
                    + (uint32_t)(k16 * 16 + (lane >> 4) * 8) * 2;
        ldmx4(qh[k16][0], qh[k16][1], qh[k16][2], qh[k16][3], sb + ao);
        ldmx4(ql[k16][0], ql[k16][1], ql[k16][2], ql[k16][3], sb + 128 * APB + ao);
    }
    __syncthreads();

    const bf* kvsrc[4] = {
        KHp + ((size_t)b * LL) * DQ + col0,
        KLp + ((size_t)b * LL) * DQ + col0,
        VHp + ((size_t)b * LL) * DQ + col0,
        VLp + ((size_t)b * LL) * DQ + col0
    };
    auto load_kv = [&](int blk, int s) {
        uint32_t base = sb + s * KV_STAGE;
        size_t roff = (size_t)blk * 64;
#pragma unroll
        for (int it = 0; it < 8; it++) {
            int g = it * 256 + tid;
            int m = g >> 9;
            int r = (g & 511) >> 3, c = g & 7;
            cp16(base + m * KV_MAT + r * APB + c * 16,
                 kvsrc[m] + (roff + r) * DQ + c * 8);
        }
    };

    float m_[2] = {0.f, 0.f}, l_[2] = {1.f, 1.f};
    float o_[8][4];
#pragma unroll
    for (int d = 0; d < 8; d++)
#pragma unroll
        for (int j = 0; j < 4; j++) o_[d][j] = 0.f;

    load_kv(0, 0);
    CP_COMMIT();

    const int NBLK = LL / 64;
    for (int i = 0; i < NBLK; i++) {
        if (i + 1 < NBLK) { load_kv(i + 1, (i + 1) & 1); CP_COMMIT(); CP_WAIT1(); }
        else CP_WAIT0();
        __syncthreads();

        uint32_t stg = sb + (i & 1) * KV_STAGE;

        // ---- S = Q K^T (pair-interleaved) ----
        float s_[8][4];
#pragma unroll
        for (int nt = 0; nt < 8; nt++)
#pragma unroll
            for (int j = 0; j < 4; j++) s_[nt][j] = 0.f;

#pragma unroll
        for (int k16 = 0; k16 < 4; k16++) {
            uint32_t bcol = (uint32_t)(k16 * 16 + ((lane >> 3) & 1) * 8) * 2;
            uint32_t brow = (uint32_t)(lane & 7);
#pragma unroll
            for (int ntp = 0; ntp < 4; ntp++) {
                int nt0 = 2 * ntp, nt1 = nt0 + 1;
                uint32_t boA = (brow + nt0 * 8) * APB + bcol;
                uint32_t boB = (brow + nt1 * 8) * APB + bcol;
                uint32_t kha0, kha1, kla0, kla1, khb0, khb1, klb0, klb1;
                ldmx2(kha0, kha1, stg + boA);
                ldmx2(khb0, khb1, stg + boB);
                ldmx2(kla0, kla1, stg + KV_MAT + boA);
                ldmx2(klb0, klb1, stg + KV_MAT + boB);
                mma16816(s_[nt0], qh[k16], kha0, kha1);
                mma16816(s_[nt1], qh[k16], khb0, khb1);
                mma16816(s_[nt0], qh[k16], kla0, kla1);
                mma16816(s_[nt1], qh[k16], klb0, klb1);
                mma16816(s_[nt0], ql[k16], kha0, kha1);
                mma16816(s_[nt1], ql[k16], khb0, khb1);
            }
        }

        // ---- online softmax-1 ----
#pragma unroll
        for (int hh = 0; hh < 2; hh++) {
            float mx = s_[0][hh * 2];
#pragma unroll
            for (int nt = 0; nt < 8; nt++)
                mx = fmaxf(mx, fmaxf(s_[nt][hh * 2], s_[nt][hh * 2 + 1]));
            mx = fmaxf(mx, __shfl_xor_sync(0xffffffffu, mx, 1));
            mx = fmaxf(mx, __shfl_xor_sync(0xffffffffu, mx, 2));
            float mn = fmaxf(m_[hh], mx);
            float corr = __expf(m_[hh] - mn);
            m_[hh] = mn;
            float sum = 0.f;
#pragma unroll
            for (int nt = 0; nt < 8; nt++) {
                float p0 = __expf(s_[nt][hh * 2] - mn);
                float p1 = __expf(s_[nt][hh * 2 + 1] - mn);
                s_[nt][hh * 2] = p0; s_[nt][hh * 2 + 1] = p1;
                sum += p0 + p1;
            }
            sum += __shfl_xor_sync(0xffffffffu, sum, 1);
            sum += __shfl_xor_sync(0xffffffffu, sum, 2);
            l_[hh] = l_[hh] * corr + sum;
#pragma unroll
            for (int d = 0; d < 8; d++) {
                o_[d][hh * 2] *= corr; o_[d][hh * 2 + 1] *= corr;
            }
        }

        // ---- pack P into A-frags (hi/lo) ----
        uint32_t ph[4][4], pl[4][4];
#pragma unroll
        for (int j = 0; j < 4; j++) {
            split2pack(s_[2 * j][0], s_[2 * j][1], ph[j][0], pl[j][0]);
            split2pack(s_[2 * j][2], s_[2 * j][3], ph[j][1], pl[j][1]);
            split2pack(s_[2 * j + 1][0], s_[2 * j + 1][1], ph[j][2], pl[j][2]);
            split2pack(s_[2 * j + 1][2], s_[2 * j + 1][3], ph[j][3], pl[j][3]);
        }

        // ---- O += P V (pair-interleaved) ----
        uint32_t vbase = stg + 2 * KV_MAT;
#pragma unroll
        for (int j = 0; j < 4; j++) {
            uint32_t vrow = (uint32_t)(j * 16 + (lane & 15)) * APB;
#pragma unroll
            for (int dtp = 0; dtp < 4; dtp++) {
                int dt0 = 2 * dtp, dt1 = dt0 + 1;
                uint32_t voA = vrow + dt0 * 16;
                uint32_t voB = vrow + dt1 * 16;
                uint32_t vha0, vha1, vla0, vla1, vhb0, vhb1, vlb0, vlb1;
                ldmx2t(vha0, vha1, vbase + voA);
                ldmx2t(vhb0, vhb1, vbase + voB);
                ldmx2t(vla0, vla1, vbase + KV_MAT + voA);
                ldmx2t(vlb0, vlb1, vbase + KV_MAT + voB);
                mma16816(o_[dt0], ph[j], vha0, vha1);
                mma16816(o_[dt1], ph[j], vhb0, vhb1);
                mma16816(o_[dt0], ph[j], vla0, vla1);
                mma16816(o_[dt1], ph[j], vlb0, vlb1);
                mma16816(o_[dt0], pl[j], vha0, vha1);
                mma16816(o_[dt1], pl[j], vhb0, vhb1);
            }
        }
        __syncthreads();
    }

    // ---- epilogue ----
    float inv0 = 1.f / l_[0], inv1 = 1.f / l_[1];
#pragma unroll
    for (int hh = 0; hh < 2; hh++) {
        float inv = hh == 0 ? inv0 : inv1;
        size_t grow = qrow0 + wid * 16 + (lane >> 2) + hh * 8;
#pragma unroll
        for (int dt = 0; dt < 8; dt++) {
            size_t idx = grow * DQ + col0 + dt * 8 + (lane & 3) * 2;
            float f0 = o_[dt][hh * 2] * inv;
            float f1 = o_[dt][hh * 2 + 1] * inv;
            bf h0, l0, h1, l1;
            split_bf16(f0, h0, l0); split_bf16(f1, h1, l1);
            *(__nv_bfloat162*)(OHp + idx) = __nv_bfloat162(h0, h1);
            *(__nv_bfloat162*)(OLp + idx) = __nv_bfloat162(l0, l1);
        }
    }
}

// ---------------------------------------------------------------------------
// kernel_launch
// ---------------------------------------------------------------------------
extern "C" void kernel_launch(void* const* d_in, const int* in_sizes, int n_in,
                              void* d_out, int out_size) {
    const float* x_q   = (const float*)d_in[0];
    const float* x_kv  = (const float*)d_in[1];
    const float* qn_g  = (const float*)d_in[2];
    const float* qn_b  = (const float*)d_in[3];
    const float* kvn_g = (const float*)d_in[4];
    const float* kvn_b = (const float*)d_in[5];
    const float* Wq    = (const float*)d_in[6];
    const float* bq    = (const float*)d_in[7];
    const float* Wk    = (const float*)d_in[8];
    const float* bk    = (const float*)d_in[9];
    const float* Wv    = (const float*)d_in[10];
    const float* bv    = (const float*)d_in[11];
    const float* Wo    = (const float*)d_in[12];
    const float* bo    = (const float*)d_in[13];
    const float* n2_g  = (const float*)d_in[14];
    const float* n2_b  = (const float*)d_in[15];
    const float* W1    = (const float*)d_in[16];
    const float* b1    = (const float*)d_in[17];
    const float* W2    = (const float*)d_in[18];
    const float* b2    = (const float*)d_in[19];
    float* out = (float*)d_out;

    bf* bfb = nullptr;
    cudaGetSymbolAddress((void**)&bfb, g_bf);

    bf* XQH = bfb + (size_t)O_XQH * EM;   bf* XQL = bfb + (size_t)O_XQL * EM;
    bf* XKVH = bfb + (size_t)O_XKVH * EM; bf* XKVL = bfb + (size_t)O_XKVL * EM;
    bf* ATTH = bfb + (size_t)O_ATTH * EM; bf* ATTL = bfb + (size_t)O_ATTL * EM;
    bf* X2H = bfb + (size_t)O_X2H * EM;   bf* X2L = bfb + (size_t)O_X2L * EM;
    bf* Hh  = bfb + (size_t)O_HH * EM;    bf* Hl  = bfb + (size_t)O_HL * EM;
    bf* WQH = bfb + (size_t)O_WQH * EM;   bf* WQL = bfb + (size_t)O_WQL * EM;
    bf* WKH = bfb + (size_t)O_WKH * EM;   bf* WKL = bfb + (size_t)O_WKL * EM;
    bf* WVH = bfb + (size_t)O_WVH * EM;   bf* WVL = bfb + (size_t)O_WVL * EM;
    bf* WOH = bfb + (size_t)O_WOH * EM;   bf* WOL = bfb + (size_t)O_WOL * EM;
    bf* W1H = bfb + (size_t)O_W1H * EM;   bf* W1L = bfb + (size_t)O_W1L * EM;
    bf* W2H = bfb + (size_t)O_W2H * EM;   bf* W2L = bfb + (size_t)O_W2L * EM;
    bf* QH  = bfb + (size_t)O_QH * EM;    bf* QL  = bfb + (size_t)O_QL * EM;
    bf* KH  = bfb + (size_t)O_KH * EM;    bf* KL  = bfb + (size_t)O_KL * EM;
    bf* VH  = bfb + (size_t)O_VH * EM;    bf* VL  = bfb + (size_t)O_VL * EM;

    cudaFuncSetAttribute(gemm_mma<1>, cudaFuncAttributeMaxDynamicSharedMemorySize, GEMM_SMEM);
    cudaFuncSetAttribute(gemm_mma<2>, cudaFuncAttributeMaxDynamicSharedMemorySize, GEMM_SMEM);
    cudaFuncSetAttribute(gemm_mma<3>, cudaFuncAttributeMaxDynamicSharedMemorySize, GEMM_SMEM);
    cudaFuncSetAttribute(gemm_mma<4>, cudaFuncAttributeMaxDynamicSharedMemorySize, GEMM_SMEM);
    cudaFuncSetAttribute(attn_mma, cudaFuncAttributeMaxDynamicSharedMemorySize, ATTN_SMEM);

    // 1: QKV+O weight splits (one launch)
    convert4_kernel<<<4096, 256>>>(Wq, Wk, Wv, Wo,
                                   WQH, WQL, WKH, WKL, WVH, WVL, WOH, WOL);
    // 2: MLP weight splits (one launch)
    convert2_kernel<<<8192, 256>>>(W1, W2, W1H, W1L, W2H, W2L);

    // 3: both input LNs fused
    ln2x_bf16_kernel<<<2 * MROWS, 256>>>(x_q, qn_g, qn_b, XQH, XQL,
                                         x_kv, kvn_g, kvn_b, XKVH, XKVL);

    // 4-6: Q/K/V projections -> bf16 hi/lo (scale folded into Q)
    gemm_mma<4><<<dim3(DQ / 128, MROWS / 128), 256, GEMM_SMEM>>>(
        XQH, XQL, WQH, WQL, bq, nullptr, nullptr, QH, QL, MROWS, DQ, DQ, 0.125f);
    gemm_mma<4><<<dim3(DQ / 128, MROWS / 128), 256, GEMM_SMEM>>>(
        XKVH, XKVL, WKH, WKL, bk, nullptr, nullptr, KH, KL, MROWS, DQ, DQ, 1.0f);
    gemm_mma<4><<<dim3(DQ / 128, MROWS / 128), 256, GEMM_SMEM>>>(
        XKVH, XKVL, WVH, WVL, bv, nullptr, nullptr, VH, VL, MROWS, DQ, DQ, 1.0f);

    // 7: tensor-core attention
    attn_mma<<<dim3(NN / 128, HH, BB), 256, ATTN_SMEM>>>(
        QH, QL, KH, KL, VH, VL, ATTH, ATTL);

    // 8: out projection + residual with x_q
    gemm_mma<1><<<dim3(DQ / 128, MROWS / 128), 256, GEMM_SMEM>>>(
        ATTH, ATTL, WOH, WOL, bo, x_q, out, nullptr, nullptr, MROWS, DQ, DQ, 1.0f);

    // 9: LN2
    ln_bf16_kernel<<<MROWS, 256>>>(out, n2_g, n2_b, X2H, X2L);

    // 10: MLP up + GELU -> bf16 split
    gemm_mma<2><<<dim3(DFF / 128, MROWS / 128), 256, GEMM_SMEM>>>(
        X2H, X2L, W1H, W1L, b1, nullptr, nullptr, Hh, Hl, MROWS, DFF, DQ, 1.0f);

    // 11: MLP down + residual accumulate into d_out
    gemm_mma<3><<<dim3(DQ / 128, MROWS / 128), 256, GEMM_SMEM>>>(
        Hh, Hl, W2H, W2L, b2, nullptr, out, nullptr, nullptr, MROWS, DQ, DFF, 1.0f);
}

// round 6
// speedup vs baseline: 2.6408x; 1.1189x over previous
#include <cuda_runtime.h>
#include <cuda_bf16.h>
#include <math.h>
#include <stdint.h>

#define BB   2
#define NN   2048
#define LL   2048
#define DQ   1024
#define HH   16
#define HD   64
#define MROWS 4096
#define DFF  4096

typedef __nv_bfloat16 bf;

// ---------------------------------------------------------------------------
// Static scratch
// ---------------------------------------------------------------------------
#define EM (1024u*1024u)
__device__ __align__(256) bf g_bf[112u * EM];

#define O_XQH 0
#define O_XQL 4
#define O_XKVH 8
#define O_XKVL 12
#define O_ATTH 16
#define O_ATTL 20
#define O_X2H 24
#define O_X2L 28
#define O_HH  32
#define O_HL  48
#define O_WQH 64
#define O_WQL 65
#define O_WKH 66
#define O_WKL 67
#define O_WVH 68
#define O_WVL 69
#define O_WOH 70
#define O_WOL 71
#define O_W1H 72
#define O_W1L 76
#define O_W2H 80
#define O_W2L 84
#define O_QH  88
#define O_QL  92
#define O_KH  96
#define O_KL  100
#define O_VH  104
#define O_VL  108

// ---------------------------------------------------------------------------
// helpers
// ---------------------------------------------------------------------------
__device__ __forceinline__ uint32_t smem_u32(const void* p) {
    uint32_t a;
    asm("{ .reg .u64 t; cvta.to.shared.u64 t, %1; cvt.u32.u64 %0, t; }" : "=r"(a) : "l"(p));
    return a;
}
__device__ __forceinline__ void ldmx4(uint32_t& r0, uint32_t& r1, uint32_t& r2,
                                      uint32_t& r3, uint32_t a) {
    asm volatile("ldmatrix.sync.aligned.m8n8.x4.shared.b16 {%0,%1,%2,%3}, [%4];"
                 : "=r"(r0), "=r"(r1), "=r"(r2), "=r"(r3) : "r"(a));
}
__device__ __forceinline__ void ldmx2(uint32_t& r0, uint32_t& r1, uint32_t a) {
    asm volatile("ldmatrix.sync.aligned.m8n8.x2.shared.b16 {%0,%1}, [%2];"
                 : "=r"(r0), "=r"(r1) : "r"(a));
}
__device__ __forceinline__ void ldmx2t(uint32_t& r0, uint32_t& r1, uint32_t a) {
    asm volatile("ldmatrix.sync.aligned.m8n8.x2.trans.shared.b16 {%0,%1}, [%2];"
                 : "=r"(r0), "=r"(r1) : "r"(a));
}
__device__ __forceinline__ void mma16816(float* d, const uint32_t* a,
                                         uint32_t b0, uint32_t b1) {
    asm volatile(
        "mma.sync.aligned.m16n8k16.row.col.f32.bf16.bf16.f32 "
        "{%0,%1,%2,%3}, {%4,%5,%6,%7}, {%8,%9}, {%0,%1,%2,%3};"
        : "+f"(d[0]), "+f"(d[1]), "+f"(d[2]), "+f"(d[3])
        : "r"(a[0]), "r"(a[1]), "r"(a[2]), "r"(a[3]), "r"(b0), "r"(b1));
}
__device__ __forceinline__ void cp16(uint32_t dst, const void* src) {
    asm volatile("cp.async.cg.shared.global [%0], [%1], 16;" :: "r"(dst), "l"(src));
}
#define CP_COMMIT() asm volatile("cp.async.commit_group;" ::: "memory")
#define CP_WAIT0()  asm volatile("cp.async.wait_group 0;" ::: "memory")
#define CP_WAIT1()  asm volatile("cp.async.wait_group 1;" ::: "memory")

__device__ __forceinline__ float gelu_exact(float x) {
    return 0.5f * x * (1.f + erff(x * 0.7071067811865476f));
}
__device__ __forceinline__ void split_bf16(float x, bf& h, bf& l) {
    h = __float2bfloat16(x);
    l = __float2bfloat16(x - __bfloat162float(h));
}
__device__ __forceinline__ void split2pack(float a, float b, uint32_t& hi, uint32_t& lo) {
    bf ha = __float2bfloat16(a), hb = __float2bfloat16(b);
    float ra = a - __bfloat162float(ha), rb = b - __bfloat162float(hb);
    __nv_bfloat162 H(ha, hb);
    __nv_bfloat162 L(__float2bfloat16(ra), __float2bfloat16(rb));
    hi = *(uint32_t*)&H;
    lo = *(uint32_t*)&L;
}

// ---------------------------------------------------------------------------
// Fused LayerNorm (two tensors) -> bf16 hi/lo split
// ---------------------------------------------------------------------------
__global__ void ln2x_bf16_kernel(const float* __restrict__ xA,
                                 const float* __restrict__ gA,
                                 const float* __restrict__ bA,
                                 bf* __restrict__ yhA, bf* __restrict__ ylA,
                                 const float* __restrict__ xB,
                                 const float* __restrict__ gB,
                                 const float* __restrict__ bB,
                                 bf* __restrict__ yhB, bf* __restrict__ ylB) {
    int row = blockIdx.x;
    const float* x; const float* g; const float* b; bf* yh; bf* yl;
    if (row < MROWS) { x = xA; g = gA; b = bA; yh = yhA; yl = ylA; }
    else { x = xB; g = gB; b = bB; yh = yhB; yl = ylB; row -= MROWS; }

    const float* xr = x + (size_t)row * DQ;
    float v[4];
    float s = 0.f, s2 = 0.f;
#pragma unroll
    for (int i = 0; i < 4; i++) {
        float t = xr[threadIdx.x + i * 256];
        v[i] = t; s += t; s2 += t * t;
    }
#pragma unroll
    for (int o = 16; o > 0; o >>= 1) {
        s  += __shfl_xor_sync(0xffffffffu, s,  o);
        s2 += __shfl_xor_sync(0xffffffffu, s2, o);
    }
    __shared__ float ws[8], ws2[8];
    int w = threadIdx.x >> 5, lane = threadIdx.x & 31;
    if (lane == 0) { ws[w] = s; ws2[w] = s2; }
    __syncthreads();
    if (w == 0) {
        s  = (lane < 8) ? ws[lane]  : 0.f;
        s2 = (lane < 8) ? ws2[lane] : 0.f;
#pragma unroll
        for (int o = 4; o > 0; o >>= 1) {
            s  += __shfl_xor_sync(0xffffffffu, s,  o);
            s2 += __shfl_xor_sync(0xffffffffu, s2, o);
        }
        if (lane == 0) { ws[0] = s; ws2[0] = s2; }
    }
    __syncthreads();
    float mean = ws[0] * (1.f / DQ);
    float var  = ws2[0] * (1.f / DQ) - mean * mean;
    float rstd = rsqrtf(var + 1e-5f);
    size_t base = (size_t)row * DQ;
#pragma unroll
    for (int i = 0; i < 4; i++) {
        int c = threadIdx.x + i * 256;
        float yv = (v[i] - mean) * rstd * g[c] + b[c];
        bf h, l; split_bf16(yv, h, l);
        yh[base + c] = h;
        yl[base + c] = l;
    }
}

// single-tensor LN (for LN2)
__global__ void ln_bf16_kernel(const float* __restrict__ x,
                               const float* __restrict__ g,
                               const float* __restrict__ b,
                               bf* __restrict__ yh, bf* __restrict__ yl) {
    int row = blockIdx.x;
    const float* xr = x + (size_t)row * DQ;
    float v[4];
    float s = 0.f, s2 = 0.f;
#pragma unroll
    for (int i = 0; i < 4; i++) {
        float t = xr[threadIdx.x + i * 256];
        v[i] = t; s += t; s2 += t * t;
    }
#pragma unroll
    for (int o = 16; o > 0; o >>= 1) {
        s  += __shfl_xor_sync(0xffffffffu, s,  o);
        s2 += __shfl_xor_sync(0xffffffffu, s2, o);
    }
    __shared__ float ws[8], ws2[8];
    int w = threadIdx.x >> 5, lane = threadIdx.x & 31;
    if (lane == 0) { ws[w] = s; ws2[w] = s2; }
    __syncthreads();
    if (w == 0) {
        s  = (lane < 8) ? ws[lane]  : 0.f;
        s2 = (lane < 8) ? ws2[lane] : 0.f;
#pragma unroll
        for (int o = 4; o > 0; o >>= 1) {
            s  += __shfl_xor_sync(0xffffffffu, s,  o);
            s2 += __shfl_xor_sync(0xffffffffu, s2, o);
        }
        if (lane == 0) { ws[0] = s; ws2[0] = s2; }
    }
    __syncthreads();
    float mean = ws[0] * (1.f / DQ);
    float var  = ws2[0] * (1.f / DQ) - mean * mean;
    float rstd = rsqrtf(var + 1e-5f);
    size_t base = (size_t)row * DQ;
#pragma unroll
    for (int i = 0; i < 4; i++) {
        int c = threadIdx.x + i * 256;
        float yv = (v[i] - mean) * rstd * g[c] + b[c];
        bf h, l; split_bf16(yv, h, l);
        yh[base + c] = h;
        yl[base + c] = l;
    }
}

// ---------------------------------------------------------------------------
// Fused weight converts
// ---------------------------------------------------------------------------
__global__ void convert4_kernel(const float* __restrict__ w0, const float* __restrict__ w1,
                                const float* __restrict__ w2, const float* __restrict__ w3,
                                bf* __restrict__ h0, bf* __restrict__ l0,
                                bf* __restrict__ h1, bf* __restrict__ l1,
                                bf* __restrict__ h2, bf* __restrict__ l2,
                                bf* __restrict__ h3, bf* __restrict__ l3) {
    int i = blockIdx.x * blockDim.x + threadIdx.x;
    int seg = i >> 18;
    int off = i & 0x3FFFF;
    const float* w = seg == 0 ? w0 : seg == 1 ? w1 : seg == 2 ? w2 : w3;
    bf* h = seg == 0 ? h0 : seg == 1 ? h1 : seg == 2 ? h2 : h3;
    bf* l = seg == 0 ? l0 : seg == 1 ? l1 : seg == 2 ? l2 : l3;
    float4 v = ((const float4*)w)[off];
    bf a0, b0, a1, b1, a2, b2, a3, b3;
    split_bf16(v.x, a0, b0); split_bf16(v.y, a1, b1);
    split_bf16(v.z, a2, b2); split_bf16(v.w, a3, b3);
    __nv_bfloat162* hp = (__nv_bfloat162*)(h + (size_t)off * 4);
    __nv_bfloat162* lp = (__nv_bfloat162*)(l + (size_t)off * 4);
    hp[0] = __nv_bfloat162(a0, a1); hp[1] = __nv_bfloat162(a2, a3);
    lp[0] = __nv_bfloat162(b0, b1); lp[1] = __nv_bfloat162(b2, b3);
}

__global__ void convert2_kernel(const float* __restrict__ w0, const float* __restrict__ w1,
                                bf* __restrict__ h0, bf* __restrict__ l0,
                                bf* __restrict__ h1, bf* __restrict__ l1) {
    int i = blockIdx.x * blockDim.x + threadIdx.x;
    int seg = i >> 20;
    int off = i & 0xFFFFF;
    const float* w = seg == 0 ? w0 : w1;
    bf* h = seg == 0 ? h0 : h1;
    bf* l = seg == 0 ? l0 : l1;
    float4 v = ((const float4*)w)[off];
    bf a0, b0, a1, b1, a2, b2, a3, b3;
    split_bf16(v.x, a0, b0); split_bf16(v.y, a1, b1);
    split_bf16(v.z, a2, b2); split_bf16(v.w, a3, b3);
    __nv_bfloat162* hp = (__nv_bfloat162*)(h + (size_t)off * 4);
    __nv_bfloat162* lp = (__nv_bfloat162*)(l + (size_t)off * 4);
    hp[0] = __nv_bfloat162(a0, a1); hp[1] = __nv_bfloat162(a2, a3);
    lp[0] = __nv_bfloat162(b0, b1); lp[1] = __nv_bfloat162(b2, b3);
}

// ---------------------------------------------------------------------------
// HMMA GEMM (bf16x3 split), B-frags resident / A-frags transient.
// __launch_bounds__(256,2) -> <=128 regs -> 2 CTAs/SM.
// EPI: 0 bias->fp32; 1 bias+res->fp32; 2 gelu->bf16 hi/lo; 3 bias+C rmw;
// 4 (acc+bias)*alpha -> bf16 hi/lo
// ---------------------------------------------------------------------------
#define PITCHB 80
#define MAT_BYTES (128 * PITCHB)
#define STAGE_BYTES (4 * MAT_BYTES)
#define GEMM_SMEM (2 * STAGE_BYTES)

template <int EPI>
__global__ void __launch_bounds__(256, 2)
gemm_mma(const bf* __restrict__ Ah, const bf* __restrict__ Al,
         const bf* __restrict__ Bh, const bf* __restrict__ Bl,
         const float* __restrict__ bias, const float* __restrict__ res,
         float* __restrict__ C, bf* __restrict__ Ho, bf* __restrict__ Lo,
         int M, int N, int K, float alpha) {
    extern __shared__ char smc[];
    const int tid = threadIdx.x, lane = tid & 31, wid = tid >> 5;
    const int wm = wid & 1, wn = wid >> 1;
    const size_t m0 = (size_t)blockIdx.y * 128;
    const size_t n0 = (size_t)blockIdx.x * 128;
    const uint32_t sbase = smem_u32(smc);

    const bf* gsrc0 = Ah + m0 * K;
    const bf* gsrc1 = Al + m0 * K;
    const bf* gsrc2 = Bh + n0 * K;
    const bf* gsrc3 = Bl + n0 * K;

    auto load_stage = [&](int s, int kt) {
        uint32_t base = sbase + s * STAGE_BYTES;
#pragma unroll
        for (int i = 0; i < 8; i++) {
            const int t = i >> 1;
            int idx = tid + (i & 1) * 256;
            int row = idx >> 2, seg = idx & 3;
            const bf* src = (t == 0 ? gsrc0 : t == 1 ? gsrc1 : t == 2 ? gsrc2 : gsrc3);
            cp16(base + t * MAT_BYTES + row * PITCHB + seg * 16,
                 src + (size_t)row * K + kt + seg * 8);
        }
    };

    float acc[4][4][4];
#pragma unroll
    for (int a = 0; a < 4; a++)
#pragma unroll
        for (int b = 0; b < 4; b++)
#pragma unroll
            for (int c = 0; c < 4; c++) acc[a][b][c] = 0.f;

    const int nk = K >> 5;
    load_stage(0, 0);
    CP_COMMIT();

    for (int cc = 0; cc < nk; cc++) {
        CP_WAIT0();
        __syncthreads();
        if (cc + 1 < nk) { load_stage((cc + 1) & 1, (cc + 1) << 5); CP_COMMIT(); }

        uint32_t st = sbase + (cc & 1) * STAGE_BYTES;
        uint32_t sAh = st, sAl = st + MAT_BYTES;
        uint32_t sBh = st + 2 * MAT_BYTES, sBl = st + 3 * MAT_BYTES;

#pragma unroll
        for (int k16 = 0; k16 < 2; k16++) {
            // B fragments resident (16 regs)
            uint32_t bcol = (uint32_t)(k16 * 16 + (((lane >> 3) & 1) << 3)) * 2;
            uint32_t brow = (uint32_t)(wn * 32 + (lane & 7));
            uint32_t bh[4][2], bl[4][2];
#pragma unroll
            for (int nt = 0; nt < 4; nt++) {
                uint32_t bo = (brow + nt * 8) * PITCHB + bcol;
                ldmx2(bh[nt][0], bh[nt][1], sBh + bo);
                ldmx2(bl[nt][0], bl[nt][1], sBl + bo);
            }
            // A fragments transient per mt (8 regs)
            uint32_t acol = (uint32_t)(k16 * 16 + ((lane >> 4) << 3)) * 2;
            uint32_t arow = (uint32_t)(wm * 64 + (lane & 15));
#pragma unroll
            for (int mt = 0; mt < 4; mt++) {
                uint32_t ao = (arow + mt * 16) * PITCHB + acol;
                uint32_t ah[4], al[4];
                ldmx4(ah[0], ah[1], ah[2], ah[3], sAh + ao);
                ldmx4(al[0], al[1], al[2], al[3], sAl + ao);
#pragma unroll
                for (int nt = 0; nt < 4; nt++) mma16816(acc[mt][nt], ah, bh[nt][0], bh[nt][1]);
#pragma unroll
                for (int nt = 0; nt < 4; nt++) mma16816(acc[mt][nt], ah, bl[nt][0], bl[nt][1]);
#pragma unroll
                for (int nt = 0; nt < 4; nt++) mma16816(acc[mt][nt], al, bh[nt][0], bh[nt][1]);
            }
        }
    }

#pragma unroll
    for (int mt = 0; mt < 4; mt++) {
        int r0 = wm * 64 + mt * 16 + (lane >> 2);
#pragma unroll
        for (int nt = 0; nt < 4; nt++) {
            size_t gcol = n0 + wn * 32 + nt * 8 + (lane & 3) * 2;
            float2 bb = *(const float2*)(bias + gcol);
#pragma unroll
            for (int h = 0; h < 2; h++) {
                size_t grow = m0 + r0 + h * 8;
                size_t idx = grow * (size_t)N + gcol;
                float v0 = acc[mt][nt][h * 2 + 0] + bb.x;
                float v1 = acc[mt][nt][h * 2 + 1] + bb.y;
                if (EPI == 1) {
                    float2 rr = *(const float2*)(res + idx);
                    v0 += rr.x; v1 += rr.y;
                }
                if (EPI == 3) {
                    float2 rr = *(const float2*)(C + idx);
                    v0 += rr.x; v1 += rr.y;
                }
                if (EPI == 2 || EPI == 4) {
                    if (EPI == 2) { v0 = gelu_exact(v0); v1 = gelu_exact(v1); }
                    else          { v0 *= alpha; v1 *= alpha; }
                    bf h0, l0, h1, l1;
                    split_bf16(v0, h0, l0); split_bf16(v1, h1, l1);
                    *(__nv_bfloat162*)(Ho + idx) = __nv_bfloat162(h0, h1);
                    *(__nv_bfloat162*)(Lo + idx) = __nv_bfloat162(l0, l1);
                } else {
                    float2 o; o.x = v0; o.y = v1;
                    *(float2*)(C + idx) = o;
                }
            }
        }
    }
}

// ---------------------------------------------------------------------------
// Tensor-core flash attention, softmax-1, pair-interleaved MMAs (unchanged).
// ---------------------------------------------------------------------------
#define APB 144
#define KV_MAT (64 * APB)
#define KV_STAGE (4 * KV_MAT)
#define ATTN_SMEM (2 * KV_STAGE)

__global__ void __launch_bounds__(256, 1)
attn_mma(const bf* __restrict__ QHp, const bf* __restrict__ QLp,
         const bf* __restrict__ KHp, const bf* __restrict__ KLp,
         const bf* __restrict__ VHp, const bf* __restrict__ VLp,
         bf* __restrict__ OHp, bf* __restrict__ OLp) {
    extern __shared__ char smc[];
    const uint32_t sb = smem_u32(smc);
    const int tid = threadIdx.x, lane = tid & 31, wid = tid >> 5;
    const int b = blockIdx.z, h = blockIdx.y;
    const int n0 = blockIdx.x * 128;
    const size_t qrow0 = (size_t)b * NN + n0;
    const size_t col0 = (size_t)h * HD;

    {
        const bf* s0 = QHp + qrow0 * DQ + col0;
        const bf* s1 = QLp + qrow0 * DQ + col0;
#pragma unroll
        for (int it = 0; it < 8; it++) {
            int g = it * 256 + tid;
            int m = g >> 10;
            int r = (g & 1023) >> 3, c = g & 7;
            const bf* src = m == 0 ? s0 : s1;
            cp16(sb + m * (128 * APB) + r * APB + c * 16, src + (size_t)r * DQ + c * 8);
        }
    }
    CP_COMMIT();
    CP_WAIT0();
    __syncthreads();

    uint32_t qh[4][4], ql[4][4];
#pragma unroll
    for (int k16 = 0; k16 < 4; k16++) {
        uint32_t ao = (uint32_t)(wid * 16 + (lane & 15)) * APB
                    + (uint32_t)(k16 * 16 + (lane >> 4) * 8) * 2;
        ldmx4(qh[k16][0], qh[k16][1], qh[k16][2], qh[k16][3], sb + ao);
        ldmx4(ql[k16][0], ql[k16][1], ql[k16][2], ql[k16][3], sb + 128 * APB + ao);
    }
    __syncthreads();

    const bf* kvsrc[4] = {
        KHp + ((size_t)b * LL) * DQ + col0,
        KLp + ((size_t)b * LL) * DQ + col0,
        VHp + ((size_t)b * LL) * DQ + col0,
        VLp + ((size_t)b * LL) * DQ + col0
    };
    auto load_kv = [&](int blk, int s) {
        uint32_t base = sb + s * KV_STAGE;
        size_t roff = (size_t)blk * 64;
#pragma unroll
        for (int it = 0; it < 8; it++) {
            int g = it * 256 + tid;
            int m = g >> 9;
            int r = (g & 511) >> 3, c = g & 7;
            cp16(base + m * KV_MAT + r * APB + c * 16,
                 kvsrc[m] + (roff + r) * DQ + c * 8);
        }
    };

    float m_[2] = {0.f, 0.f}, l_[2] = {1.f, 1.f};
    float o_[8][4];
#pragma unroll
    for (int d = 0; d < 8; d++)
#pragma unroll
        for (int j = 0; j < 4; j++) o_[d][j] = 0.f;

    load_kv(0, 0);
    CP_COMMIT();

    const int NBLK = LL / 64;
    for (int i = 0; i < NBLK; i++) {
        if (i + 1 < NBLK) { load_kv(i + 1, (i + 1) & 1); CP_COMMIT(); CP_WAIT1(); }
        else CP_WAIT0();
        __syncthreads();

        uint32_t stg = sb + (i & 1) * KV_STAGE;

        float s_[8][4];
#pragma unroll
        for (int nt = 0; nt < 8; nt++)
#pragma unroll
            for (int j = 0; j < 4; j++) s_[nt][j] = 0.f;

#pragma unroll
        for (int k16 = 0; k16 < 4; k16++) {
            uint32_t bcol = (uint32_t)(k16 * 16 + ((lane >> 3) & 1) * 8) * 2;
            uint32_t brow = (uint32_t)(lane & 7);
#pragma unroll
            for (int ntp = 0; ntp < 4; ntp++) {
                int nt0 = 2 * ntp, nt1 = nt0 + 1;
                uint32_t boA = (brow + nt0 * 8) * APB + bcol;
                uint32_t boB = (brow + nt1 * 8) * APB + bcol;
                uint32_t kha0, kha1, kla0, kla1, khb0, khb1, klb0, klb1;
                ldmx2(kha0, kha1, stg + boA);
                ldmx2(khb0, khb1, stg + boB);
                ldmx2(kla0, kla1, stg + KV_MAT + boA);
                ldmx2(klb0, klb1, stg + KV_MAT + boB);
                mma16816(s_[nt0], qh[k16], kha0, kha1);
                mma16816(s_[nt1], qh[k16], khb0, khb1);
                mma16816(s_[nt0], qh[k16], kla0, kla1);
                mma16816(s_[nt1], qh[k16], klb0, klb1);
                mma16816(s_[nt0], ql[k16], kha0, kha1);
                mma16816(s_[nt1], ql[k16], khb0, khb1);
            }
        }

#pragma unroll
        for (int hh = 0; hh < 2; hh++) {
            float mx = s_[0][hh * 2];
#pragma unroll
            for (int nt = 0; nt < 8; nt++)
                mx = fmaxf(mx, fmaxf(s_[nt][hh * 2], s_[nt][hh * 2 + 1]));
            mx = fmaxf(mx, __shfl_xor_sync(0xffffffffu, mx, 1));
            mx = fmaxf(mx, __shfl_xor_sync(0xffffffffu, mx, 2));
            float mn = fmaxf(m_[hh], mx);
            float corr = __expf(m_[hh] - mn);
            m_[hh] = mn;
            float sum = 0.f;
#pragma unroll
            for (int nt = 0; nt < 8; nt++) {
                float p0 = __expf(s_[nt][hh * 2] - mn);
                float p1 = __expf(s_[nt][hh * 2 + 1] - mn);
                s_[nt][hh * 2] = p0; s_[nt][hh * 2 + 1] = p1;
                sum += p0 + p1;
            }
            sum += __shfl_xor_sync(0xffffffffu, sum, 1);
            sum += __shfl_xor_sync(0xffffffffu, sum, 2);
            l_[hh] = l_[hh] * corr + sum;
#pragma unroll
            for (int d = 0; d < 8; d++) {
                o_[d][hh * 2] *= corr; o_[d][hh * 2 + 1] *= corr;
            }
        }

        uint32_t ph[4][4], pl[4][4];
#pragma unroll
        for (int j = 0; j < 4; j++) {
            split2pack(s_[2 * j][0], s_[2 * j][1], ph[j][0], pl[j][0]);
            split2pack(s_[2 * j][2], s_[2 * j][3], ph[j][1], pl[j][1]);
            split2pack(s_[2 * j + 1][0], s_[2 * j + 1][1], ph[j][2], pl[j][2]);
            split2pack(s_[2 * j + 1][2], s_[2 * j + 1][3], ph[j][3], pl[j][3]);
        }

        uint32_t vbase = stg + 2 * KV_MAT;
#pragma unroll
        for (int j = 0; j < 4; j++) {
            uint32_t vrow = (uint32_t)(j * 16 + (lane & 15)) * APB;
#pragma unroll
            for (int dtp = 0; dtp < 4; dtp++) {
                int dt0 = 2 * dtp, dt1 = dt0 + 1;
                uint32_t voA = vrow + dt0 * 16;
                uint32_t voB = vrow + dt1 * 16;
                uint32_t vha0, vha1, vla0, vla1, vhb0, vhb1, vlb0, vlb1;
                ldmx2t(vha0, vha1, vbase + voA);
                ldmx2t(vhb0, vhb1, vbase + voB);
                ldmx2t(vla0, vla1, vbase + KV_MAT + voA);
                ldmx2t(vlb0, vlb1, vbase + KV_MAT + voB);
                mma16816(o_[dt0], ph[j], vha0, vha1);
                mma16816(o_[dt1], ph[j], vhb0, vhb1);
                mma16816(o_[dt0], ph[j], vla0, vla1);
                mma16816(o_[dt1], ph[j], vlb0, vlb1);
                mma16816(o_[dt0], pl[j], vha0, vha1);
                mma16816(o_[dt1], pl[j], vhb0, vhb1);
            }
        }
        __syncthreads();
    }

    float inv0 = 1.f / l_[0], inv1 = 1.f / l_[1];
#pragma unroll
    for (int hh = 0; hh < 2; hh++) {
        float inv = hh == 0 ? inv0 : inv1;
        size_t grow = qrow0 + wid * 16 + (lane >> 2) + hh * 8;
#pragma unroll
        for (int dt = 0; dt < 8; dt++) {
            size_t idx = grow * DQ + col0 + dt * 8 + (lane & 3) * 2;
            float f0 = o_[dt][hh * 2] * inv;
            float f1 = o_[dt][hh * 2 + 1] * inv;
            bf h0, l0, h1, l1;
            split_bf16(f0, h0, l0); split_bf16(f1, h1, l1);
            *(__nv_bfloat162*)(OHp + idx) = __nv_bfloat162(h0, h1);
            *(__nv_bfloat162*)(OLp + idx) = __nv_bfloat162(l0, l1);
        }
    }
}

// ---------------------------------------------------------------------------
// kernel_launch
// ---------------------------------------------------------------------------
extern "C" void kernel_launch(void* const* d_in, const int* in_sizes, int n_in,
                              void* d_out, int out_size) {
    const float* x_q   = (const float*)d_in[0];
    const float* x_kv  = (const float*)d_in[1];
    const float* qn_g  = (const float*)d_in[2];
    const float* qn_b  = (const float*)d_in[3];
    const float* kvn_g = (const float*)d_in[4];
    const float* kvn_b = (const float*)d_in[5];
    const float* Wq    = (const float*)d_in[6];
    const float* bq    = (const float*)d_in[7];
    const float* Wk    = (const float*)d_in[8];
    const float* bk    = (const float*)d_in[9];
    const float* Wv    = (const float*)d_in[10];
    const float* bv    = (const float*)d_in[11];
    const float* Wo    = (const float*)d_in[12];
    const float* bo    = (const float*)d_in[13];
    const float* n2_g  = (const float*)d_in[14];
    const float* n2_b  = (const float*)d_in[15];
    const float* W1    = (const float*)d_in[16];
    const float* b1    = (const float*)d_in[17];
    const float* W2    = (const float*)d_in[18];
    const float* b2    = (const float*)d_in[19];
    float* out = (float*)d_out;

    bf* bfb = nullptr;
    cudaGetSymbolAddress((void**)&bfb, g_bf);

    bf* XQH = bfb + (size_t)O_XQH * EM;   bf* XQL = bfb + (size_t)O_XQL * EM;
    bf* XKVH = bfb + (size_t)O_XKVH * EM; bf* XKVL = bfb + (size_t)O_XKVL * EM;
    bf* ATTH = bfb + (size_t)O_ATTH * EM; bf* ATTL = bfb + (size_t)O_ATTL * EM;
    bf* X2H = bfb + (size_t)O_X2H * EM;   bf* X2L = bfb + (size_t)O_X2L * EM;
    bf* Hh  = bfb + (size_t)O_HH * EM;    bf* Hl  = bfb + (size_t)O_HL * EM;
    bf* WQH = bfb + (size_t)O_WQH * EM;   bf* WQL = bfb + (size_t)O_WQL * EM;
    bf* WKH = bfb + (size_t)O_WKH * EM;   bf* WKL = bfb + (size_t)O_WKL * EM;
    bf* WVH = bfb + (size_t)O_WVH * EM;   bf* WVL = bfb + (size_t)O_WVL * EM;
    bf* WOH = bfb + (size_t)O_WOH * EM;   bf* WOL = bfb + (size_t)O_WOL * EM;
    bf* W1H = bfb + (size_t)O_W1H * EM;   bf* W1L = bfb + (size_t)O_W1L * EM;
    bf* W2H = bfb + (size_t)O_W2H * EM;   bf* W2L = bfb + (size_t)O_W2L * EM;
    bf* QH  = bfb + (size_t)O_QH * EM;    bf* QL  = bfb + (size_t)O_QL * EM;
    bf* KH  = bfb + (size_t)O_KH * EM;    bf* KL  = bfb + (size_t)O_KL * EM;
    bf* VH  = bfb + (size_t)O_VH * EM;    bf* VL  = bfb + (size_t)O_VL * EM;

    cudaFuncSetAttribute(gemm_mma<1>, cudaFuncAttributeMaxDynamicSharedMemorySize, GEMM_SMEM);
    cudaFuncSetAttribute(gemm_mma<2>, cudaFuncAttributeMaxDynamicSharedMemorySize, GEMM_SMEM);
    cudaFuncSetAttribute(gemm_mma<3>, cudaFuncAttributeMaxDynamicSharedMemorySize, GEMM_SMEM);
    cudaFuncSetAttribute(gemm_mma<4>, cudaFuncAttributeMaxDynamicSharedMemorySize, GEMM_SMEM);
    cudaFuncSetAttribute(attn_mma, cudaFuncAttributeMaxDynamicSharedMemorySize, ATTN_SMEM);

    convert4_kernel<<<4096, 256>>>(Wq, Wk, Wv, Wo,
                                   WQH, WQL, WKH, WKL, WVH, WVL, WOH, WOL);
    convert2_kernel<<<8192, 256>>>(W1, W2, W1H, W1L, W2H, W2L);

    ln2x_bf16_kernel<<<2 * MROWS, 256>>>(x_q, qn_g, qn_b, XQH, XQL,
                                         x_kv, kvn_g, kvn_b, XKVH, XKVL);

    gemm_mma<4><<<dim3(DQ / 128, MROWS / 128), 256, GEMM_SMEM>>>(
        XQH, XQL, WQH, WQL, bq, nullptr, nullptr, QH, QL, MROWS, DQ, DQ, 0.125f);
    gemm_mma<4><<<dim3(DQ / 128, MROWS / 128), 256, GEMM_SMEM>>>(
        XKVH, XKVL, WKH, WKL, bk, nullptr, nullptr, KH, KL, MROWS, DQ, DQ, 1.0f);
    gemm_mma<4><<<dim3(DQ / 128, MROWS / 128), 256, GEMM_SMEM>>>(
        XKVH, XKVL, WVH, WVL, bv, nullptr, nullptr, VH, VL, MROWS, DQ, DQ, 1.0f);

    attn_mma<<<dim3(NN / 128, HH, BB), 256, ATTN_SMEM>>>(
        QH, QL, KH, KL, VH, VL, ATTH, ATTL);

    gemm_mma<1><<<dim3(DQ / 128, MROWS / 128), 256, GEMM_SMEM>>>(
        ATTH, ATTL, WOH, WOL, bo, x_q, out, nullptr, nullptr, MROWS, DQ, DQ, 1.0f);

    ln_bf16_kernel<<<MROWS, 256>>>(out, n2_g, n2_b, X2H, X2L);

    gemm_mma<2><<<dim3(DFF / 128, MROWS / 128), 256, GEMM_SMEM>>>(
        X2H, X2L, W1H, W1L, b1, nullptr, nullptr, Hh, Hl, MROWS, DFF, DQ, 1.0f);

    gemm_mma<3><<<dim3(DQ / 128, MROWS / 128), 256, GEMM_SMEM>>>(
        Hh, Hl, W2H, W2L, b2, nullptr, out, nullptr, nullptr, MROWS, DQ, DFF, 1.0f);
}

// round 7
// speedup vs baseline: 2.7212x; 1.0304x over previous
#include <cuda_runtime.h>
#include <cuda_bf16.h>
#include <math.h>
#include <stdint.h>

#define BB   2
#define NN   2048
#define LL   2048
#define DQ   1024
#define HH   16
#define HD   64
#define MROWS 4096
#define DFF  4096

typedef __nv_bfloat16 bf;

// ---------------------------------------------------------------------------
// Static scratch
// ---------------------------------------------------------------------------
#define EM (1024u*1024u)
__device__ __align__(256) bf g_bf[112u * EM];

#define O_XQH 0
#define O_XQL 4
#define O_XKVH 8
#define O_XKVL 12
#define O_ATTH 16
#define O_ATTL 20
#define O_X2H 24
#define O_X2L 28
#define O_HH  32
#define O_HL  48
#define O_WQH 64
#define O_WQL 65
#define O_WKH 66
#define O_WKL 67
#define O_WVH 68
#define O_WVL 69
#define O_WOH 70
#define O_WOL 71
#define O_W1H 72
#define O_W1L 76
#define O_W2H 80
#define O_W2L 84
#define O_QH  88
#define O_QL  92
#define O_KH  96
#define O_KL  100
#define O_VH  104
#define O_VL  108

// ---------------------------------------------------------------------------
// helpers
// ---------------------------------------------------------------------------
__device__ __forceinline__ uint32_t smem_u32(const void* p) {
    uint32_t a;
    asm("{ .reg .u64 t; cvta.to.shared.u64 t, %1; cvt.u32.u64 %0, t; }" : "=r"(a) : "l"(p));
    return a;
}
__device__ __forceinline__ void ldmx4(uint32_t& r0, uint32_t& r1, uint32_t& r2,
                                      uint32_t& r3, uint32_t a) {
    asm volatile("ldmatrix.sync.aligned.m8n8.x4.shared.b16 {%0,%1,%2,%3}, [%4];"
                 : "=r"(r0), "=r"(r1), "=r"(r2), "=r"(r3) : "r"(a));
}
__device__ __forceinline__ void ldmx2(uint32_t& r0, uint32_t& r1, uint32_t a) {
    asm volatile("ldmatrix.sync.aligned.m8n8.x2.shared.b16 {%0,%1}, [%2];"
                 : "=r"(r0), "=r"(r1) : "r"(a));
}
__device__ __forceinline__ void ldmx2t(uint32_t& r0, uint32_t& r1, uint32_t a) {
    asm volatile("ldmatrix.sync.aligned.m8n8.x2.trans.shared.b16 {%0,%1}, [%2];"
                 : "=r"(r0), "=r"(r1) : "r"(a));
}
__device__ __forceinline__ void mma16816(float* d, const uint32_t* a,
                                         uint32_t b0, uint32_t b1) {
    asm volatile(
        "mma.sync.aligned.m16n8k16.row.col.f32.bf16.bf16.f32 "
        "{%0,%1,%2,%3}, {%4,%5,%6,%7}, {%8,%9}, {%0,%1,%2,%3};"
        : "+f"(d[0]), "+f"(d[1]), "+f"(d[2]), "+f"(d[3])
        : "r"(a[0]), "r"(a[1]), "r"(a[2]), "r"(a[3]), "r"(b0), "r"(b1));
}
__device__ __forceinline__ void cp16(uint32_t dst, const void* src) {
    asm volatile("cp.async.cg.shared.global [%0], [%1], 16;" :: "r"(dst), "l"(src));
}
#define CP_COMMIT() asm volatile("cp.async.commit_group;" ::: "memory")
#define CP_WAIT0()  asm volatile("cp.async.wait_group 0;" ::: "memory")
#define CP_WAIT1()  asm volatile("cp.async.wait_group 1;" ::: "memory")

__device__ __forceinline__ float gelu_exact(float x) {
    return 0.5f * x * (1.f + erff(x * 0.7071067811865476f));
}
__device__ __forceinline__ void split_bf16(float x, bf& h, bf& l) {
    h = __float2bfloat16(x);
    l = __float2bfloat16(x - __bfloat162float(h));
}
__device__ __forceinline__ void split2pack(float a, float b, uint32_t& hi, uint32_t& lo) {
    bf ha = __float2bfloat16(a), hb = __float2bfloat16(b);
    float ra = a - __bfloat162float(ha), rb = b - __bfloat162float(hb);
    __nv_bfloat162 H(ha, hb);
    __nv_bfloat162 L(__float2bfloat16(ra), __float2bfloat16(rb));
    hi = *(uint32_t*)&H;
    lo = *(uint32_t*)&L;
}

// ---------------------------------------------------------------------------
// Fused LayerNorm (two tensors) -> bf16 hi/lo split
// ---------------------------------------------------------------------------
__global__ void ln2x_bf16_kernel(const float* __restrict__ xA,
                                 const float* __restrict__ gA,
                                 const float* __restrict__ bA,
                                 bf* __restrict__ yhA, bf* __restrict__ ylA,
                                 const float* __restrict__ xB,
                                 const float* __restrict__ gB,
                                 const float* __restrict__ bB,
                                 bf* __restrict__ yhB, bf* __restrict__ ylB) {
    int row = blockIdx.x;
    const float* x; const float* g; const float* b; bf* yh; bf* yl;
    if (row < MROWS) { x = xA; g = gA; b = bA; yh = yhA; yl = ylA; }
    else { x = xB; g = gB; b = bB; yh = yhB; yl = ylB; row -= MROWS; }

    const float* xr = x + (size_t)row * DQ;
    float v[4];
    float s = 0.f, s2 = 0.f;
#pragma unroll
    for (int i = 0; i < 4; i++) {
        float t = xr[threadIdx.x + i * 256];
        v[i] = t; s += t; s2 += t * t;
    }
#pragma unroll
    for (int o = 16; o > 0; o >>= 1) {
        s  += __shfl_xor_sync(0xffffffffu, s,  o);
        s2 += __shfl_xor_sync(0xffffffffu, s2, o);
    }
    __shared__ float ws[8], ws2[8];
    int w = threadIdx.x >> 5, lane = threadIdx.x & 31;
    if (lane == 0) { ws[w] = s; ws2[w] = s2; }
    __syncthreads();
    if (w == 0) {
        s  = (lane < 8) ? ws[lane]  : 0.f;
        s2 = (lane < 8) ? ws2[lane] : 0.f;
#pragma unroll
        for (int o = 4; o > 0; o >>= 1) {
            s  += __shfl_xor_sync(0xffffffffu, s,  o);
            s2 += __shfl_xor_sync(0xffffffffu, s2, o);
        }
        if (lane == 0) { ws[0] = s; ws2[0] = s2; }
    }
    __syncthreads();
    float mean = ws[0] * (1.f / DQ);
    float var  = ws2[0] * (1.f / DQ) - mean * mean;
    float rstd = rsqrtf(var + 1e-5f);
    size_t base = (size_t)row * DQ;
#pragma unroll
    for (int i = 0; i < 4; i++) {
        int c = threadIdx.x + i * 256;
        float yv = (v[i] - mean) * rstd * g[c] + b[c];
        bf h, l; split_bf16(yv, h, l);
        yh[base + c] = h;
        yl[base + c] = l;
    }
}

// single-tensor LN (for LN2)
__global__ void ln_bf16_kernel(const float* __restrict__ x,
                               const float* __restrict__ g,
                               const float* __restrict__ b,
                               bf* __restrict__ yh, bf* __restrict__ yl) {
    int row = blockIdx.x;
    const float* xr = x + (size_t)row * DQ;
    float v[4];
    float s = 0.f, s2 = 0.f;
#pragma unroll
    for (int i = 0; i < 4; i++) {
        float t = xr[threadIdx.x + i * 256];
        v[i] = t; s += t; s2 += t * t;
    }
#pragma unroll
    for (int o = 16; o > 0; o >>= 1) {
        s  += __shfl_xor_sync(0xffffffffu, s,  o);
        s2 += __shfl_xor_sync(0xffffffffu, s2, o);
    }
    __shared__ float ws[8], ws2[8];
    int w = threadIdx.x >> 5, lane = threadIdx.x & 31;
    if (lane == 0) { ws[w] = s; ws2[w] = s2; }
    __syncthreads();
    if (w == 0) {
        s  = (lane < 8) ? ws[lane]  : 0.f;
        s2 = (lane < 8) ? ws2[lane] : 0.f;
#pragma unroll
        for (int o = 4; o > 0; o >>= 1) {
            s  += __shfl_xor_sync(0xffffffffu, s,  o);
            s2 += __shfl_xor_sync(0xffffffffu, s2, o);
        }
        if (lane == 0) { ws[0] = s; ws2[0] = s2; }
    }
    __syncthreads();
    float mean = ws[0] * (1.f / DQ);
    float var  = ws2[0] * (1.f / DQ) - mean * mean;
    float rstd = rsqrtf(var + 1e-5f);
    size_t base = (size_t)row * DQ;
#pragma unroll
    for (int i = 0; i < 4; i++) {
        int c = threadIdx.x + i * 256;
        float yv = (v[i] - mean) * rstd * g[c] + b[c];
        bf h, l; split_bf16(yv, h, l);
        yh[base + c] = h;
        yl[base + c] = l;
    }
}

// ---------------------------------------------------------------------------
// Fused weight converts
// ---------------------------------------------------------------------------
__global__ void convert4_kernel(const float* __restrict__ w0, const float* __restrict__ w1,
                                const float* __restrict__ w2, const float* __restrict__ w3,
                                bf* __restrict__ h0, bf* __restrict__ l0,
                                bf* __restrict__ h1, bf* __restrict__ l1,
                                bf* __restrict__ h2, bf* __restrict__ l2,
                                bf* __restrict__ h3, bf* __restrict__ l3) {
    int i = blockIdx.x * blockDim.x + threadIdx.x;
    int seg = i >> 18;
    int off = i & 0x3FFFF;
    const float* w = seg == 0 ? w0 : seg == 1 ? w1 : seg == 2 ? w2 : w3;
    bf* h = seg == 0 ? h0 : seg == 1 ? h1 : seg == 2 ? h2 : h3;
    bf* l = seg == 0 ? l0 : seg == 1 ? l1 : seg == 2 ? l2 : l3;
    float4 v = ((const float4*)w)[off];
    bf a0, b0, a1, b1, a2, b2, a3, b3;
    split_bf16(v.x, a0, b0); split_bf16(v.y, a1, b1);
    split_bf16(v.z, a2, b2); split_bf16(v.w, a3, b3);
    __nv_bfloat162* hp = (__nv_bfloat162*)(h + (size_t)off * 4);
    __nv_bfloat162* lp = (__nv_bfloat162*)(l + (size_t)off * 4);
    hp[0] = __nv_bfloat162(a0, a1); hp[1] = __nv_bfloat162(a2, a3);
    lp[0] = __nv_bfloat162(b0, b1); lp[1] = __nv_bfloat162(b2, b3);
}

__global__ void convert2_kernel(const float* __restrict__ w0, const float* __restrict__ w1,
                                bf* __restrict__ h0, bf* __restrict__ l0,
                                bf* __restrict__ h1, bf* __restrict__ l1) {
    int i = blockIdx.x * blockDim.x + threadIdx.x;
    int seg = i >> 20;
    int off = i & 0xFFFFF;
    const float* w = seg == 0 ? w0 : w1;
    bf* h = seg == 0 ? h0 : h1;
    bf* l = seg == 0 ? l0 : l1;
    float4 v = ((const float4*)w)[off];
    bf a0, b0, a1, b1, a2, b2, a3, b3;
    split_bf16(v.x, a0, b0); split_bf16(v.y, a1, b1);
    split_bf16(v.z, a2, b2); split_bf16(v.w, a3, b3);
    __nv_bfloat162* hp = (__nv_bfloat162*)(h + (size_t)off * 4);
    __nv_bfloat162* lp = (__nv_bfloat162*)(l + (size_t)off * 4);
    hp[0] = __nv_bfloat162(a0, a1); hp[1] = __nv_bfloat162(a2, a3);
    lp[0] = __nv_bfloat162(b0, b1); lp[1] = __nv_bfloat162(b2, b3);
}

// ---------------------------------------------------------------------------
// HMMA GEMM core (bf16x3 split). B fragments front-loaded via paired ldmx4,
// A transient per (mt,k16). Per-accumulator term order identical to R6.
// ---------------------------------------------------------------------------
#define PITCHB 80
#define MAT_BYTES (128 * PITCHB)
#define STAGE_BYTES (4 * MAT_BYTES)
#define GEMM_SMEM (2 * STAGE_BYTES)

template <int EPI>
__device__ __forceinline__ void gemm_core(
    const bf* __restrict__ Ah, const bf* __restrict__ Al,
    const bf* __restrict__ Bh, const bf* __restrict__ Bl,
    const float* __restrict__ bias, const float* __restrict__ res,
    float* __restrict__ C, bf* __restrict__ Ho, bf* __restrict__ Lo,
    int N, int K, float alpha, size_t m0, size_t n0, char* smc) {
    const int tid = threadIdx.x, lane = tid & 31, wid = tid >> 5;
    const int wm = wid & 1, wn = wid >> 1;
    const uint32_t sbase = smem_u32(smc);

    const bf* gsrc0 = Ah + m0 * K;
    const bf* gsrc1 = Al + m0 * K;
    const bf* gsrc2 = Bh + n0 * K;
    const bf* gsrc3 = Bl + n0 * K;

    auto load_stage = [&](int s, int kt) {
        uint32_t base = sbase + s * STAGE_BYTES;
#pragma unroll
        for (int i = 0; i < 8; i++) {
            const int t = i >> 1;
            int idx = tid + (i & 1) * 256;
            int row = idx >> 2, seg = idx & 3;
            const bf* src = (t == 0 ? gsrc0 : t == 1 ? gsrc1 : t == 2 ? gsrc2 : gsrc3);
            cp16(base + t * MAT_BYTES + row * PITCHB + seg * 16,
                 src + (size_t)row * K + kt + seg * 8);
        }
    };

    float acc[4][4][4];
#pragma unroll
    for (int a = 0; a < 4; a++)
#pragma unroll
        for (int b = 0; b < 4; b++)
#pragma unroll
            for (int c = 0; c < 4; c++) acc[a][b][c] = 0.f;

    const int nk = K >> 5;
    load_stage(0, 0);
    CP_COMMIT();

    // lane-dependent fragment addressing (hoisted)
    const uint32_t brow = (uint32_t)(wn * 32 + ((lane >> 4) & 1) * 8 + (lane & 7));
    const uint32_t bcolh = (uint32_t)(((lane >> 3) & 1) * 8) * 2;
    const uint32_t arow = (uint32_t)(wm * 64 + (lane & 15));
    const uint32_t acolh = (uint32_t)((lane >> 4) << 3) * 2;

    for (int cc = 0; cc < nk; cc++) {
        CP_WAIT0();
        __syncthreads();
        if (cc + 1 < nk) { load_stage((cc + 1) & 1, (cc + 1) << 5); CP_COMMIT(); }

        uint32_t st = sbase + (cc & 1) * STAGE_BYTES;
        uint32_t sAh = st, sAl = st + MAT_BYTES;
        uint32_t sBh = st + 2 * MAT_BYTES, sBl = st + 3 * MAT_BYTES;

        // ---- front-load ALL B fragments for both k16 steps ----
        // Bx_[k16][nt*2+half]; ldmx4 covers nt pair x k-halves
        uint32_t Bh_[2][8], Bl_[2][8];
#pragma unroll
        for (int k16 = 0; k16 < 2; k16++) {
            uint32_t bcol = (uint32_t)(k16 * 16) * 2 + bcolh;
#pragma unroll
            for (int pr = 0; pr < 2; pr++) {
                uint32_t bo = (brow + pr * 16) * PITCHB + bcol;
                ldmx4(Bh_[k16][pr * 4 + 0], Bh_[k16][pr * 4 + 1],
                      Bh_[k16][pr * 4 + 2], Bh_[k16][pr * 4 + 3], sBh + bo);
                ldmx4(Bl_[k16][pr * 4 + 0], Bl_[k16][pr * 4 + 1],
                      Bl_[k16][pr * 4 + 2], Bl_[k16][pr * 4 + 3], sBl + bo);
            }
        }

        // ---- per mt: transient A, 24 MMAs ----
#pragma unroll
        for (int mt = 0; mt < 4; mt++) {
            uint32_t aro = (arow + mt * 16) * PITCHB;
#pragma unroll
            for (int k16 = 0; k16 < 2; k16++) {
                uint32_t ao = aro + (uint32_t)(k16 * 16) * 2 + acolh;
                uint32_t ah[4], al[4];
                ldmx4(ah[0], ah[1], ah[2], ah[3], sAh + ao);
                ldmx4(al[0], al[1], al[2], al[3], sAl + ao);
#pragma unroll
                for (int nt = 0; nt < 4; nt++)
                    mma16816(acc[mt][nt], ah, Bh_[k16][nt * 2], Bh_[k16][nt * 2 + 1]);
#pragma unroll
                for (int nt = 0; nt < 4; nt++)
                    mma16816(acc[mt][nt], ah, Bl_[k16][nt * 2], Bl_[k16][nt * 2 + 1]);
#pragma unroll
                for (int nt = 0; nt < 4; nt++)
                    mma16816(acc[mt][nt], al, Bh_[k16][nt * 2], Bh_[k16][nt * 2 + 1]);
            }
        }
    }

#pragma unroll
    for (int mt = 0; mt < 4; mt++) {
        int r0 = wm * 64 + mt * 16 + (lane >> 2);
#pragma unroll
        for (int nt = 0; nt < 4; nt++) {
            size_t gcol = n0 + wn * 32 + nt * 8 + (lane & 3) * 2;
            float2 bb = *(const float2*)(bias + gcol);
#pragma unroll
            for (int h = 0; h < 2; h++) {
                size_t grow = m0 + r0 + h * 8;
                size_t idx = grow * (size_t)N + gcol;
                float v0 = acc[mt][nt][h * 2 + 0] + bb.x;
                float v1 = acc[mt][nt][h * 2 + 1] + bb.y;
                if (EPI == 1) {
                    float2 rr = *(const float2*)(res + idx);
                    v0 += rr.x; v1 += rr.y;
                }
                if (EPI == 3) {
                    float2 rr = *(const float2*)(C + idx);
                    v0 += rr.x; v1 += rr.y;
                }
                if (EPI == 2 || EPI == 4) {
                    if (EPI == 2) { v0 = gelu_exact(v0); v1 = gelu_exact(v1); }
                    else          { v0 *= alpha; v1 *= alpha; }
                    bf h0, l0, h1, l1;
                    split_bf16(v0, h0, l0); split_bf16(v1, h1, l1);
                    *(__nv_bfloat162*)(Ho + idx) = __nv_bfloat162(h0, h1);
                    *(__nv_bfloat162*)(Lo + idx) = __nv_bfloat162(l0, l1);
                } else {
                    float2 o; o.x = v0; o.y = v1;
                    *(float2*)(C + idx) = o;
                }
            }
        }
    }
}

template <int EPI>
__global__ void __launch_bounds__(256, 2)
gemm_mma(const bf* __restrict__ Ah, const bf* __restrict__ Al,
         const bf* __restrict__ Bh, const bf* __restrict__ Bl,
         const float* __restrict__ bias, const float* __restrict__ res,
         float* __restrict__ C, bf* __restrict__ Ho, bf* __restrict__ Lo,
         int N, int K, float alpha) {
    extern __shared__ char smc[];
    gemm_core<EPI>(Ah, Al, Bh, Bl, bias, res, C, Ho, Lo, N, K, alpha,
                   (size_t)blockIdx.y * 128, (size_t)blockIdx.x * 128, smc);
}

// Fused K/V projection: blockIdx.x 0-7 -> K, 8-15 -> V
__global__ void __launch_bounds__(256, 2)
gemm_kv(const bf* __restrict__ Xh, const bf* __restrict__ Xl,
        const bf* __restrict__ WKh, const bf* __restrict__ WKl,
        const bf* __restrict__ WVh, const bf* __restrict__ WVl,
        const float* __restrict__ bk, const float* __restrict__ bv,
        bf* __restrict__ KH, bf* __restrict__ KL,
        bf* __restrict__ VH, bf* __restrict__ VL) {
    extern __shared__ char smc[];
    bool isV = blockIdx.x >= 8;
    gemm_core<4>(Xh, Xl, isV ? WVh : WKh, isV ? WVl : WKl,
                 isV ? bv : bk, nullptr, nullptr,
                 isV ? VH : KH, isV ? VL : KL, DQ, DQ, 1.0f,
                 (size_t)blockIdx.y * 128, (size_t)(blockIdx.x & 7) * 128, smc);
}

// ---------------------------------------------------------------------------
// Tensor-core flash attention, softmax-1, pair-interleaved MMAs (unchanged).
// ---------------------------------------------------------------------------
#define APB 144
#define KV_MAT (64 * APB)
#define KV_STAGE (4 * KV_MAT)
#define ATTN_SMEM (2 * KV_STAGE)

__global__ void __launch_bounds__(256, 1)
attn_mma(const bf* __restrict__ QHp, const bf* __restrict__ QLp,
         const bf* __restrict__ KHp, const bf* __restrict__ KLp,
         const bf* __restrict__ VHp, const bf* __restrict__ VLp,
         bf* __restrict__ OHp, bf* __restrict__ OLp) {
    extern __shared__ char smc[];
    const uint32_t sb = smem_u32(smc);
    const int tid = threadIdx.x, lane = tid & 31, wid = tid >> 5;
    const int b = blockIdx.z, h = blockIdx.y;
    const int n0 = blockIdx.x * 128;
    const size_t qrow0 = (size_t)b * NN + n0;
    const size_t col0 = (size_t)h * HD;

    {
        const bf* s0 = QHp + qrow0 * DQ + col0;
        const bf* s1 = QLp + qrow0 * DQ + col0;
#pragma unroll
        for (int it = 0; it < 8; it++) {
            int g = it * 256 + tid;
            int m = g >> 10;
            int r = (g & 1023) >> 3, c = g & 7;
            const bf* src = m == 0 ? s0 : s1;
            cp16(sb + m * (128 * APB) + r * APB + c * 16, src + (size_t)r * DQ + c * 8);
        }
    }
    CP_COMMIT();
    CP_WAIT0();
    __syncthreads();

    uint32_t qh[4][4], ql[4][4];
#pragma unroll
    for (int k16 = 0; k16 < 4; k16++) {
        uint32_t ao = (uint32_t)(wid * 16 + (lane & 15)) * APB
                    + (uint32_t)(k16 * 16 + (lane >> 4) * 8) * 2;
        ldmx4(qh[k16][0], qh[k16][1], qh[k16][2], qh[k16][3], sb + ao);
        ldmx4(ql[k16][0], ql[k16][1], ql[k16][2], ql[k16][3], sb + 128 * APB + ao);
    }
    __syncthreads();

    const bf* kvsrc[4] = {
        KHp + ((size_t)b * LL) * DQ + col0,
        KLp + ((size_t)b * LL) * DQ + col0,
        VHp + ((size_t)b * LL) * DQ + col0,
        VLp + ((size_t)b * LL) * DQ + col0
    };
    auto load_kv = [&](int blk, int s) {
        uint32_t base = sb + s * KV_STAGE;
        size_t roff = (size_t)blk * 64;
#pragma unroll
        for (int it = 0; it < 8; it++) {
            int g = it * 256 + tid;
            int m = g >> 9;
            int r = (g & 511) >> 3, c = g & 7;
            cp16(base + m * KV_MAT + r * APB + c * 16,
                 kvsrc[m] + (roff + r) * DQ + c * 8);
        }
    };

    float m_[2] = {0.f, 0.f}, l_[2] = {1.f, 1.f};
    float o_[8][4];
#pragma unroll
    for (int d = 0; d < 8; d++)
#pragma unroll
        for (int j = 0; j < 4; j++) o_[d][j] = 0.f;

    load_kv(0, 0);
    CP_COMMIT();

    const int NBLK = LL / 64;
    for (int i = 0; i < NBLK; i++) {
        if (i + 1 < NBLK) { load_kv(i + 1, (i + 1) & 1); CP_COMMIT(); CP_WAIT1(); }
        else CP_WAIT0();
        __syncthreads();

        uint32_t stg = sb + (i & 1) * KV_STAGE;

        float s_[8][4];
#pragma unroll
        for (int nt = 0; nt < 8; nt++)
#pragma unroll
            for (int j = 0; j < 4; j++) s_[nt][j] = 0.f;

#pragma unroll
        for (int k16 = 0; k16 < 4; k16++) {
            uint32_t bcol = (uint32_t)(k16 * 16 + ((lane >> 3) & 1) * 8) * 2;
            uint32_t brow = (uint32_t)(lane & 7);
#pragma unroll
            for (int ntp = 0; ntp < 4; ntp++) {
                int nt0 = 2 * ntp, nt1 = nt0 + 1;
                uint32_t boA = (brow + nt0 * 8) * APB + bcol;
                uint32_t boB = (brow + nt1 * 8) * APB + bcol;
                uint32_t kha0, kha1, kla0, kla1, khb0, khb1, klb0, klb1;
                ldmx2(kha0, kha1, stg + boA);
                ldmx2(khb0, khb1, stg + boB);
                ldmx2(kla0, kla1, stg + KV_MAT + boA);
                ldmx2(klb0, klb1, stg + KV_MAT + boB);
                mma16816(s_[nt0], qh[k16], kha0, kha1);
                mma16816(s_[nt1], qh[k16], khb0, khb1);
                mma16816(s_[nt0], qh[k16], kla0, kla1);
                mma16816(s_[nt1], qh[k16], klb0, klb1);
                mma16816(s_[nt0], ql[k16], kha0, kha1);
                mma16816(s_[nt1], ql[k16], khb0, khb1);
            }
        }

#pragma unroll
        for (int hh = 0; hh < 2; hh++) {
            float mx = s_[0][hh * 2];
#pragma unroll
            for (int nt = 0; nt < 8; nt++)
                mx = fmaxf(mx, fmaxf(s_[nt][hh * 2], s_[nt][hh * 2 + 1]));
            mx = fmaxf(mx, __shfl_xor_sync(0xffffffffu, mx, 1));
            mx = fmaxf(mx, __shfl_xor_sync(0xffffffffu, mx, 2));
            float mn = fmaxf(m_[hh], mx);
            float corr = __expf(m_[hh] - mn);
            m_[hh] = mn;
            float sum = 0.f;
#pragma unroll
            for (int nt = 0; nt < 8; nt++) {
                float p0 = __expf(s_[nt][hh * 2] - mn);
                float p1 = __expf(s_[nt][hh * 2 + 1] - mn);
                s_[nt][hh * 2] = p0; s_[nt][hh * 2 + 1] = p1;
                sum += p0 + p1;
            }
            sum += __shfl_xor_sync(0xffffffffu, sum, 1);
            sum += __shfl_xor_sync(0xffffffffu, sum, 2);
            l_[hh] = l_[hh] * corr + sum;
#pragma unroll
            for (int d = 0; d < 8; d++) {
                o_[d][hh * 2] *= corr; o_[d][hh * 2 + 1] *= corr;
            }
        }

        uint32_t ph[4][4], pl[4][4];
#pragma unroll
        for (int j = 0; j < 4; j++) {
            split2pack(s_[2 * j][0], s_[2 * j][1], ph[j][0], pl[j][0]);
            split2pack(s_[2 * j][2], s_[2 * j][3], ph[j][1], pl[j][1]);
            split2pack(s_[2 * j + 1][0], s_[2 * j + 1][1], ph[j][2], pl[j][2]);
            split2pack(s_[2 * j + 1][2], s_[2 * j + 1][3], ph[j][3], pl[j][3]);
        }

        uint32_t vbase = stg + 2 * KV_MAT;
#pragma unroll
        for (int j = 0; j < 4; j++) {
            uint32_t vrow = (uint32_t)(j * 16 + (lane & 15)) * APB;
#pragma unroll
            for (int dtp = 0; dtp < 4; dtp++) {
                int dt0 = 2 * dtp, dt1 = dt0 + 1;
                uint32_t voA = vrow + dt0 * 16;
                uint32_t voB = vrow + dt1 * 16;
                uint32_t vha0, vha1, vla0, vla1, vhb0, vhb1, vlb0, vlb1;
                ldmx2t(vha0, vha1, vbase + voA);
                ldmx2t(vhb0, vhb1, vbase + voB);
                ldmx2t(vla0, vla1, vbase + KV_MAT + voA);
                ldmx2t(vlb0, vlb1, vbase + KV_MAT + voB);
                mma16816(o_[dt0], ph[j], vha0, vha1);
                mma16816(o_[dt1], ph[j], vhb0, vhb1);
                mma16816(o_[dt0], ph[j], vla0, vla1);
                mma16816(o_[dt1], ph[j], vlb0, vlb1);
                mma16816(o_[dt0], pl[j], vha0, vha1);
                mma16816(o_[dt1], pl[j], vhb0, vhb1);
            }
        }
        __syncthreads();
    }

    float inv0 = 1.f / l_[0], inv1 = 1.f / l_[1];
#pragma unroll
    for (int hh = 0; hh < 2; hh++) {
        float inv = hh == 0 ? inv0 : inv1;
        size_t grow = qrow0 + wid * 16 + (lane >> 2) + hh * 8;
#pragma unroll
        for (int dt = 0; dt < 8; dt++) {
            size_t idx = grow * DQ + col0 + dt * 8 + (lane & 3) * 2;
            float f0 = o_[dt][hh * 2] * inv;
            float f1 = o_[dt][hh * 2 + 1] * inv;
            bf h0, l0, h1, l1;
            split_bf16(f0, h0, l0); split_bf16(f1, h1, l1);
            *(__nv_bfloat162*)(OHp + idx) = __nv_bfloat162(h0, h1);
            *(__nv_bfloat162*)(OLp + idx) = __nv_bfloat162(l0, l1);
        }
    }
}

// ---------------------------------------------------------------------------
// kernel_launch
// ---------------------------------------------------------------------------
extern "C" void kernel_launch(void* const* d_in, const int* in_sizes, int n_in,
                              void* d_out, int out_size) {
    const float* x_q   = (const float*)d_in[0];
    const float* x_kv  = (const float*)d_in[1];
    const float* qn_g  = (const float*)d_in[2];
    const float* qn_b  = (const float*)d_in[3];
    const float* kvn_g = (const float*)d_in[4];
    const float* kvn_b = (const float*)d_in[5];
    const float* Wq    = (const float*)d_in[6];
    const float* bq    = (const float*)d_in[7];
    const float* Wk    = (const float*)d_in[8];
    const float* bk    = (const float*)d_in[9];
    const float* Wv    = (const float*)d_in[10];
    const float* bv    = (const float*)d_in[11];
    const float* Wo    = (const float*)d_in[12];
    const float* bo    = (const float*)d_in[13];
    const float* n2_g  = (const float*)d_in[14];
    const float* n2_b  = (const float*)d_in[15];
    const float* W1    = (const float*)d_in[16];
    const float* b1    = (const float*)d_in[17];
    const float* W2    = (const float*)d_in[18];
    const float* b2    = (const float*)d_in[19];
    float* out = (float*)d_out;

    bf* bfb = nullptr;
    cudaGetSymbolAddress((void**)&bfb, g_bf);

    bf* XQH = bfb + (size_t)O_XQH * EM;   bf* XQL = bfb + (size_t)O_XQL * EM;
    bf* XKVH = bfb + (size_t)O_XKVH * EM; bf* XKVL = bfb + (size_t)O_XKVL * EM;
    bf* ATTH = bfb + (size_t)O_ATTH * EM; bf* ATTL = bfb + (size_t)O_ATTL * EM;
    bf* X2H = bfb + (size_t)O_X2H * EM;   bf* X2L = bfb + (size_t)O_X2L * EM;
    bf* Hh  = bfb + (size_t)O_HH * EM;    bf* Hl  = bfb + (size_t)O_HL * EM;
    bf* WQH = bfb + (size_t)O_WQH * EM;   bf* WQL = bfb + (size_t)O_WQL * EM;
    bf* WKH = bfb + (size_t)O_WKH * EM;   bf* WKL = bfb + (size_t)O_WKL * EM;
    bf* WVH = bfb + (size_t)O_WVH * EM;   bf* WVL = bfb + (size_t)O_WVL * EM;
    bf* WOH = bfb + (size_t)O_WOH * EM;   bf* WOL = bfb + (size_t)O_WOL * EM;
    bf* W1H = bfb + (size_t)O_W1H * EM;   bf* W1L = bfb + (size_t)O_W1L * EM;
    bf* W2H = bfb + (size_t)O_W2H * EM;   bf* W2L = bfb + (size_t)O_W2L * EM;
    bf* QH  = bfb + (size_t)O_QH * EM;    bf* QL  = bfb + (size_t)O_QL * EM;
    bf* KH  = bfb + (size_t)O_KH * EM;    bf* KL  = bfb + (size_t)O_KL * EM;
    bf* VH  = bfb + (size_t)O_VH * EM;    bf* VL  = bfb + (size_t)O_VL * EM;

    cudaFuncSetAttribute(gemm_mma<1>, cudaFuncAttributeMaxDynamicSharedMemorySize, GEMM_SMEM);
    cudaFuncSetAttribute(gemm_mma<2>, cudaFuncAttributeMaxDynamicSharedMemorySize, GEMM_SMEM);
    cudaFuncSetAttribute(gemm_mma<3>, cudaFuncAttributeMaxDynamicSharedMemorySize, GEMM_SMEM);
    cudaFuncSetAttribute(gemm_mma<4>, cudaFuncAttributeMaxDynamicSharedMemorySize, GEMM_SMEM);
    cudaFuncSetAttribute(gemm_kv, cudaFuncAttributeMaxDynamicSharedMemorySize, GEMM_SMEM);
    cudaFuncSetAttribute(attn_mma, cudaFuncAttributeMaxDynamicSharedMemorySize, ATTN_SMEM);

    // 1-2: weight splits
    convert4_kernel<<<4096, 256>>>(Wq, Wk, Wv, Wo,
                                   WQH, WQL, WKH, WKL, WVH, WVL, WOH, WOL);
    convert2_kernel<<<8192, 256>>>(W1, W2, W1H, W1L, W2H, W2L);

    // 3: both input LNs fused
    ln2x_bf16_kernel<<<2 * MROWS, 256>>>(x_q, qn_g, qn_b, XQH, XQL,
                                         x_kv, kvn_g, kvn_b, XKVH, XKVL);

    // 4: Q projection (scale folded in)
    gemm_mma<4><<<dim3(DQ / 128, MROWS / 128), 256, GEMM_SMEM>>>(
        XQH, XQL, WQH, WQL, bq, nullptr, nullptr, QH, QL, DQ, DQ, 0.125f);

    // 5: fused K+V projection
    gemm_kv<<<dim3(16, MROWS / 128), 256, GEMM_SMEM>>>(
        XKVH, XKVL, WKH, WKL, WVH, WVL, bk, bv, KH, KL, VH, VL);

    // 6: tensor-core attention (profiled launch)
    attn_mma<<<dim3(NN / 128, HH, BB), 256, ATTN_SMEM>>>(
        QH, QL, KH, KL, VH, VL, ATTH, ATTL);

    // 7: out projection + residual with x_q
    gemm_mma<1><<<dim3(DQ / 128, MROWS / 128), 256, GEMM_SMEM>>>(
        ATTH, ATTL, WOH, WOL, bo, x_q, out, nullptr, nullptr, DQ, DQ, 1.0f);

    // 8: LN2
    ln_bf16_kernel<<<MROWS, 256>>>(out, n2_g, n2_b, X2H, X2L);

    // 9: MLP up + GELU -> bf16 split
    gemm_mma<2><<<dim3(DFF / 128, MROWS / 128), 256, GEMM_SMEM>>>(
        X2H, X2L, W1H, W1L, b1, nullptr, nullptr, Hh, Hl, DFF, DQ, 1.0f);

    // 10: MLP down + residual accumulate into d_out
    gemm_mma<3><<<dim3(DQ / 128, MROWS / 128), 256, GEMM_SMEM>>>(
        Hh, Hl, W2H, W2L, b2, nullptr, out, nullptr, nullptr, DQ, DFF, 1.0f);
}

// round 10
// speedup vs baseline: 3.0110x; 1.1065x over previous
#include <cuda_runtime.h>
#include <cuda_bf16.h>
#include <math.h>
#include <stdint.h>

#define BB   2
#define NN   2048
#define LL   2048
#define DQ   1024
#define HH   16
#define HD   64
#define MROWS 4096
#define DFF  4096

typedef __nv_bfloat16 bf;

// ---------------------------------------------------------------------------
// Static scratch
// ---------------------------------------------------------------------------
#define EM (1024u*1024u)
__device__ __align__(256) bf g_bf[112u * EM];

#define O_XQH 0
#define O_XQL 4
#define O_XKVH 8
#define O_XKVL 12
#define O_ATTH 16
#define O_ATTL 20
#define O_X2H 24
#define O_X2L 28
#define O_HH  32
#define O_HL  48
#define O_WQH 64
#define O_WQL 65
#define O_WKH 66
#define O_WKL 67
#define O_WVH 68
#define O_WVL 69
#define O_WOH 70
#define O_WOL 71
#define O_W1H 72
#define O_W1L 76
#define O_W2H 80
#define O_W2L 84
#define O_QH  88
#define O_QL  92
#define O_KH  96
#define O_KL  100
#define O_VH  104
#define O_VL  108

// ---------------------------------------------------------------------------
// helpers
// ---------------------------------------------------------------------------
__device__ __forceinline__ uint32_t smem_u32(const void* p) {
    uint32_t a;
    asm("{ .reg .u64 t; cvta.to.shared.u64 t, %1; cvt.u32.u64 %0, t; }" : "=r"(a) : "l"(p));
    return a;
}
__device__ __forceinline__ void ldmx4(uint32_t& r0, uint32_t& r1, uint32_t& r2,
                                      uint32_t& r3, uint32_t a) {
    asm volatile("ldmatrix.sync.aligned.m8n8.x4.shared.b16 {%0,%1,%2,%3}, [%4];"
                 : "=r"(r0), "=r"(r1), "=r"(r2), "=r"(r3) : "r"(a));
}
__device__ __forceinline__ void ldmx2(uint32_t& r0, uint32_t& r1, uint32_t a) {
    asm volatile("ldmatrix.sync.aligned.m8n8.x2.shared.b16 {%0,%1}, [%2];"
                 : "=r"(r0), "=r"(r1) : "r"(a));
}
__device__ __forceinline__ void ldmx2t(uint32_t& r0, uint32_t& r1, uint32_t a) {
    asm volatile("ldmatrix.sync.aligned.m8n8.x2.trans.shared.b16 {%0,%1}, [%2];"
                 : "=r"(r0), "=r"(r1) : "r"(a));
}
__device__ __forceinline__ void mma16816(float* d, const uint32_t* a,
                                         uint32_t b0, uint32_t b1) {
    asm volatile(
        "mma.sync.aligned.m16n8k16.row.col.f32.bf16.bf16.f32 "
        "{%0,%1,%2,%3}, {%4,%5,%6,%7}, {%8,%9}, {%0,%1,%2,%3};"
        : "+f"(d[0]), "+f"(d[1]), "+f"(d[2]), "+f"(d[3])
        : "r"(a[0]), "r"(a[1]), "r"(a[2]), "r"(a[3]), "r"(b0), "r"(b1));
}
__device__ __forceinline__ void cp16(uint32_t dst, const void* src) {
    asm volatile("cp.async.cg.shared.global [%0], [%1], 16;" :: "r"(dst), "l"(src));
}
#define CP_COMMIT() asm volatile("cp.async.commit_group;" ::: "memory")
#define CP_WAIT0()  asm volatile("cp.async.wait_group 0;" ::: "memory")
#define CP_WAIT1()  asm volatile("cp.async.wait_group 1;" ::: "memory")

__device__ __forceinline__ float gelu_exact(float x) {
    return 0.5f * x * (1.f + erff(x * 0.7071067811865476f));
}
__device__ __forceinline__ void split_bf16(float x, bf& h, bf& l) {
    h = __float2bfloat16(x);
    l = __float2bfloat16(x - __bfloat162float(h));
}
__device__ __forceinline__ void split2pack(float a, float b, uint32_t& hi, uint32_t& lo) {
    bf ha = __float2bfloat16(a), hb = __float2bfloat16(b);
    float ra = a - __bfloat162float(ha), rb = b - __bfloat162float(hb);
    __nv_bfloat162 H(ha, hb);
    __nv_bfloat162 L(__float2bfloat16(ra), __float2bfloat16(rb));
    hi = *(uint32_t*)&H;
    lo = *(uint32_t*)&L;
}

// GEMM smem swizzle: pitch 64B (32 bf16), 16B chunk XORed with (row>>1)&3.
// 16B-aligned; conflict-free for ldmatrix 8-row phases and cp.async stores.
__device__ __forceinline__ uint32_t swz(uint32_t row, uint32_t colbyte) {
    return row * 64 + ((((colbyte >> 4) ^ (row >> 1)) & 3u) << 4);
}

// ---------------------------------------------------------------------------
// Fused LayerNorm (two tensors) -> bf16 hi/lo split
// ---------------------------------------------------------------------------
__global__ void ln2x_bf16_kernel(const float* __restrict__ xA,
                                 const float* __restrict__ gA,
                                 const float* __restrict__ bA,
                                 bf* __restrict__ yhA, bf* __restrict__ ylA,
                                 const float* __restrict__ xB,
                                 const float* __restrict__ gB,
                                 const float* __restrict__ bB,
                                 bf* __restrict__ yhB, bf* __restrict__ ylB) {
    int row = blockIdx.x;
    const float* x; const float* g; const float* b; bf* yh; bf* yl;
    if (row < MROWS) { x = xA; g = gA; b = bA; yh = yhA; yl = ylA; }
    else { x = xB; g = gB; b = bB; yh = yhB; yl = ylB; row -= MROWS; }

    const float* xr = x + (size_t)row * DQ;
    float v[4];
    float s = 0.f, s2 = 0.f;
#pragma unroll
    for (int i = 0; i < 4; i++) {
        float t = xr[threadIdx.x + i * 256];
        v[i] = t; s += t; s2 += t * t;
    }
#pragma unroll
    for (int o = 16; o > 0; o >>= 1) {
        s  += __shfl_xor_sync(0xffffffffu, s,  o);
        s2 += __shfl_xor_sync(0xffffffffu, s2, o);
    }
    __shared__ float ws[8], ws2[8];
    int w = threadIdx.x >> 5, lane = threadIdx.x & 31;
    if (lane == 0) { ws[w] = s; ws2[w] = s2; }
    __syncthreads();
    if (w == 0) {
        s  = (lane < 8) ? ws[lane]  : 0.f;
        s2 = (lane < 8) ? ws2[lane] : 0.f;
#pragma unroll
        for (int o = 4; o > 0; o >>= 1) {
            s  += __shfl_xor_sync(0xffffffffu, s,  o);
            s2 += __shfl_xor_sync(0xffffffffu, s2, o);
        }
        if (lane == 0) { ws[0] = s; ws2[0] = s2; }
    }
    __syncthreads();
    float mean = ws[0] * (1.f / DQ);
    float var  = ws2[0] * (1.f / DQ) - mean * mean;
    float rstd = rsqrtf(var + 1e-5f);
    size_t base = (size_t)row * DQ;
#pragma unroll
    for (int i = 0; i < 4; i++) {
        int c = threadIdx.x + i * 256;
        float yv = (v[i] - mean) * rstd * g[c] + b[c];
        bf h, l; split_bf16(yv, h, l);
        yh[base + c] = h;
        yl[base + c] = l;
    }
}

// single-tensor LN (for LN2)
__global__ void ln_bf16_kernel(const float* __restrict__ x,
                               const float* __restrict__ g,
                               const float* __restrict__ b,
                               bf* __restrict__ yh, bf* __restrict__ yl) {
    int row = blockIdx.x;
    const float* xr = x + (size_t)row * DQ;
    float v[4];
    float s = 0.f, s2 = 0.f;
#pragma unroll
    for (int i = 0; i < 4; i++) {
        float t = xr[threadIdx.x + i * 256];
        v[i] = t; s += t; s2 += t * t;
    }
#pragma unroll
    for (int o = 16; o > 0; o >>= 1) {
        s  += __shfl_xor_sync(0xffffffffu, s,  o);
        s2 += __shfl_xor_sync(0xffffffffu, s2, o);
    }
    __shared__ float ws[8], ws2[8];
    int w = threadIdx.x >> 5, lane = threadIdx.x & 31;
    if (lane == 0) { ws[w] = s; ws2[w] = s2; }
    __syncthreads();
    if (w == 0) {
        s  = (lane < 8) ? ws[lane]  : 0.f;
        s2 = (lane < 8) ? ws2[lane] : 0.f;
#pragma unroll
        for (int o = 4; o > 0; o >>= 1) {
            s  += __shfl_xor_sync(0xffffffffu, s,  o);
            s2 += __shfl_xor_sync(0xffffffffu, s2, o);
        }
        if (lane == 0) { ws[0] = s; ws2[0] = s2; }
    }
    __syncthreads();
    float mean = ws[0] * (1.f / DQ);
    float var  = ws2[0] * (1.f / DQ) - mean * mean;
    float rstd = rsqrtf(var + 1e-5f);
    size_t base = (size_t)row * DQ;
#pragma unroll
    for (int i = 0; i < 4; i++) {
        int c = threadIdx.x + i * 256;
        float yv = (v[i] - mean) * rstd * g[c] + b[c];
        bf h, l; split_bf16(yv, h, l);
        yh[base + c] = h;
        yl[base + c] = l;
    }
}

// ---------------------------------------------------------------------------
// Single fused weight convert: all 6 weight tensors in one launch.
// float4 entries: QKVO = 4x256K = 1M, W1 = 1M, W2 = 1M  -> 3M total.
// ---------------------------------------------------------------------------
__global__ void convert_all_kernel(
    const float* __restrict__ wq, const float* __restrict__ wk,
    const float* __restrict__ wv, const float* __restrict__ wo,
    const float* __restrict__ w1, const float* __restrict__ w2,
    bf* __restrict__ base) {
    int i = blockIdx.x * blockDim.x + threadIdx.x;   // 0 .. 3M-1
    const float* w; bf* h; bf* l; int off;
    if (i < (1 << 20)) {             // QKVO region: 4 x 256K float4
        int seg = i >> 18;
        off = i & 0x3FFFF;
        w = seg == 0 ? wq : seg == 1 ? wk : seg == 2 ? wv : wo;
        h = base + (size_t)(O_WQH + 2 * seg) * EM;
        l = base + (size_t)(O_WQL + 2 * seg) * EM;
    } else {
        int j = i - (1 << 20);
        int seg = j >> 20;           // 0 -> W1, 1 -> W2
        off = j & 0xFFFFF;
        w = seg == 0 ? w1 : w2;
        h = base + (size_t)(seg == 0 ? O_W1H : O_W2H) * EM;
        l = base + (size_t)(seg == 0 ? O_W1L : O_W2L) * EM;
    }
    float4 v = ((const float4*)w)[off];
    bf a0, b0, a1, b1, a2, b2, a3, b3;
    split_bf16(v.x, a0, b0); split_bf16(v.y, a1, b1);
    split_bf16(v.z, a2, b2); split_bf16(v.w, a3, b3);
    __nv_bfloat162* hp = (__nv_bfloat162*)(h + (size_t)off * 4);
    __nv_bfloat162* lp = (__nv_bfloat162*)(l + (size_t)off * 4);
    hp[0] = __nv_bfloat162(a0, a1); hp[1] = __nv_bfloat162(a2, a3);
    lp[0] = __nv_bfloat162(b0, b1); lp[1] = __nv_bfloat162(b2, b3);
}

// ---------------------------------------------------------------------------
// HMMA GEMM core (bf16x3 split), 3-stage cp.async pipeline, pitch-64 XOR swizzle.
// ---------------------------------------------------------------------------
#define MAT_BYTES (128 * 64)          // 8192
#define STAGE_BYTES (4 * MAT_BYTES)   // 32768
#define GEMM_SMEM (3 * STAGE_BYTES)   // 98304

template <int EPI>
__device__ __forceinline__ void gemm_core(
    const bf* __restrict__ Ah, const bf* __restrict__ Al,
    const bf* __restrict__ Bh, const bf* __restrict__ Bl,
    const float* __restrict__ bias, const float* __restrict__ res,
    float* __restrict__ C, bf* __restrict__ Ho, bf* __restrict__ Lo,
    int N, int K, float alpha, size_t m0, size_t n0, char* smc) {
    const int tid = threadIdx.x, lane = tid & 31, wid = tid >> 5;
    const int wm = wid & 1, wn = wid >> 1;
    const uint32_t sbase = smem_u32(smc);

    const bf* gsrc0 = Ah + m0 * K;
    const bf* gsrc1 = Al + m0 * K;
    const bf* gsrc2 = Bh + n0 * K;
    const bf* gsrc3 = Bl + n0 * K;

    auto load_stage = [&](int s, int kt) {
        uint32_t base = sbase + s * STAGE_BYTES;
#pragma unroll
        for (int i = 0; i < 8; i++) {
            const int t = i >> 1;
            int idx = tid + (i & 1) * 256;
            int row = idx >> 2, seg = idx & 3;
            const bf* src = (t == 0 ? gsrc0 : t == 1 ? gsrc1 : t == 2 ? gsrc2 : gsrc3);
            cp16(base + t * MAT_BYTES + swz((uint32_t)row, (uint32_t)(seg * 16)),
                 src + (size_t)row * K + kt + seg * 8);
        }
    };

    float acc[4][4][4];
#pragma unroll
    for (int a = 0; a < 4; a++)
#pragma unroll
        for (int b = 0; b < 4; b++)
#pragma unroll
            for (int c = 0; c < 4; c++) acc[a][b][c] = 0.f;

    const int nk = K >> 5;
    load_stage(0, 0);
    CP_COMMIT();
    load_stage(1, 32);
    CP_COMMIT();

    const uint32_t brow = (uint32_t)(wn * 32 + ((lane >> 4) & 1) * 8 + (lane & 7));
    const uint32_t bcolh = (uint32_t)(((lane >> 3) & 1) * 16);
    const uint32_t arow = (uint32_t)(wm * 64 + (lane & 15));
    const uint32_t acolh = (uint32_t)((lane >> 4) * 16);

    int stage = 0;
    for (int cc = 0; cc < nk; cc++) {
        if (cc + 1 < nk) CP_WAIT1(); else CP_WAIT0();
        __syncthreads();
        if (cc + 2 < nk) {
            int ns = stage + 2; if (ns >= 3) ns -= 3;
            load_stage(ns, (cc + 2) << 5);
            CP_COMMIT();
        }

        uint32_t st = sbase + stage * STAGE_BYTES;
        uint32_t sAh = st, sAl = st + MAT_BYTES;
        uint32_t sBh = st + 2 * MAT_BYTES, sBl = st + 3 * MAT_BYTES;

        uint32_t Bh_[2][8], Bl_[2][8];
#pragma unroll
        for (int k16 = 0; k16 < 2; k16++) {
            uint32_t bcol = (uint32_t)(k16 * 32) + bcolh;
#pragma unroll
            for (int pr = 0; pr < 2; pr++) {
                uint32_t bo = swz(brow + pr * 16, bcol);
                ldmx4(Bh_[k16][pr * 4 + 0], Bh_[k16][pr * 4 + 1],
                      Bh_[k16][pr * 4 + 2], Bh_[k16][pr * 4 + 3], sBh + bo);
                ldmx4(Bl_[k16][pr * 4 + 0], Bl_[k16][pr * 4 + 1],
                      Bl_[k16][pr * 4 + 2], Bl_[k16][pr * 4 + 3], sBl + bo);
            }
        }

#pragma unroll
        for (int mt = 0; mt < 4; mt++) {
#pragma unroll
            for (int k16 = 0; k16 < 2; k16++) {
                uint32_t ao = swz(arow + mt * 16, (uint32_t)(k16 * 32) + acolh);
                uint32_t ah[4], al[4];
                ldmx4(ah[0], ah[1], ah[2], ah[3], sAh + ao);
                ldmx4(al[0], al[1], al[2], al[3], sAl + ao);
#pragma unroll
                for (int nt = 0; nt < 4; nt++)
                    mma16816(acc[mt][nt], ah, Bh_[k16][nt * 2], Bh_[k16][nt * 2 + 1]);
#pragma unroll
                for (int nt = 0; nt < 4; nt++)
                    mma16816(acc[mt][nt], ah, Bl_[k16][nt * 2], Bl_[k16][nt * 2 + 1]);
#pragma unroll
                for (int nt = 0; nt < 4; nt++)
                    mma16816(acc[mt][nt], al, Bh_[k16][nt * 2], Bh_[k16][nt * 2 + 1]);
            }
        }
        stage++; if (stage >= 3) stage -= 3;
    }

#pragma unroll
    for (int mt = 0; mt < 4; mt++) {
        int r0 = wm * 64 + mt * 16 + (lane >> 2);
#pragma unroll
        for (int nt = 0; nt < 4; nt++) {
            size_t gcol = n0 + wn * 32 + nt * 8 + (lane & 3) * 2;
            float2 bb = *(const float2*)(bias + gcol);
#pragma unroll
            for (int h = 0; h < 2; h++) {
                size_t grow = m0 + r0 + h * 8;
                size_t idx = grow * (size_t)N + gcol;
                float v0 = acc[mt][nt][h * 2 + 0] + bb.x;
                float v1 = acc[mt][nt][h * 2 + 1] + bb.y;
                if (EPI == 1) {
                    float2 rr = *(const float2*)(res + idx);
                    v0 += rr.x; v1 += rr.y;
                }
                if (EPI == 3) {
                    float2 rr = *(const float2*)(C + idx);
                    v0 += rr.x; v1 += rr.y;
                }
                if (EPI == 2 || EPI == 4) {
                    if (EPI == 2) { v0 = gelu_exact(v0); v1 = gelu_exact(v1); }
                    else          { v0 *= alpha; v1 *= alpha; }
                    bf h0, l0, h1, l1;
                    split_bf16(v0, h0, l0); split_bf16(v1, h1, l1);
                    *(__nv_bfloat162*)(Ho + idx) = __nv_bfloat162(h0, h1);
                    *(__nv_bfloat162*)(Lo + idx) = __nv_bfloat162(l0, l1);
                } else {
                    float2 o; o.x = v0; o.y = v1;
                    *(float2*)(C + idx) = o;
                }
            }
        }
    }
}

template <int EPI>
__global__ void __launch_bounds__(256, 2)
gemm_mma(const bf* __restrict__ Ah, const bf* __restrict__ Al,
         const bf* __restrict__ Bh, const bf* __restrict__ Bl,
         const float* __restrict__ bias, const float* __restrict__ res,
         float* __restrict__ C, bf* __restrict__ Ho, bf* __restrict__ Lo,
         int N, int K, float alpha) {
    extern __shared__ char smc[];
    gemm_core<EPI>(Ah, Al, Bh, Bl, bias, res, C, Ho, Lo, N, K, alpha,
                   (size_t)blockIdx.y * 128, (size_t)blockIdx.x * 128, smc);
}

// Fused Q/K/V projection: blockIdx.x 0-7 -> Q, 8-15 -> K, 16-23 -> V
__global__ void __launch_bounds__(256, 2)
gemm_qkv(const bf* __restrict__ XQh, const bf* __restrict__ XQl,
         const bf* __restrict__ XKVh, const bf* __restrict__ XKVl,
         const bf* __restrict__ WQh, const bf* __restrict__ WQl,
         const bf* __restrict__ WKh, const bf* __restrict__ WKl,
         const bf* __restrict__ WVh, const bf* __restrict__ WVl,
         const float* __restrict__ bq, const float* __restrict__ bk,
         const float* __restrict__ bv,
         bf* __restrict__ QH, bf* __restrict__ QL,
         bf* __restrict__ KH, bf* __restrict__ KL,
         bf* __restrict__ VH, bf* __restrict__ VL) {
    extern __shared__ char smc[];
    size_t m0 = (size_t)blockIdx.y * 128;
    int xb = blockIdx.x;
    if (xb < 8) {
        gemm_core<4>(XQh, XQl, WQh, WQl, bq, nullptr, nullptr, QH, QL,
                     DQ, DQ, 0.125f, m0, (size_t)xb * 128, smc);
    } else if (xb < 16) {
        gemm_core<4>(XKVh, XKVl, WKh, WKl, bk, nullptr, nullptr, KH, KL,
                     DQ, DQ, 1.0f, m0, (size_t)(xb - 8) * 128, smc);
    } else {
        gemm_core<4>(XKVh, XKVl, WVh, WVl, bv, nullptr, nullptr, VH, VL,
                     DQ, DQ, 1.0f, m0, (size_t)(xb - 16) * 128, smc);
    }
}

// ---------------------------------------------------------------------------
// Tensor-core flash attention, softmax-1, pair-interleaved MMAs (unchanged).
// ---------------------------------------------------------------------------
#define APB 144
#define KV_MAT (64 * APB)
#define KV_STAGE (4 * KV_MAT)
#define ATTN_SMEM (2 * KV_STAGE)

__global__ void __launch_bounds__(256, 1)
attn_mma(const bf* __restrict__ QHp, const bf* __restrict__ QLp,
         const bf* __restrict__ KHp, const bf* __restrict__ KLp,
         const bf* __restrict__ VHp, const bf* __restrict__ VLp,
         bf* __restrict__ OHp, bf* __restrict__ OLp) {
    extern __shared__ char smc[];
    const uint32_t sb = smem_u32(smc);
    const int tid = threadIdx.x, lane = tid & 31, wid = tid >> 5;
    const int b = blockIdx.z, h = blockIdx.y;
    const int n0 = blockIdx.x * 128;
    const size_t qrow0 = (size_t)b * NN + n0;
    const size_t col0 = (size_t)h * HD;

    {
        const bf* s0 = QHp + qrow0 * DQ + col0;
        const bf* s1 = QLp + qrow0 * DQ + col0;
#pragma unroll
        for (int it = 0; it < 8; it++) {
            int g = it * 256 + tid;
            int m = g >> 10;
            int r = (g & 1023) >> 3, c = g & 7;
            const bf* src = m == 0 ? s0 : s1;
            cp16(sb + m * (128 * APB) + r * APB + c * 16, src + (size_t)r * DQ + c * 8);
        }
    }
    CP_COMMIT();
    CP_WAIT0();
    __syncthreads();

    uint32_t qh[4][4], ql[4][4];
#pragma unroll
    for (int k16 = 0; k16 < 4; k16++) {
        uint32_t ao = (uint32_t)(wid * 16 + (lane & 15)) * APB
                    + (uint32_t)(k16 * 16 + (lane >> 4) * 8) * 2;
        ldmx4(qh[k16][0], qh[k16][1], qh[k16][2], qh[k16][3], sb + ao);
        ldmx4(ql[k16][0], ql[k16][1], ql[k16][2], ql[k16][3], sb + 128 * APB + ao);
    }
    __syncthreads();

    const bf* kvsrc[4] = {
        KHp + ((size_t)b * LL) * DQ + col0,
        KLp + ((size_t)b * LL) * DQ + col0,
        VHp + ((size_t)b * LL) * DQ + col0,
        VLp + ((size_t)b * LL) * DQ + col0
    };
    auto load_kv = [&](int blk, int s) {
        uint32_t base = sb + s * KV_STAGE;
        size_t roff = (size_t)blk * 64;
#pragma unroll
        for (int it = 0; it < 8; it++) {
            int g = it * 256 + tid;
            int m = g >> 9;
            int r = (g & 511) >> 3, c = g & 7;
            cp16(base + m * KV_MAT + r * APB + c * 16,
                 kvsrc[m] + (roff + r) * DQ + c * 8);
        }
    };

    float m_[2] = {0.f, 0.f}, l_[2] = {1.f, 1.f};
    float o_[8][4];
#pragma unroll
    for (int d = 0; d < 8; d++)
#pragma unroll
        for (int j = 0; j < 4; j++) o_[d][j] = 0.f;

    load_kv(0, 0);
    CP_COMMIT();

    const int NBLK = LL / 64;
    for (int i = 0; i < NBLK; i++) {
        if (i + 1 < NBLK) { load_kv(i + 1, (i + 1) & 1); CP_COMMIT(); CP_WAIT1(); }
        else CP_WAIT0();
        __syncthreads();

        uint32_t stg = sb + (i & 1) * KV_STAGE;

        float s_[8][4];
#pragma unroll
        for (int nt = 0; nt < 8; nt++)
#pragma unroll
            for (int j = 0; j < 4; j++) s_[nt][j] = 0.f;

#pragma unroll
        for (int k16 = 0; k16 < 4; k16++) {
            uint32_t bcol = (uint32_t)(k16 * 16 + ((lane >> 3) & 1) * 8) * 2;
            uint32_t brow = (uint32_t)(lane & 7);
#pragma unroll
            for (int ntp = 0; ntp < 4; ntp++) {
                int nt0 = 2 * ntp, nt1 = nt0 + 1;
                uint32_t boA = (brow + nt0 * 8) * APB + bcol;
                uint32_t boB = (brow + nt1 * 8) * APB + bcol;
                uint32_t kha0, kha1, kla0, kla1, khb0, khb1, klb0, klb1;
                ldmx2(kha0, kha1, stg + boA);
                ldmx2(khb0, khb1, stg + boB);
                ldmx2(kla0, kla1, stg + KV_MAT + boA);
                ldmx2(klb0, klb1, stg + KV_MAT + boB);
                mma16816(s_[nt0], qh[k16], kha0, kha1);
                mma16816(s_[nt1], qh[k16], khb0, khb1);
                mma16816(s_[nt0], qh[k16], kla0, kla1);
                mma16816(s_[nt1], qh[k16], klb0, klb1);
                mma16816(s_[nt0], ql[k16], kha0, kha1);
                mma16816(s_[nt1], ql[k16], khb0, khb1);
            }
        }

#pragma unroll
        for (int hh = 0; hh < 2; hh++) {
            float mx = s_[0][hh * 2];
#pragma unroll
            for (int nt = 0; nt < 8; nt++)
                mx = fmaxf(mx, fmaxf(s_[nt][hh * 2], s_[nt][hh * 2 + 1]));
            mx = fmaxf(mx, __shfl_xor_sync(0xffffffffu, mx, 1));
            mx = fmaxf(mx, __shfl_xor_sync(0xffffffffu, mx, 2));
            float mn = fmaxf(m_[hh], mx);
            float corr = __expf(m_[hh] - mn);
            m_[hh] = mn;
            float sum = 0.f;
#pragma unroll
            for (int nt = 0; nt < 8; nt++) {
                float p0 = __expf(s_[nt][hh * 2] - mn);
                float p1 = __expf(s_[nt][hh * 2 + 1] - mn);
                s_[nt][hh * 2] = p0; s_[nt][hh * 2 + 1] = p1;
                sum += p0 + p1;
            }
            sum += __shfl_xor_sync(0xffffffffu, sum, 1);
            sum += __shfl_xor_sync(0xffffffffu, sum, 2);
            l_[hh] = l_[hh] * corr + sum;
#pragma unroll
            for (int d = 0; d < 8; d++) {
                o_[d][hh * 2] *= corr; o_[d][hh * 2 + 1] *= corr;
            }
        }

        uint32_t ph[4][4], pl[4][4];
#pragma unroll
        for (int j = 0; j < 4; j++) {
            split2pack(s_[2 * j][0], s_[2 * j][1], ph[j][0], pl[j][0]);
            split2pack(s_[2 * j][2], s_[2 * j][3], ph[j][1], pl[j][1]);
            split2pack(s_[2 * j + 1][0], s_[2 * j + 1][1], ph[j][2], pl[j][2]);
            split2pack(s_[2 * j + 1][2], s_[2 * j + 1][3], ph[j][3], pl[j][3]);
        }

        uint32_t vbase = stg + 2 * KV_MAT;
#pragma unroll
        for (int j = 0; j < 4; j++) {
            uint32_t vrow = (uint32_t)(j * 16 + (lane & 15)) * APB;
#pragma unroll
            for (int dtp = 0; dtp < 4; dtp++) {
                int dt0 = 2 * dtp, dt1 = dt0 + 1;
                uint32_t voA = vrow + dt0 * 16;
                uint32_t voB = vrow + dt1 * 16;
                uint32_t vha0, vha1, vla0, vla1, vhb0, vhb1, vlb0, vlb1;
                ldmx2t(vha0, vha1, vbase + voA);
                ldmx2t(vhb0, vhb1, vbase + voB);
                ldmx2t(vla0, vla1, vbase + KV_MAT + voA);
                ldmx2t(vlb0, vlb1, vbase + KV_MAT + voB);
                mma16816(o_[dt0], ph[j], vha0, vha1);
                mma16816(o_[dt1], ph[j], vhb0, vhb1);
                mma16816(o_[dt0], ph[j], vla0, vla1);
                mma16816(o_[dt1], ph[j], vlb0, vlb1);
                mma16816(o_[dt0], pl[j], vha0, vha1);
                mma16816(o_[dt1], pl[j], vhb0, vhb1);
            }
        }
        __syncthreads();
    }

    float inv0 = 1.f / l_[0], inv1 = 1.f / l_[1];
#pragma unroll
    for (int hh = 0; hh < 2; hh++) {
        float inv = hh == 0 ? inv0 : inv1;
        size_t grow = qrow0 + wid * 16 + (lane >> 2) + hh * 8;
#pragma unroll
        for (int dt = 0; dt < 8; dt++) {
            size_t idx = grow * DQ + col0 + dt * 8 + (lane & 3) * 2;
            float f0 = o_[dt][hh * 2] * inv;
            float f1 = o_[dt][hh * 2 + 1] * inv;
            bf h0, l0, h1, l1;
            split_bf16(f0, h0, l0); split_bf16(f1, h1, l1);
            *(__nv_bfloat162*)(OHp + idx) = __nv_bfloat162(h0, h1);
            *(__nv_bfloat162*)(OLp + idx) = __nv_bfloat162(l0, l1);
        }
    }
}

// ---------------------------------------------------------------------------
// kernel_launch
// ---------------------------------------------------------------------------
extern "C" void kernel_launch(void* const* d_in, const int* in_sizes, int n_in,
                              void* d_out, int out_size) {
    const float* x_q   = (const float*)d_in[0];
    const float* x_kv  = (const float*)d_in[1];
    const float* qn_g  = (const float*)d_in[2];
    const float* qn_b  = (const float*)d_in[3];
    const float* kvn_g = (const float*)d_in[4];
    const float* kvn_b = (const float*)d_in[5];
    const float* Wq    = (const float*)d_in[6];
    const float* bq    = (const float*)d_in[7];
    const float* Wk    = (const float*)d_in[8];
    const float* bk    = (const float*)d_in[9];
    const float* Wv    = (const float*)d_in[10];
    const float* bv    = (const float*)d_in[11];
    const float* Wo    = (const float*)d_in[12];
    const float* bo    = (const float*)d_in[13];
    const float* n2_g  = (const float*)d_in[14];
    const float* n2_b  = (const float*)d_in[15];
    const float* W1    = (const float*)d_in[16];
    const float* b1    = (const float*)d_in[17];
    const float* W2    = (const float*)d_in[18];
    const float* b2    = (const float*)d_in[19];
    float* out = (float*)d_out;

    bf* bfb = nullptr;
    cudaGetSymbolAddress((void**)&bfb, g_bf);

    bf* XQH = bfb + (size_t)O_XQH * EM;   bf* XQL = bfb + (size_t)O_XQL * EM;
    bf* XKVH = bfb + (size_t)O_XKVH * EM; bf* XKVL = bfb + (size_t)O_XKVL * EM;
    bf* ATTH = bfb + (size_t)O_ATTH * EM; bf* ATTL = bfb + (size_t)O_ATTL * EM;
    bf* X2H = bfb + (size_t)O_X2H * EM;   bf* X2L = bfb + (size_t)O_X2L * EM;
    bf* Hh  = bfb + (size_t)O_HH * EM;    bf* Hl  = bfb + (size_t)O_HL * EM;
    bf* WQH = bfb + (size_t)O_WQH * EM;   bf* WQL = bfb + (size_t)O_WQL * EM;
    bf* WKH = bfb + (size_t)O_WKH * EM;   bf* WKL = bfb + (size_t)O_WKL * EM;
    bf* WVH = bfb + (size_t)O_WVH * EM;   bf* WVL = bfb + (size_t)O_WVL * EM;
    bf* WOH = bfb + (size_t)O_WOH * EM;   bf* WOL = bfb + (size_t)O_WOL * EM;
    bf* W1H = bfb + (size_t)O_W1H * EM;   bf* W1L = bfb + (size_t)O_W1L * EM;
    bf* W2H = bfb + (size_t)O_W2H * EM;   bf* W2L = bfb + (size_t)O_W2L * EM;
    bf* QH  = bfb + (size_t)O_QH * EM;    bf* QL  = bfb + (size_t)O_QL * EM;
    bf* KH  = bfb + (size_t)O_KH * EM;    bf* KL  = bfb + (size_t)O_KL * EM;
    bf* VH  = bfb + (size_t)O_VH * EM;    bf* VL  = bfb + (size_t)O_VL * EM;

    cudaFuncSetAttribute(gemm_mma<1>, cudaFuncAttributeMaxDynamicSharedMemorySize, GEMM_SMEM);
    cudaFuncSetAttribute(gemm_mma<2>, cudaFuncAttributeMaxDynamicSharedMemorySize, GEMM_SMEM);
    cudaFuncSetAttribute(gemm_mma<3>, cudaFuncAttributeMaxDynamicSharedMemorySize, GEMM_SMEM);
    cudaFuncSetAttribute(gemm_qkv, cudaFuncAttributeMaxDynamicSharedMemorySize, GEMM_SMEM);
    cudaFuncSetAttribute(attn_mma, cudaFuncAttributeMaxDynamicSharedMemorySize, ATTN_SMEM);

    // 1: all weight splits (one launch, 3M float4 entries -> 12288 blocks)
    convert_all_kernel<<<12288, 256>>>(Wq, Wk, Wv, Wo, W1, W2, bfb);

    // 2: both input LNs fused
    ln2x_bf16_kernel<<<2 * MROWS, 256>>>(x_q, qn_g, qn_b, XQH, XQL,
                                         x_kv, kvn_g, kvn_b, XKVH, XKVL);

    // 3: fused Q+K+V projection (scale folded into Q)
    gemm_qkv<<<dim3(24, MROWS / 128), 256, GEMM_SMEM>>>(
        XQH, XQL, XKVH, XKVL, WQH, WQL, WKH, WKL, WVH, WVL,
        bq, bk, bv, QH, QL, KH, KL, VH, VL);

    // 4: tensor-core attention  (ncu-profiled launch)
    attn_mma<<<dim3(NN / 128, HH, BB), 256, ATTN_SMEM>>>(
        QH, QL, KH, KL, VH, VL, ATTH, ATTL);

    // 5: out projection + residual with x_q
    gemm_mma<1><<<dim3(DQ / 128, MROWS / 128), 256, GEMM_SMEM>>>(
        ATTH, ATTL, WOH, WOL, bo, x_q, out, nullptr, nullptr, DQ, DQ, 1.0f);

    // 6: LN2
    ln_bf16_kernel<<<MROWS, 256>>>(out, n2_g, n2_b, X2H, X2L);

    // 7: MLP up + GELU -> bf16 split
    gemm_mma<2><<<dim3(DFF / 128, MROWS / 128), 256, GEMM_SMEM>>>(
        X2H, X2L, W1H, W1L, b1, nullptr, nullptr, Hh, Hl, DFF, DQ, 1.0f);

    // 8: MLP down + residual accumulate into d_out
    gemm_mma<3><<<dim3(DQ / 128, MROWS / 128), 256, GEMM_SMEM>>>(
        Hh, Hl, W2H, W2L, b2, nullptr, out, nullptr, nullptr, DQ, DFF, 1.0f);
}

// round 11
// speedup vs baseline: 3.0981x; 1.0289x over previous
#include <cuda_runtime.h>
#include <cuda_bf16.h>
#include <math.h>
#include <stdint.h>

#define BB   2
#define NN   2048
#define LL   2048
#define DQ   1024
#define HH   16
#define HD   64
#define MROWS 4096
#define DFF  4096

typedef __nv_bfloat16 bf;

// ---------------------------------------------------------------------------
// Static scratch
// ---------------------------------------------------------------------------
#define EM (1024u*1024u)
__device__ __align__(256) bf g_bf[112u * EM];

#define O_XQH 0
#define O_XQL 4
#define O_XKVH 8
#define O_XKVL 12
#define O_ATTH 16
#define O_ATTL 20
#define O_X2H 24
#define O_X2L 28
#define O_HH  32
#define O_HL  48
#define O_WQH 64
#define O_WQL 65
#define O_WKH 66
#define O_WKL 67
#define O_WVH 68
#define O_WVL 69
#define O_WOH 70
#define O_WOL 71
#define O_W1H 72
#define O_W1L 76
#define O_W2H 80
#define O_W2L 84
#define O_QH  88
#define O_QL  92
#define O_KH  96
#define O_KL  100
#define O_VH  104
#define O_VL  108

// ---------------------------------------------------------------------------
// helpers
// ---------------------------------------------------------------------------
__device__ __forceinline__ uint32_t smem_u32(const void* p) {
    uint32_t a;
    asm("{ .reg .u64 t; cvta.to.shared.u64 t, %1; cvt.u32.u64 %0, t; }" : "=r"(a) : "l"(p));
    return a;
}
__device__ __forceinline__ void ldmx4(uint32_t& r0, uint32_t& r1, uint32_t& r2,
                                      uint32_t& r3, uint32_t a) {
    asm volatile("ldmatrix.sync.aligned.m8n8.x4.shared.b16 {%0,%1,%2,%3}, [%4];"
                 : "=r"(r0), "=r"(r1), "=r"(r2), "=r"(r3) : "r"(a));
}
__device__ __forceinline__ void ldmx2(uint32_t& r0, uint32_t& r1, uint32_t a) {
    asm volatile("ldmatrix.sync.aligned.m8n8.x2.shared.b16 {%0,%1}, [%2];"
                 : "=r"(r0), "=r"(r1) : "r"(a));
}
__device__ __forceinline__ void ldmx2t(uint32_t& r0, uint32_t& r1, uint32_t a) {
    asm volatile("ldmatrix.sync.aligned.m8n8.x2.trans.shared.b16 {%0,%1}, [%2];"
                 : "=r"(r0), "=r"(r1) : "r"(a));
}
__device__ __forceinline__ void mma16816(float* d, const uint32_t* a,
                                         uint32_t b0, uint32_t b1) {
    asm volatile(
        "mma.sync.aligned.m16n8k16.row.col.f32.bf16.bf16.f32 "
        "{%0,%1,%2,%3}, {%4,%5,%6,%7}, {%8,%9}, {%0,%1,%2,%3};"
        : "+f"(d[0]), "+f"(d[1]), "+f"(d[2]), "+f"(d[3])
        : "r"(a[0]), "r"(a[1]), "r"(a[2]), "r"(a[3]), "r"(b0), "r"(b1));
}
__device__ __forceinline__ void cp16(uint32_t dst, const void* src) {
    asm volatile("cp.async.cg.shared.global [%0], [%1], 16;" :: "r"(dst), "l"(src));
}
#define CP_COMMIT() asm volatile("cp.async.commit_group;" ::: "memory")
#define CP_WAIT0()  asm volatile("cp.async.wait_group 0;" ::: "memory")
#define CP_WAIT1()  asm volatile("cp.async.wait_group 1;" ::: "memory")

__device__ __forceinline__ float gelu_exact(float x) {
    return 0.5f * x * (1.f + erff(x * 0.7071067811865476f));
}
__device__ __forceinline__ void split_bf16(float x, bf& h, bf& l) {
    h = __float2bfloat16(x);
    l = __float2bfloat16(x - __bfloat162float(h));
}
__device__ __forceinline__ void split2pack(float a, float b, uint32_t& hi, uint32_t& lo) {
    bf ha = __float2bfloat16(a), hb = __float2bfloat16(b);
    float ra = a - __bfloat162float(ha), rb = b - __bfloat162float(hb);
    __nv_bfloat162 H(ha, hb);
    __nv_bfloat162 L(__float2bfloat16(ra), __float2bfloat16(rb));
    hi = *(uint32_t*)&H;
    lo = *(uint32_t*)&L;
}

// GEMM smem swizzle: pitch 64B, 16B chunk XORed with (row>>1)&3.
__device__ __forceinline__ uint32_t swz(uint32_t row, uint32_t colbyte) {
    return row * 64 + ((((colbyte >> 4) ^ (row >> 1)) & 3u) << 4);
}

// ---------------------------------------------------------------------------
// Fused LayerNorm (two tensors) -> bf16 hi/lo split
// ---------------------------------------------------------------------------
__global__ void ln2x_bf16_kernel(const float* __restrict__ xA,
                                 const float* __restrict__ gA,
                                 const float* __restrict__ bA,
                                 bf* __restrict__ yhA, bf* __restrict__ ylA,
                                 const float* __restrict__ xB,
                                 const float* __restrict__ gB,
                                 const float* __restrict__ bB,
                                 bf* __restrict__ yhB, bf* __restrict__ ylB) {
    int row = blockIdx.x;
    const float* x; const float* g; const float* b; bf* yh; bf* yl;
    if (row < MROWS) { x = xA; g = gA; b = bA; yh = yhA; yl = ylA; }
    else { x = xB; g = gB; b = bB; yh = yhB; yl = ylB; row -= MROWS; }

    const float* xr = x + (size_t)row * DQ;
    float v[4];
    float s = 0.f, s2 = 0.f;
#pragma unroll
    for (int i = 0; i < 4; i++) {
        float t = xr[threadIdx.x + i * 256];
        v[i] = t; s += t; s2 += t * t;
    }
#pragma unroll
    for (int o = 16; o > 0; o >>= 1) {
        s  += __shfl_xor_sync(0xffffffffu, s,  o);
        s2 += __shfl_xor_sync(0xffffffffu, s2, o);
    }
    __shared__ float ws[8], ws2[8];
    int w = threadIdx.x >> 5, lane = threadIdx.x & 31;
    if (lane == 0) { ws[w] = s; ws2[w] = s2; }
    __syncthreads();
    if (w == 0) {
        s  = (lane < 8) ? ws[lane]  : 0.f;
        s2 = (lane < 8) ? ws2[lane] : 0.f;
#pragma unroll
        for (int o = 4; o > 0; o >>= 1) {
            s  += __shfl_xor_sync(0xffffffffu, s,  o);
            s2 += __shfl_xor_sync(0xffffffffu, s2, o);
        }
        if (lane == 0) { ws[0] = s; ws2[0] = s2; }
    }
    __syncthreads();
    float mean = ws[0] * (1.f / DQ);
    float var  = ws2[0] * (1.f / DQ) - mean * mean;
    float rstd = rsqrtf(var + 1e-5f);
    size_t base = (size_t)row * DQ;
#pragma unroll
    for (int i = 0; i < 4; i++) {
        int c = threadIdx.x + i * 256;
        float yv = (v[i] - mean) * rstd * g[c] + b[c];
        bf h, l; split_bf16(yv, h, l);
        yh[base + c] = h;
        yl[base + c] = l;
    }
}

// single-tensor LN (for LN2)
__global__ void ln_bf16_kernel(const float* __restrict__ x,
                               const float* __restrict__ g,
                               const float* __restrict__ b,
                               bf* __restrict__ yh, bf* __restrict__ yl) {
    int row = blockIdx.x;
    const float* xr = x + (size_t)row * DQ;
    float v[4];
    float s = 0.f, s2 = 0.f;
#pragma unroll
    for (int i = 0; i < 4; i++) {
        float t = xr[threadIdx.x + i * 256];
        v[i] = t; s += t; s2 += t * t;
    }
#pragma unroll
    for (int o = 16; o > 0; o >>= 1) {
        s  += __shfl_xor_sync(0xffffffffu, s,  o);
        s2 += __shfl_xor_sync(0xffffffffu, s2, o);
    }
    __shared__ float ws[8], ws2[8];
    int w = threadIdx.x >> 5, lane = threadIdx.x & 31;
    if (lane == 0) { ws[w] = s; ws2[w] = s2; }
    __syncthreads();
    if (w == 0) {
        s  = (lane < 8) ? ws[lane]  : 0.f;
        s2 = (lane < 8) ? ws2[lane] : 0.f;
#pragma unroll
        for (int o = 4; o > 0; o >>= 1) {
            s  += __shfl_xor_sync(0xffffffffu, s,  o);
            s2 += __shfl_xor_sync(0xffffffffu, s2, o);
        }
        if (lane == 0) { ws[0] = s; ws2[0] = s2; }
    }
    __syncthreads();
    float mean = ws[0] * (1.f / DQ);
    float var  = ws2[0] * (1.f / DQ) - mean * mean;
    float rstd = rsqrtf(var + 1e-5f);
    size_t base = (size_t)row * DQ;
#pragma unroll
    for (int i = 0; i < 4; i++) {
        int c = threadIdx.x + i * 256;
        float yv = (v[i] - mean) * rstd * g[c] + b[c];
        bf h, l; split_bf16(yv, h, l);
        yh[base + c] = h;
        yl[base + c] = l;
    }
}

// ---------------------------------------------------------------------------
// Single fused weight convert: all 6 weight tensors (3M float4 entries).
// ---------------------------------------------------------------------------
__global__ void convert_all_kernel(
    const float* __restrict__ wq, const float* __restrict__ wk,
    const float* __restrict__ wv, const float* __restrict__ wo,
    const float* __restrict__ w1, const float* __restrict__ w2,
    bf* __restrict__ base) {
    int i = blockIdx.x * blockDim.x + threadIdx.x;   // 0 .. 3M-1
    const float* w; bf* h; bf* l; int off;
    if (i < (1 << 20)) {
        int seg = i >> 18;
        off = i & 0x3FFFF;
        w = seg == 0 ? wq : seg == 1 ? wk : seg == 2 ? wv : wo;
        h = base + (size_t)(O_WQH + 2 * seg) * EM;
        l = base + (size_t)(O_WQL + 2 * seg) * EM;
    } else {
        int j = i - (1 << 20);
        int seg = j >> 20;
        off = j & 0xFFFFF;
        w = seg == 0 ? w1 : w2;
        h = base + (size_t)(seg == 0 ? O_W1H : O_W2H) * EM;
        l = base + (size_t)(seg == 0 ? O_W1L : O_W2L) * EM;
    }
    float4 v = ((const float4*)w)[off];
    bf a0, b0, a1, b1, a2, b2, a3, b3;
    split_bf16(v.x, a0, b0); split_bf16(v.y, a1, b1);
    split_bf16(v.z, a2, b2); split_bf16(v.w, a3, b3);
    __nv_bfloat162* hp = (__nv_bfloat162*)(h + (size_t)off * 4);
    __nv_bfloat162* lp = (__nv_bfloat162*)(l + (size_t)off * 4);
    hp[0] = __nv_bfloat162(a0, a1); hp[1] = __nv_bfloat162(a2, a3);
    lp[0] = __nv_bfloat162(b0, b1); lp[1] = __nv_bfloat162(b2, b3);
}

// ---------------------------------------------------------------------------
// HMMA GEMM core (bf16x3 split), 3-stage cp.async pipeline, pitch-64 swizzle.
// ---------------------------------------------------------------------------
#define MAT_BYTES (128 * 64)
#define STAGE_BYTES (4 * MAT_BYTES)
#define GEMM_SMEM (3 * STAGE_BYTES)

template <int EPI>
__device__ __forceinline__ void gemm_core(
    const bf* __restrict__ Ah, const bf* __restrict__ Al,
    const bf* __restrict__ Bh, const bf* __restrict__ Bl,
    const float* __restrict__ bias, const float* __restrict__ res,
    float* __restrict__ C, bf* __restrict__ Ho, bf* __restrict__ Lo,
    int N, int K, float alpha, size_t m0, size_t n0, char* smc) {
    const int tid = threadIdx.x, lane = tid & 31, wid = tid >> 5;
    const int wm = wid & 1, wn = wid >> 1;
    const uint32_t sbase = smem_u32(smc);

    const bf* gsrc0 = Ah + m0 * K;
    const bf* gsrc1 = Al + m0 * K;
    const bf* gsrc2 = Bh + n0 * K;
    const bf* gsrc3 = Bl + n0 * K;

    auto load_stage = [&](int s, int kt) {
        uint32_t base = sbase + s * STAGE_BYTES;
#pragma unroll
        for (int i = 0; i < 8; i++) {
            const int t = i >> 1;
            int idx = tid + (i & 1) * 256;
            int row = idx >> 2, seg = idx & 3;
            const bf* src = (t == 0 ? gsrc0 : t == 1 ? gsrc1 : t == 2 ? gsrc2 : gsrc3);
            cp16(base + t * MAT_BYTES + swz((uint32_t)row, (uint32_t)(seg * 16)),
                 src + (size_t)row * K + kt + seg * 8);
        }
    };

    float acc[4][4][4];
#pragma unroll
    for (int a = 0; a < 4; a++)
#pragma unroll
        for (int b = 0; b < 4; b++)
#pragma unroll
            for (int c = 0; c < 4; c++) acc[a][b][c] = 0.f;

    const int nk = K >> 5;
    load_stage(0, 0);
    CP_COMMIT();
    load_stage(1, 32);
    CP_COMMIT();

    const uint32_t brow = (uint32_t)(wn * 32 + ((lane >> 4) & 1) * 8 + (lane & 7));
    const uint32_t bcolh = (uint32_t)(((lane >> 3) & 1) * 16);
    const uint32_t arow = (uint32_t)(wm * 64 + (lane & 15));
    const uint32_t acolh = (uint32_t)((lane >> 4) * 16);

    int stage = 0;
    for (int cc = 0; cc < nk; cc++) {
        if (cc + 1 < nk) CP_WAIT1(); else CP_WAIT0();
        __syncthreads();
        if (cc + 2 < nk) {
            int ns = stage + 2; if (ns >= 3) ns -= 3;
            load_stage(ns, (cc + 2) << 5);
            CP_COMMIT();
        }

        uint32_t st = sbase + stage * STAGE_BYTES;
        uint32_t sAh = st, sAl = st + MAT_BYTES;
        uint32_t sBh = st + 2 * MAT_BYTES, sBl = st + 3 * MAT_BYTES;

        uint32_t Bh_[2][8], Bl_[2][8];
#pragma unroll
        for (int k16 = 0; k16 < 2; k16++) {
            uint32_t bcol = (uint32_t)(k16 * 32) + bcolh;
#pragma unroll
            for (int pr = 0; pr < 2; pr++) {
                uint32_t bo = swz(brow + pr * 16, bcol);
                ldmx4(Bh_[k16][pr * 4 + 0], Bh_[k16][pr * 4 + 1],
                      Bh_[k16][pr * 4 + 2], Bh_[k16][pr * 4 + 3], sBh + bo);
                ldmx4(Bl_[k16][pr * 4 + 0], Bl_[k16][pr * 4 + 1],
                      Bl_[k16][pr * 4 + 2], Bl_[k16][pr * 4 + 3], sBl + bo);
            }
        }

#pragma unroll
        for (int mt = 0; mt < 4; mt++) {
#pragma unroll
            for (int k16 = 0; k16 < 2; k16++) {
                uint32_t ao = swz(arow + mt * 16, (uint32_t)(k16 * 32) + acolh);
                uint32_t ah[4], al[4];
                ldmx4(ah[0], ah[1], ah[2], ah[3], sAh + ao);
                ldmx4(al[0], al[1], al[2], al[3], sAl + ao);
#pragma unroll
                for (int nt = 0; nt < 4; nt++)
                    mma16816(acc[mt][nt], ah, Bh_[k16][nt * 2], Bh_[k16][nt * 2 + 1]);
#pragma unroll
                for (int nt = 0; nt < 4; nt++)
                    mma16816(acc[mt][nt], ah, Bl_[k16][nt * 2], Bl_[k16][nt * 2 + 1]);
#pragma unroll
                for (int nt = 0; nt < 4; nt++)
                    mma16816(acc[mt][nt], al, Bh_[k16][nt * 2], Bh_[k16][nt * 2 + 1]);
            }
        }
        stage++; if (stage >= 3) stage -= 3;
    }

#pragma unroll
    for (int mt = 0; mt < 4; mt++) {
        int r0 = wm * 64 + mt * 16 + (lane >> 2);
#pragma unroll
        for (int nt = 0; nt < 4; nt++) {
            size_t gcol = n0 + wn * 32 + nt * 8 + (lane & 3) * 2;
            float2 bb = *(const float2*)(bias + gcol);
#pragma unroll
            for (int h = 0; h < 2; h++) {
                size_t grow = m0 + r0 + h * 8;
                size_t idx = grow * (size_t)N + gcol;
                float v0 = acc[mt][nt][h * 2 + 0] + bb.x;
                float v1 = acc[mt][nt][h * 2 + 1] + bb.y;
                if (EPI == 1) {
                    float2 rr = *(const float2*)(res + idx);
                    v0 += rr.x; v1 += rr.y;
                }
                if (EPI == 3) {
                    float2 rr = *(const float2*)(C + idx);
                    v0 += rr.x; v1 += rr.y;
                }
                if (EPI == 2 || EPI == 4) {
                    if (EPI == 2) { v0 = gelu_exact(v0); v1 = gelu_exact(v1); }
                    else          { v0 *= alpha; v1 *= alpha; }
                    bf h0, l0, h1, l1;
                    split_bf16(v0, h0, l0); split_bf16(v1, h1, l1);
                    *(__nv_bfloat162*)(Ho + idx) = __nv_bfloat162(h0, h1);
                    *(__nv_bfloat162*)(Lo + idx) = __nv_bfloat162(l0, l1);
                } else {
                    float2 o; o.x = v0; o.y = v1;
                    *(float2*)(C + idx) = o;
                }
            }
        }
    }
}

template <int EPI>
__global__ void __launch_bounds__(256, 2)
gemm_mma(const bf* __restrict__ Ah, const bf* __restrict__ Al,
         const bf* __restrict__ Bh, const bf* __restrict__ Bl,
         const float* __restrict__ bias, const float* __restrict__ res,
         float* __restrict__ C, bf* __restrict__ Ho, bf* __restrict__ Lo,
         int N, int K, float alpha) {
    extern __shared__ char smc[];
    gemm_core<EPI>(Ah, Al, Bh, Bl, bias, res, C, Ho, Lo, N, K, alpha,
                   (size_t)blockIdx.y * 128, (size_t)blockIdx.x * 128, smc);
}

// Fused Q/K/V projection: blockIdx.x 0-7 -> Q, 8-15 -> K, 16-23 -> V
__global__ void __launch_bounds__(256, 2)
gemm_qkv(const bf* __restrict__ XQh, const bf* __restrict__ XQl,
         const bf* __restrict__ XKVh, const bf* __restrict__ XKVl,
         const bf* __restrict__ WQh, const bf* __restrict__ WQl,
         const bf* __restrict__ WKh, const bf* __restrict__ WKl,
         const bf* __restrict__ WVh, const bf* __restrict__ WVl,
         const float* __restrict__ bq, const float* __restrict__ bk,
         const float* __restrict__ bv,
         bf* __restrict__ QH, bf* __restrict__ QL,
         bf* __restrict__ KH, bf* __restrict__ KL,
         bf* __restrict__ VH, bf* __restrict__ VL) {
    extern __shared__ char smc[];
    size_t m0 = (size_t)blockIdx.y * 128;
    int xb = blockIdx.x;
    if (xb < 8) {
        gemm_core<4>(XQh, XQl, WQh, WQl, bq, nullptr, nullptr, QH, QL,
                     DQ, DQ, 0.125f, m0, (size_t)xb * 128, smc);
    } else if (xb < 16) {
        gemm_core<4>(XKVh, XKVl, WKh, WKl, bk, nullptr, nullptr, KH, KL,
                     DQ, DQ, 1.0f, m0, (size_t)(xb - 8) * 128, smc);
    } else {
        gemm_core<4>(XKVh, XKVl, WVh, WVl, bv, nullptr, nullptr, VH, VL,
                     DQ, DQ, 1.0f, m0, (size_t)(xb - 16) * 128, smc);
    }
}

// ---------------------------------------------------------------------------
// Tensor-core flash attention, softmax-1.
// 128 threads (4 warps) x 64 q-rows per CTA -> 2-3 CTAs/SM co-resident so
// one CTA's MMAs overlap another's softmax. Per-warp math identical to R10.
// ---------------------------------------------------------------------------
#define APB 144
#define KV_MAT (64 * APB)
#define KV_STAGE (4 * KV_MAT)
#define ATTN_SMEM (2 * KV_STAGE)   // 73728

__global__ void __launch_bounds__(128, 3)
attn_mma(const bf* __restrict__ QHp, const bf* __restrict__ QLp,
         const bf* __restrict__ KHp, const bf* __restrict__ KLp,
         const bf* __restrict__ VHp, const bf* __restrict__ VLp,
         bf* __restrict__ OHp, bf* __restrict__ OLp) {
    extern __shared__ char smc[];
    const uint32_t sb = smem_u32(smc);
    const int tid = threadIdx.x, lane = tid & 31, wid = tid >> 5;  // wid 0..3
    const int b = blockIdx.z, h = blockIdx.y;
    const int n0 = blockIdx.x * 64;
    const size_t qrow0 = (size_t)b * NN + n0;
    const size_t col0 = (size_t)h * HD;

    // ---- stage Q (hi/lo, 64 rows) through smem into A-fragments ----
    {
        const bf* s0 = QHp + qrow0 * DQ + col0;
        const bf* s1 = QLp + qrow0 * DQ + col0;
#pragma unroll
        for (int it = 0; it < 8; it++) {
            int g = it * 128 + tid;            // 0..1023
            int m = g >> 9;                    // 0..1
            int r = (g & 511) >> 3, c = g & 7; // 64 rows x 8 chunks
            const bf* src = m == 0 ? s0 : s1;
            cp16(sb + m * (64 * APB) + r * APB + c * 16, src + (size_t)r * DQ + c * 8);
        }
    }
    CP_COMMIT();
    CP_WAIT0();
    __syncthreads();

    uint32_t qh[4][4], ql[4][4];
#pragma unroll
    for (int k16 = 0; k16 < 4; k16++) {
        uint32_t ao = (uint32_t)(wid * 16 + (lane & 15)) * APB
                    + (uint32_t)(k16 * 16 + (lane >> 4) * 8) * 2;
        ldmx4(qh[k16][0], qh[k16][1], qh[k16][2], qh[k16][3], sb + ao);
        ldmx4(ql[k16][0], ql[k16][1], ql[k16][2], ql[k16][3], sb + 64 * APB + ao);
    }
    __syncthreads();

    const bf* kvsrc[4] = {
        KHp + ((size_t)b * LL) * DQ + col0,
        KLp + ((size_t)b * LL) * DQ + col0,
        VHp + ((size_t)b * LL) * DQ + col0,
        VLp + ((size_t)b * LL) * DQ + col0
    };
    auto load_kv = [&](int blk, int s) {
        uint32_t base = sb + s * KV_STAGE;
        size_t roff = (size_t)blk * 64;
#pragma unroll
        for (int it = 0; it < 16; it++) {
            int g = it * 128 + tid;            // 0..2047
            int m = g >> 9;
            int r = (g & 511) >> 3, c = g & 7;
            cp16(base + m * KV_MAT + r * APB + c * 16,
                 kvsrc[m] + (roff + r) * DQ + c * 8);
        }
    };

    float m_[2] = {0.f, 0.f}, l_[2] = {1.f, 1.f};
    float o_[8][4];
#pragma unroll
    for (int d = 0; d < 8; d++)
#pragma unroll
        for (int j = 0; j < 4; j++) o_[d][j] = 0.f;

    load_kv(0, 0);
    CP_COMMIT();

    const int NBLK = LL / 64;
    for (int i = 0; i < NBLK; i++) {
        if (i + 1 < NBLK) { load_kv(i + 1, (i + 1) & 1); CP_COMMIT(); CP_WAIT1(); }
        else CP_WAIT0();
        __syncthreads();

        uint32_t stg = sb + (i & 1) * KV_STAGE;

        float s_[8][4];
#pragma unroll
        for (int nt = 0; nt < 8; nt++)
#pragma unroll
            for (int j = 0; j < 4; j++) s_[nt][j] = 0.f;

#pragma unroll
        for (int k16 = 0; k16 < 4; k16++) {
            uint32_t bcol = (uint32_t)(k16 * 16 + ((lane >> 3) & 1) * 8) * 2;
            uint32_t brow = (uint32_t)(lane & 7);
#pragma unroll
            for (int ntp = 0; ntp < 4; ntp++) {
                int nt0 = 2 * ntp, nt1 = nt0 + 1;
                uint32_t boA = (brow + nt0 * 8) * APB + bcol;
                uint32_t boB = (brow + nt1 * 8) * APB + bcol;
                uint32_t kha0, kha1, kla0, kla1, khb0, khb1, klb0, klb1;
                ldmx2(kha0, kha1, stg + boA);
                ldmx2(khb0, khb1, stg + boB);
                ldmx2(kla0, kla1, stg + KV_MAT + boA);
                ldmx2(klb0, klb1, stg + KV_MAT + boB);
                mma16816(s_[nt0], qh[k16], kha0, kha1);
                mma16816(s_[nt1], qh[k16], khb0, khb1);
                mma16816(s_[nt0], qh[k16], kla0, kla1);
                mma16816(s_[nt1], qh[k16], klb0, klb1);
                mma16816(s_[nt0], ql[k16], kha0, kha1);
                mma16816(s_[nt1], ql[k16], khb0, khb1);
            }
        }

#pragma unroll
        for (int hh = 0; hh < 2; hh++) {
            float mx = s_[0][hh * 2];
#pragma unroll
            for (int nt = 0; nt < 8; nt++)
                mx = fmaxf(mx, fmaxf(s_[nt][hh * 2], s_[nt][hh * 2 + 1]));
            mx = fmaxf(mx, __shfl_xor_sync(0xffffffffu, mx, 1));
            mx = fmaxf(mx, __shfl_xor_sync(0xffffffffu, mx, 2));
            float mn = fmaxf(m_[hh], mx);
            float corr = __expf(m_[hh] - mn);
            m_[hh] = mn;
            float sum = 0.f;
#pragma unroll
            for (int nt = 0; nt < 8; nt++) {
                float p0 = __expf(s_[nt][hh * 2] - mn);
                float p1 = __expf(s_[nt][hh * 2 + 1] - mn);
                s_[nt][hh * 2] = p0; s_[nt][hh * 2 + 1] = p1;
                sum += p0 + p1;
            }
            sum += __shfl_xor_sync(0xffffffffu, sum, 1);
            sum += __shfl_xor_sync(0xffffffffu, sum, 2);
            l_[hh] = l_[hh] * corr + sum;
#pragma unroll
            for (int d = 0; d < 8; d++) {
                o_[d][hh * 2] *= corr; o_[d][hh * 2 + 1] *= corr;
            }
        }

        uint32_t ph[4][4], pl[4][4];
#pragma unroll
        for (int j = 0; j < 4; j++) {
            split2pack(s_[2 * j][0], s_[2 * j][1], ph[j][0], pl[j][0]);
            split2pack(s_[2 * j][2], s_[2 * j][3], ph[j][1], pl[j][1]);
            split2pack(s_[2 * j + 1][0], s_[2 * j + 1][1], ph[j][2], pl[j][2]);
            split2pack(s_[2 * j + 1][2], s_[2 * j + 1][3], ph[j][3], pl[j][3]);
        }

        uint32_t vbase = stg + 2 * KV_MAT;
#pragma unroll
        for (int j = 0; j < 4; j++) {
            uint32_t vrow = (uint32_t)(j * 16 + (lane & 15)) * APB;
#pragma unroll
            for (int dtp = 0; dtp < 4; dtp++) {
                int dt0 = 2 * dtp, dt1 = dt0 + 1;
                uint32_t voA = vrow + dt0 * 16;
                uint32_t voB = vrow + dt1 * 16;
                uint32_t vha0, vha1, vla0, vla1, vhb0, vhb1, vlb0, vlb1;
                ldmx2t(vha0, vha1, vbase + voA);
                ldmx2t(vhb0, vhb1, vbase + voB);
                ldmx2t(vla0, vla1, vbase + KV_MAT + voA);
                ldmx2t(vlb0, vlb1, vbase + KV_MAT + voB);
                mma16816(o_[dt0], ph[j], vha0, vha1);
                mma16816(o_[dt1], ph[j], vhb0, vhb1);
                mma16816(o_[dt0], ph[j], vla0, vla1);
                mma16816(o_[dt1], ph[j], vlb0, vlb1);
                mma16816(o_[dt0], pl[j], vha0, vha1);
                mma16816(o_[dt1], pl[j], vhb0, vhb1);
            }
        }
        __syncthreads();
    }

    float inv0 = 1.f / l_[0], inv1 = 1.f / l_[1];
#pragma unroll
    for (int hh = 0; hh < 2; hh++) {
        float inv = hh == 0 ? inv0 : inv1;
        size_t grow = qrow0 + wid * 16 + (lane >> 2) + hh * 8;
#pragma unroll
        for (int dt = 0; dt < 8; dt++) {
            size_t idx = grow * DQ + col0 + dt * 8 + (lane & 3) * 2;
            float f0 = o_[dt][hh * 2] * inv;
            float f1 = o_[dt][hh * 2 + 1] * inv;
            bf h0, l0, h1, l1;
            split_bf16(f0, h0, l0); split_bf16(f1, h1, l1);
            *(__nv_bfloat162*)(OHp + idx) = __nv_bfloat162(h0, h1);
            *(__nv_bfloat162*)(OLp + idx) = __nv_bfloat162(l0, l1);
        }
    }
}

// ---------------------------------------------------------------------------
// kernel_launch
// ---------------------------------------------------------------------------
extern "C" void kernel_launch(void* const* d_in, const int* in_sizes, int n_in,
                              void* d_out, int out_size) {
    const float* x_q   = (const float*)d_in[0];
    const float* x_kv  = (const float*)d_in[1];
    const float* qn_g  = (const float*)d_in[2];
    const float* qn_b  = (const float*)d_in[3];
    const float* kvn_g = (const float*)d_in[4];
    const float* kvn_b = (const float*)d_in[5];
    const float* Wq    = (const float*)d_in[6];
    const float* bq    = (const float*)d_in[7];
    const float* Wk    = (const float*)d_in[8];
    const float* bk    = (const float*)d_in[9];
    const float* Wv    = (const float*)d_in[10];
    const float* bv    = (const float*)d_in[11];
    const float* Wo    = (const float*)d_in[12];
    const float* bo    = (const float*)d_in[13];
    const float* n2_g  = (const float*)d_in[14];
    const float* n2_b  = (const float*)d_in[15];
    const float* W1    = (const float*)d_in[16];
    const float* b1    = (const float*)d_in[17];
    const float* W2    = (const float*)d_in[18];
    const float* b2    = (const float*)d_in[19];
    float* out = (float*)d_out;

    bf* bfb = nullptr;
    cudaGetSymbolAddress((void**)&bfb, g_bf);

    bf* XQH = bfb + (size_t)O_XQH * EM;   bf* XQL = bfb + (size_t)O_XQL * EM;
    bf* XKVH = bfb + (size_t)O_XKVH * EM; bf* XKVL = bfb + (size_t)O_XKVL * EM;
    bf* ATTH = bfb + (size_t)O_ATTH * EM; bf* ATTL = bfb + (size_t)O_ATTL * EM;
    bf* X2H = bfb + (size_t)O_X2H * EM;   bf* X2L = bfb + (size_t)O_X2L * EM;
    bf* Hh  = bfb + (size_t)O_HH * EM;    bf* Hl  = bfb + (size_t)O_HL * EM;
    bf* WQH = bfb + (size_t)O_WQH * EM;   bf* WQL = bfb + (size_t)O_WQL * EM;
    bf* WKH = bfb + (size_t)O_WKH * EM;   bf* WKL = bfb + (size_t)O_WKL * EM;
    bf* WVH = bfb + (size_t)O_WVH * EM;   bf* WVL = bfb + (size_t)O_WVL * EM;
    bf* WOH = bfb + (size_t)O_WOH * EM;   bf* WOL = bfb + (size_t)O_WOL * EM;
    bf* W1H = bfb + (size_t)O_W1H * EM;   bf* W1L = bfb + (size_t)O_W1L * EM;
    bf* W2H = bfb + (size_t)O_W2H * EM;   bf* W2L = bfb + (size_t)O_W2L * EM;
    bf* QH  = bfb + (size_t)O_QH * EM;    bf* QL  = bfb + (size_t)O_QL * EM;
    bf* KH  = bfb + (size_t)O_KH * EM;    bf* KL  = bfb + (size_t)O_KL * EM;
    bf* VH  = bfb + (size_t)O_VH * EM;    bf* VL  = bfb + (size_t)O_VL * EM;

    cudaFuncSetAttribute(gemm_mma<1>, cudaFuncAttributeMaxDynamicSharedMemorySize, GEMM_SMEM);
    cudaFuncSetAttribute(gemm_mma<2>, cudaFuncAttributeMaxDynamicSharedMemorySize, GEMM_SMEM);
    cudaFuncSetAttribute(gemm_mma<3>, cudaFuncAttributeMaxDynamicSharedMemorySize, GEMM_SMEM);
    cudaFuncSetAttribute(gemm_qkv, cudaFuncAttributeMaxDynamicSharedMemorySize, GEMM_SMEM);
    cudaFuncSetAttribute(attn_mma, cudaFuncAttributeMaxDynamicSharedMemorySize, ATTN_SMEM);

    // 1: all weight splits (3M float4 -> 12288 blocks)
    convert_all_kernel<<<12288, 256>>>(Wq, Wk, Wv, Wo, W1, W2, bfb);

    // 2: both input LNs fused
    ln2x_bf16_kernel<<<2 * MROWS, 256>>>(x_q, qn_g, qn_b, XQH, XQL,
                                         x_kv, kvn_g, kvn_b, XKVH, XKVL);

    // 3: fused Q+K+V projection (scale folded into Q)
    gemm_qkv<<<dim3(24, MROWS / 128), 256, GEMM_SMEM>>>(
        XQH, XQL, XKVH, XKVL, WQH, WQL, WKH, WKL, WVH, WVL,
        bq, bk, bv, QH, QL, KH, KL, VH, VL);

    // 4: tensor-core attention (128-thread CTAs, 64 q-rows, co-resident)
    attn_mma<<<dim3(NN / 64, HH, BB), 128, ATTN_SMEM>>>(
        QH, QL, KH, KL, VH, VL, ATTH, ATTL);

    // 5: out projection + residual with x_q
    gemm_mma<1><<<dim3(DQ / 128, MROWS / 128), 256, GEMM_SMEM>>>(
        ATTH, ATTL, WOH, WOL, bo, x_q, out, nullptr, nullptr, DQ, DQ, 1.0f);

    // 6: LN2
    ln_bf16_kernel<<<MROWS, 256>>>(out, n2_g, n2_b, X2H, X2L);

    // 7: MLP up + GELU -> bf16 split
    gemm_mma<2><<<dim3(DFF / 128, MROWS / 128), 256, GEMM_SMEM>>>(
        X2H, X2L, W1H, W1L, b1, nullptr, nullptr, Hh, Hl, DFF, DQ, 1.0f);

    // 8: MLP down + residual accumulate into d_out
    gemm_mma<3><<<dim3(DQ / 128, MROWS / 128), 256, GEMM_SMEM>>>(
        Hh, Hl, W2H, W2L, b2, nullptr, out, nullptr, nullptr, DQ, DFF, 1.0f);
}

// round 12
// speedup vs baseline: 4.4245x; 1.4281x over previous
#include <cuda_runtime.h>
#include <cuda_fp16.h>
#include <math.h>
#include <stdint.h>

#define BB   2
#define NN   2048
#define LL   2048
#define DQ   1024
#define HH   16
#define HD   64
#define MROWS 4096
#define DFF  4096

typedef __half hf;

// ---------------------------------------------------------------------------
// Static scratch (fp16). Offsets in EM elements.
// ---------------------------------------------------------------------------
#define EM (1024u*1024u)
__device__ __align__(256) hf g_hf[96u * EM];

#define O_XQH 0
#define O_XQL 4
#define O_XKVH 8
#define O_XKVL 12
#define O_ATTH 16
#define O_ATTL 20
#define O_X2H 24
#define O_X2L 28
#define O_HH  32
#define O_HL  48
#define O_WQ  64
#define O_WK  65
#define O_WV  66
#define O_WO  67
#define O_W1  68
#define O_W2  72
#define O_QH  76
#define O_QL  80
#define O_KK  84
#define O_VV  88

// ---------------------------------------------------------------------------
// helpers
// ---------------------------------------------------------------------------
__device__ __forceinline__ uint32_t smem_u32(const void* p) {
    uint32_t a;
    asm("{ .reg .u64 t; cvta.to.shared.u64 t, %1; cvt.u32.u64 %0, t; }" : "=r"(a) : "l"(p));
    return a;
}
__device__ __forceinline__ void ldmx4(uint32_t& r0, uint32_t& r1, uint32_t& r2,
                                      uint32_t& r3, uint32_t a) {
    asm volatile("ldmatrix.sync.aligned.m8n8.x4.shared.b16 {%0,%1,%2,%3}, [%4];"
                 : "=r"(r0), "=r"(r1), "=r"(r2), "=r"(r3) : "r"(a));
}
__device__ __forceinline__ void ldmx2(uint32_t& r0, uint32_t& r1, uint32_t a) {
    asm volatile("ldmatrix.sync.aligned.m8n8.x2.shared.b16 {%0,%1}, [%2];"
                 : "=r"(r0), "=r"(r1) : "r"(a));
}
__device__ __forceinline__ void ldmx2t(uint32_t& r0, uint32_t& r1, uint32_t a) {
    asm volatile("ldmatrix.sync.aligned.m8n8.x2.trans.shared.b16 {%0,%1}, [%2];"
                 : "=r"(r0), "=r"(r1) : "r"(a));
}
__device__ __forceinline__ void mma16816(float* d, const uint32_t* a,
                                         uint32_t b0, uint32_t b1) {
    asm volatile(
        "mma.sync.aligned.m16n8k16.row.col.f32.f16.f16.f32 "
        "{%0,%1,%2,%3}, {%4,%5,%6,%7}, {%8,%9}, {%0,%1,%2,%3};"
        : "+f"(d[0]), "+f"(d[1]), "+f"(d[2]), "+f"(d[3])
        : "r"(a[0]), "r"(a[1]), "r"(a[2]), "r"(a[3]), "r"(b0), "r"(b1));
}
__device__ __forceinline__ void cp16(uint32_t dst, const void* src) {
    asm volatile("cp.async.cg.shared.global [%0], [%1], 16;" :: "r"(dst), "l"(src));
}
#define CP_COMMIT() asm volatile("cp.async.commit_group;" ::: "memory")
#define CP_WAIT0()  asm volatile("cp.async.wait_group 0;" ::: "memory")
#define CP_WAIT1()  asm volatile("cp.async.wait_group 1;" ::: "memory")

__device__ __forceinline__ float gelu_exact(float x) {
    return 0.5f * x * (1.f + erff(x * 0.7071067811865476f));
}
__device__ __forceinline__ void split_hf(float x, hf& h, hf& l) {
    h = __float2half_rn(x);
    l = __float2half_rn(x - __half2float(h));
}
__device__ __forceinline__ void split2pack(float a, float b, uint32_t& hi, uint32_t& lo) {
    hf ha = __float2half_rn(a), hb = __float2half_rn(b);
    float ra = a - __half2float(ha), rb = b - __half2float(hb);
    __half2 H = __halves2half2(ha, hb);
    __half2 L = __halves2half2(__float2half_rn(ra), __float2half_rn(rb));
    hi = *(uint32_t*)&H;
    lo = *(uint32_t*)&L;
}

// GEMM smem swizzle: pitch 64B, 16B chunk XORed with (row>>1)&3.
__device__ __forceinline__ uint32_t swz(uint32_t row, uint32_t colbyte) {
    return row * 64 + ((((colbyte >> 4) ^ (row >> 1)) & 3u) << 4);
}

// ---------------------------------------------------------------------------
// Fused LayerNorm (two tensors) -> fp16 hi/lo split
// ---------------------------------------------------------------------------
__global__ void ln2x_kernel(const float* __restrict__ xA,
                            const float* __restrict__ gA,
                            const float* __restrict__ bA,
                            hf* __restrict__ yhA, hf* __restrict__ ylA,
                            const float* __restrict__ xB,
                            const float* __restrict__ gB,
                            const float* __restrict__ bB,
                            hf* __restrict__ yhB, hf* __restrict__ ylB) {
    int row = blockIdx.x;
    const float* x; const float* g; const float* b; hf* yh; hf* yl;
    if (row < MROWS) { x = xA; g = gA; b = bA; yh = yhA; yl = ylA; }
    else { x = xB; g = gB; b = bB; yh = yhB; yl = ylB; row -= MROWS; }

    const float* xr = x + (size_t)row * DQ;
    float v[4];
    float s = 0.f, s2 = 0.f;
#pragma unroll
    for (int i = 0; i < 4; i++) {
        float t = xr[threadIdx.x + i * 256];
        v[i] = t; s += t; s2 += t * t;
    }
#pragma unroll
    for (int o = 16; o > 0; o >>= 1) {
        s  += __shfl_xor_sync(0xffffffffu, s,  o);
        s2 += __shfl_xor_sync(0xffffffffu, s2, o);
    }
    __shared__ float ws[8], ws2[8];
    int w = threadIdx.x >> 5, lane = threadIdx.x & 31;
    if (lane == 0) { ws[w] = s; ws2[w] = s2; }
    __syncthreads();
    if (w == 0) {
        s  = (lane < 8) ? ws[lane]  : 0.f;
        s2 = (lane < 8) ? ws2[lane] : 0.f;
#pragma unroll
        for (int o = 4; o > 0; o >>= 1) {
            s  += __shfl_xor_sync(0xffffffffu, s,  o);
            s2 += __shfl_xor_sync(0xffffffffu, s2, o);
        }
        if (lane == 0) { ws[0] = s; ws2[0] = s2; }
    }
    __syncthreads();
    float mean = ws[0] * (1.f / DQ);
    float var  = ws2[0] * (1.f / DQ) - mean * mean;
    float rstd = rsqrtf(var + 1e-5f);
    size_t base = (size_t)row * DQ;
#pragma unroll
    for (int i = 0; i < 4; i++) {
        int c = threadIdx.x + i * 256;
        float yv = (v[i] - mean) * rstd * g[c] + b[c];
        hf h, l; split_hf(yv, h, l);
        yh[base + c] = h;
        yl[base + c] = l;
    }
}

// single-tensor LN (for LN2)
__global__ void ln_kernel(const float* __restrict__ x,
                          const float* __restrict__ g,
                          const float* __restrict__ b,
                          hf* __restrict__ yh, hf* __restrict__ yl) {
    int row = blockIdx.x;
    const float* xr = x + (size_t)row * DQ;
    float v[4];
    float s = 0.f, s2 = 0.f;
#pragma unroll
    for (int i = 0; i < 4; i++) {
        float t = xr[threadIdx.x + i * 256];
        v[i] = t; s += t; s2 += t * t;
    }
#pragma unroll
    for (int o = 16; o > 0; o >>= 1) {
        s  += __shfl_xor_sync(0xffffffffu, s,  o);
        s2 += __shfl_xor_sync(0xffffffffu, s2, o);
    }
    __shared__ float ws[8], ws2[8];
    int w = threadIdx.x >> 5, lane = threadIdx.x & 31;
    if (lane == 0) { ws[w] = s; ws2[w] = s2; }
    __syncthreads();
    if (w == 0) {
        s  = (lane < 8) ? ws[lane]  : 0.f;
        s2 = (lane < 8) ? ws2[lane] : 0.f;
#pragma unroll
        for (int o = 4; o > 0; o >>= 1) {
            s  += __shfl_xor_sync(0xffffffffu, s,  o);
            s2 += __shfl_xor_sync(0xffffffffu, s2, o);
        }
        if (lane == 0) { ws[0] = s; ws2[0] = s2; }
    }
    __syncthreads();
    float mean = ws[0] * (1.f / DQ);
    float var  = ws2[0] * (1.f / DQ) - mean * mean;
    float rstd = rsqrtf(var + 1e-5f);
    size_t base = (size_t)row * DQ;
#pragma unroll
    for (int i = 0; i < 4; i++) {
        int c = threadIdx.x + i * 256;
        float yv = (v[i] - mean) * rstd * g[c] + b[c];
        hf h, l; split_hf(yv, h, l);
        yh[base + c] = h;
        yl[base + c] = l;
    }
}

// ---------------------------------------------------------------------------
// Single fused weight convert: all 6 weights -> SINGLE fp16. 3M float4 entries.
// ---------------------------------------------------------------------------
__global__ void convert_all_kernel(
    const float* __restrict__ wq, const float* __restrict__ wk,
    const float* __restrict__ wv, const float* __restrict__ wo,
    const float* __restrict__ w1, const float* __restrict__ w2,
    hf* __restrict__ base) {
    int i = blockIdx.x * blockDim.x + threadIdx.x;   // 0 .. 3M-1
    const float* w; hf* h; int off;
    if (i < (1 << 20)) {
        int seg = i >> 18;
        off = i & 0x3FFFF;
        w = seg == 0 ? wq : seg == 1 ? wk : seg == 2 ? wv : wo;
        h = base + (size_t)(O_WQ + seg) * EM;
    } else {
        int j = i - (1 << 20);
        int seg = j >> 20;
        off = j & 0xFFFFF;
        w = seg == 0 ? w1 : w2;
        h = base + (size_t)(seg == 0 ? O_W1 : O_W2) * EM;
    }
    float4 v = ((const float4*)w)[off];
    __half2* hp = (__half2*)(h + (size_t)off * 4);
    hp[0] = __halves2half2(__float2half_rn(v.x), __float2half_rn(v.y));
    hp[1] = __halves2half2(__float2half_rn(v.z), __float2half_rn(v.w));
}

// ---------------------------------------------------------------------------
// HMMA GEMM core: A = fp16 hi/lo (exact), B = single fp16. 2 MMAs per tile-term.
// 3-stage cp.async pipeline, pitch-64 XOR swizzle.
// EPI: 1 bias+res->fp32; 2 gelu->hi/lo; 3 bias+C rmw; 4 (acc+bias)*alpha->hi/lo;
//      5 (acc+bias)*alpha->single
// ---------------------------------------------------------------------------
#define MAT_BYTES (128 * 64)
#define STAGE_BYTES (3 * MAT_BYTES)   // 24576
#define GEMM_SMEM (3 * STAGE_BYTES)   // 73728

template <int EPI>
__device__ __forceinline__ void gemm_core(
    const hf* __restrict__ Ah, const hf* __restrict__ Al,
    const hf* __restrict__ B,
    const float* __restrict__ bias, const float* __restrict__ res,
    float* __restrict__ C, hf* __restrict__ Ho, hf* __restrict__ Lo,
    int N, int K, float alpha, size_t m0, size_t n0, char* smc) {
    const int tid = threadIdx.x, lane = tid & 31, wid = tid >> 5;
    const int wm = wid & 1, wn = wid >> 1;
    const uint32_t sbase = smem_u32(smc);

    const hf* gsrc0 = Ah + m0 * K;
    const hf* gsrc1 = Al + m0 * K;
    const hf* gsrc2 = B + n0 * K;

    auto load_stage = [&](int s, int kt) {
        uint32_t base = sbase + s * STAGE_BYTES;
#pragma unroll
        for (int i = 0; i < 6; i++) {
            const int t = i >> 1;
            int idx = tid + (i & 1) * 256;
            int row = idx >> 2, seg = idx & 3;
            const hf* src = (t == 0 ? gsrc0 : t == 1 ? gsrc1 : gsrc2);
            cp16(base + t * MAT_BYTES + swz((uint32_t)row, (uint32_t)(seg * 16)),
                 src + (size_t)row * K + kt + seg * 8);
        }
    };

    float acc[4][4][4];
#pragma unroll
    for (int a = 0; a < 4; a++)
#pragma unroll
        for (int b = 0; b < 4; b++)
#pragma unroll
            for (int c = 0; c < 4; c++) acc[a][b][c] = 0.f;

    const int nk = K >> 5;
    load_stage(0, 0);
    CP_COMMIT();
    load_stage(1, 32);
    CP_COMMIT();

    const uint32_t brow = (uint32_t)(wn * 32 + ((lane >> 4) & 1) * 8 + (lane & 7));
    const uint32_t bcolh = (uint32_t)(((lane >> 3) & 1) * 16);
    const uint32_t arow = (uint32_t)(wm * 64 + (lane & 15));
    const uint32_t acolh = (uint32_t)((lane >> 4) * 16);

    int stage = 0;
    for (int cc = 0; cc < nk; cc++) {
        if (cc + 1 < nk) CP_WAIT1(); else CP_WAIT0();
        __syncthreads();
        if (cc + 2 < nk) {
            int ns = stage + 2; if (ns >= 3) ns -= 3;
            load_stage(ns, (cc + 2) << 5);
            CP_COMMIT();
        }

        uint32_t st = sbase + stage * STAGE_BYTES;
        uint32_t sAh = st, sAl = st + MAT_BYTES;
        uint32_t sB = st + 2 * MAT_BYTES;

        uint32_t Bv[2][8];
#pragma unroll
        for (int k16 = 0; k16 < 2; k16++) {
            uint32_t bcol = (uint32_t)(k16 * 32) + bcolh;
#pragma unroll
            for (int pr = 0; pr < 2; pr++) {
                uint32_t bo = swz(brow + pr * 16, bcol);
                ldmx4(Bv[k16][pr * 4 + 0], Bv[k16][pr * 4 + 1],
                      Bv[k16][pr * 4 + 2], Bv[k16][pr * 4 + 3], sB + bo);
            }
        }

#pragma unroll
        for (int mt = 0; mt < 4; mt++) {
#pragma unroll
            for (int k16 = 0; k16 < 2; k16++) {
                uint32_t ao = swz(arow + mt * 16, (uint32_t)(k16 * 32) + acolh);
                uint32_t ah[4], al[4];
                ldmx4(ah[0], ah[1], ah[2], ah[3], sAh + ao);
                ldmx4(al[0], al[1], al[2], al[3], sAl + ao);
#pragma unroll
                for (int nt = 0; nt < 4; nt++)
                    mma16816(acc[mt][nt], ah, Bv[k16][nt * 2], Bv[k16][nt * 2 + 1]);
#pragma unroll
                for (int nt = 0; nt < 4; nt++)
                    mma16816(acc[mt][nt], al, Bv[k16][nt * 2], Bv[k16][nt * 2 + 1]);
            }
        }
        stage++; if (stage >= 3) stage -= 3;
    }

#pragma unroll
    for (int mt = 0; mt < 4; mt++) {
        int r0 = wm * 64 + mt * 16 + (lane >> 2);
#pragma unroll
        for (int nt = 0; nt < 4; nt++) {
            size_t gcol = n0 + wn * 32 + nt * 8 + (lane & 3) * 2;
            float2 bb = *(const float2*)(bias + gcol);
#pragma unroll
            for (int h = 0; h < 2; h++) {
                size_t grow = m0 + r0 + h * 8;
                size_t idx = grow * (size_t)N + gcol;
                float v0 = acc[mt][nt][h * 2 + 0] + bb.x;
                float v1 = acc[mt][nt][h * 2 + 1] + bb.y;
                if (EPI == 1) {
                    float2 rr = *(const float2*)(res + idx);
                    v0 += rr.x; v1 += rr.y;
                }
                if (EPI == 3) {
                    float2 rr = *(const float2*)(C + idx);
                    v0 += rr.x; v1 += rr.y;
                }
                if (EPI == 2 || EPI == 4) {
                    if (EPI == 2) { v0 = gelu_exact(v0); v1 = gelu_exact(v1); }
                    else          { v0 *= alpha; v1 *= alpha; }
                    hf h0, l0, h1, l1;
                    split_hf(v0, h0, l0); split_hf(v1, h1, l1);
                    *(__half2*)(Ho + idx) = __halves2half2(h0, h1);
                    *(__half2*)(Lo + idx) = __halves2half2(l0, l1);
                } else if (EPI == 5) {
                    v0 *= alpha; v1 *= alpha;
                    *(__half2*)(Ho + idx) =
                        __halves2half2(__float2half_rn(v0), __float2half_rn(v1));
                } else {
                    float2 o; o.x = v0; o.y = v1;
                    *(float2*)(C + idx) = o;
                }
            }
        }
    }
}

template <int EPI>
__global__ void __launch_bounds__(256, 2)
gemm_mma(const hf* __restrict__ Ah, const hf* __restrict__ Al,
         const hf* __restrict__ B,
         const float* __restrict__ bias, const float* __restrict__ res,
         float* __restrict__ C, hf* __restrict__ Ho, hf* __restrict__ Lo,
         int N, int K, float alpha) {
    extern __shared__ char smc[];
    gemm_core<EPI>(Ah, Al, B, bias, res, C, Ho, Lo, N, K, alpha,
                   (size_t)blockIdx.y * 128, (size_t)blockIdx.x * 128, smc);
}

// Fused Q/K/V projection: x 0-7 -> Q (hi/lo), 8-15 -> K (single), 16-23 -> V (single)
__global__ void __launch_bounds__(256, 2)
gemm_qkv(const hf* __restrict__ XQh, const hf* __restrict__ XQl,
         const hf* __restrict__ XKVh, const hf* __restrict__ XKVl,
         const hf* __restrict__ WQ, const hf* __restrict__ WK,
         const hf* __restrict__ WV,
         const float* __restrict__ bq, const float* __restrict__ bk,
         const float* __restrict__ bv,
         hf* __restrict__ QH, hf* __restrict__ QL,
         hf* __restrict__ KK, hf* __restrict__ VV) {
    extern __shared__ char smc[];
    size_t m0 = (size_t)blockIdx.y * 128;
    int xb = blockIdx.x;
    if (xb < 8) {
        gemm_core<4>(XQh, XQl, WQ, bq, nullptr, nullptr, QH, QL,
                     DQ, DQ, 0.125f, m0, (size_t)xb * 128, smc);
    } else if (xb < 16) {
        gemm_core<5>(XKVh, XKVl, WK, bk, nullptr, nullptr, KK, nullptr,
                     DQ, DQ, 1.0f, m0, (size_t)(xb - 8) * 128, smc);
    } else {
        gemm_core<5>(XKVh, XKVl, WV, bv, nullptr, nullptr, VV, nullptr,
                     DQ, DQ, 1.0f, m0, (size_t)(xb - 16) * 128, smc);
    }
}

// ---------------------------------------------------------------------------
// Tensor-core flash attention, softmax-1, fp16.
// Q hi/lo (exact), K/V single fp16 -> 2 MMAs per term. 128 thr, 64 q-rows.
// ---------------------------------------------------------------------------
#define APB 144
#define KV_MAT (64 * APB)            // 9216
#define KV_STAGE (2 * KV_MAT)        // 18432 (K + V single)
#define ATTN_SMEM (2 * KV_STAGE)     // 36864

__global__ void __launch_bounds__(128, 3)
attn_mma(const hf* __restrict__ QHp, const hf* __restrict__ QLp,
         const hf* __restrict__ Kp, const hf* __restrict__ Vp,
         hf* __restrict__ OHp, hf* __restrict__ OLp) {
    extern __shared__ char smc[];
    const uint32_t sb = smem_u32(smc);
    const int tid = threadIdx.x, lane = tid & 31, wid = tid >> 5;
    const int b = blockIdx.z, h = blockIdx.y;
    const int n0 = blockIdx.x * 64;
    const size_t qrow0 = (size_t)b * NN + n0;
    const size_t col0 = (size_t)h * HD;

    // stage Q hi/lo (64 rows) into A-fragments
    {
        const hf* s0 = QHp + qrow0 * DQ + col0;
        const hf* s1 = QLp + qrow0 * DQ + col0;
#pragma unroll
        for (int it = 0; it < 8; it++) {
            int g = it * 128 + tid;
            int m = g >> 9;
            int r = (g & 511) >> 3, c = g & 7;
            const hf* src = m == 0 ? s0 : s1;
            cp16(sb + m * (64 * APB) + r * APB + c * 16, src + (size_t)r * DQ + c * 8);
        }
    }
    CP_COMMIT();
    CP_WAIT0();
    __syncthreads();

    uint32_t qh[4][4], ql[4][4];
#pragma unroll
    for (int k16 = 0; k16 < 4; k16++) {
        uint32_t ao = (uint32_t)(wid * 16 + (lane & 15)) * APB
                    + (uint32_t)(k16 * 16 + (lane >> 4) * 8) * 2;
        ldmx4(qh[k16][0], qh[k16][1], qh[k16][2], qh[k16][3], sb + ao);
        ldmx4(ql[k16][0], ql[k16][1], ql[k16][2], ql[k16][3], sb + 64 * APB + ao);
    }
    __syncthreads();

    const hf* kvsrc[2] = {
        Kp + ((size_t)b * LL) * DQ + col0,
        Vp + ((size_t)b * LL) * DQ + col0
    };
    auto load_kv = [&](int blk, int s) {
        uint32_t base = sb + s * KV_STAGE;
        size_t roff = (size_t)blk * 64;
#pragma unroll
        for (int it = 0; it < 8; it++) {
            int g = it * 128 + tid;            // 0..1023
            int m = g >> 9;                    // 0..1
            int r = (g & 511) >> 3, c = g & 7;
            cp16(base + m * KV_MAT + r * APB + c * 16,
                 kvsrc[m] + (roff + r) * DQ + c * 8);
        }
    };

    float m_[2] = {0.f, 0.f}, l_[2] = {1.f, 1.f};
    float o_[8][4];
#pragma unroll
    for (int d = 0; d < 8; d++)
#pragma unroll
        for (int j = 0; j < 4; j++) o_[d][j] = 0.f;

    load_kv(0, 0);
    CP_COMMIT();

    const int NBLK = LL / 64;
    for (int i = 0; i < NBLK; i++) {
        if (i + 1 < NBLK) { load_kv(i + 1, (i + 1) & 1); CP_COMMIT(); CP_WAIT1(); }
        else CP_WAIT0();
        __syncthreads();

        uint32_t stg = sb + (i & 1) * KV_STAGE;

        float s_[8][4];
#pragma unroll
        for (int nt = 0; nt < 8; nt++)
#pragma unroll
            for (int j = 0; j < 4; j++) s_[nt][j] = 0.f;

#pragma unroll
        for (int k16 = 0; k16 < 4; k16++) {
            uint32_t bcol = (uint32_t)(k16 * 16 + ((lane >> 3) & 1) * 8) * 2;
            uint32_t brow = (uint32_t)(lane & 7);
#pragma unroll
            for (int ntp = 0; ntp < 4; ntp++) {
                int nt0 = 2 * ntp, nt1 = nt0 + 1;
                uint32_t boA = (brow + nt0 * 8) * APB + bcol;
                uint32_t boB = (brow + nt1 * 8) * APB + bcol;
                uint32_t ka0, ka1, kb0, kb1;
                ldmx2(ka0, ka1, stg + boA);
                ldmx2(kb0, kb1, stg + boB);
                mma16816(s_[nt0], qh[k16], ka0, ka1);
                mma16816(s_[nt1], qh[k16], kb0, kb1);
                mma16816(s_[nt0], ql[k16], ka0, ka1);
                mma16816(s_[nt1], ql[k16], kb0, kb1);
            }
        }

#pragma unroll
        for (int hh = 0; hh < 2; hh++) {
            float mx = s_[0][hh * 2];
#pragma unroll
            for (int nt = 0; nt < 8; nt++)
                mx = fmaxf(mx, fmaxf(s_[nt][hh * 2], s_[nt][hh * 2 + 1]));
            mx = fmaxf(mx, __shfl_xor_sync(0xffffffffu, mx, 1));
            mx = fmaxf(mx, __shfl_xor_sync(0xffffffffu, mx, 2));
            float mn = fmaxf(m_[hh], mx);
            float corr = __expf(m_[hh] - mn);
            m_[hh] = mn;
            float sum = 0.f;
#pragma unroll
            for (int nt = 0; nt < 8; nt++) {
                float p0 = __expf(s_[nt][hh * 2] - mn);
                float p1 = __expf(s_[nt][hh * 2 + 1] - mn);
                s_[nt][hh * 2] = p0; s_[nt][hh * 2 + 1] = p1;
                sum += p0 + p1;
            }
            sum += __shfl_xor_sync(0xffffffffu, sum, 1);
            sum += __shfl_xor_sync(0xffffffffu, sum, 2);
            l_[hh] = l_[hh] * corr + sum;
#pragma unroll
            for (int d = 0; d < 8; d++) {
                o_[d][hh * 2] *= corr; o_[d][hh * 2 + 1] *= corr;
            }
        }

        uint32_t ph[4][4], pl[4][4];
#pragma unroll
        for (int j = 0; j < 4; j++) {
            split2pack(s_[2 * j][0], s_[2 * j][1], ph[j][0], pl[j][0]);
            split2pack(s_[2 * j][2], s_[2 * j][3], ph[j][1], pl[j][1]);
            split2pack(s_[2 * j + 1][0], s_[2 * j + 1][1], ph[j][2], pl[j][2]);
            split2pack(s_[2 * j + 1][2], s_[2 * j + 1][3], ph[j][3], pl[j][3]);
        }

        uint32_t vbase = stg + KV_MAT;
#pragma unroll
        for (int j = 0; j < 4; j++) {
            uint32_t vrow = (uint32_t)(j * 16 + (lane & 15)) * APB;
#pragma unroll
            for (int dtp = 0; dtp < 4; dtp++) {
                int dt0 = 2 * dtp, dt1 = dt0 + 1;
                uint32_t voA = vrow + dt0 * 16;
                uint32_t voB = vrow + dt1 * 16;
                uint32_t va0, va1, vb0, vb1;
                ldmx2t(va0, va1, vbase + voA);
                ldmx2t(vb0, vb1, vbase + voB);
                mma16816(o_[dt0], ph[j], va0, va1);
                mma16816(o_[dt1], ph[j], vb0, vb1);
                mma16816(o_[dt0], pl[j], va0, va1);
                mma16816(o_[dt1], pl[j], vb0, vb1);
            }
        }
        __syncthreads();
    }

    float inv0 = 1.f / l_[0], inv1 = 1.f / l_[1];
#pragma unroll
    for (int hh = 0; hh < 2; hh++) {
        float inv = hh == 0 ? inv0 : inv1;
        size_t grow = qrow0 + wid * 16 + (lane >> 2) + hh * 8;
#pragma unroll
        for (int dt = 0; dt < 8; dt++) {
            size_t idx = grow * DQ + col0 + dt * 8 + (lane & 3) * 2;
            float f0 = o_[dt][hh * 2] * inv;
            float f1 = o_[dt][hh * 2 + 1] * inv;
            hf h0, l0, h1, l1;
            split_hf(f0, h0, l0); split_hf(f1, h1, l1);
            *(__half2*)(OHp + idx) = __halves2half2(h0, h1);
            *(__half2*)(OLp + idx) = __halves2half2(l0, l1);
        }
    }
}

// ---------------------------------------------------------------------------
// kernel_launch
// ---------------------------------------------------------------------------
extern "C" void kernel_launch(void* const* d_in, const int* in_sizes, int n_in,
                              void* d_out, int out_size) {
    const float* x_q   = (const float*)d_in[0];
    const float* x_kv  = (const float*)d_in[1];
    const float* qn_g  = (const float*)d_in[2];
    const float* qn_b  = (const float*)d_in[3];
    const float* kvn_g = (const float*)d_in[4];
    const float* kvn_b = (const float*)d_in[5];
    const float* Wq    = (const float*)d_in[6];
    const float* bq    = (const float*)d_in[7];
    const float* Wk    = (const float*)d_in[8];
    const float* bk    = (const float*)d_in[9];
    const float* Wv    = (const float*)d_in[10];
    const float* bv    = (const float*)d_in[11];
    const float* Wo    = (const float*)d_in[12];
    const float* bo    = (const float*)d_in[13];
    const float* n2_g  = (const float*)d_in[14];
    const float* n2_b  = (const float*)d_in[15];
    const float* W1    = (const float*)d_in[16];
    const float* b1    = (const float*)d_in[17];
    const float* W2    = (const float*)d_in[18];
    const float* b2    = (const float*)d_in[19];
    float* out = (float*)d_out;

    hf* hb = nullptr;
    cudaGetSymbolAddress((void**)&hb, g_hf);

    hf* XQH = hb + (size_t)O_XQH * EM;   hf* XQL = hb + (size_t)O_XQL * EM;
    hf* XKVH = hb + (size_t)O_XKVH * EM; hf* XKVL = hb + (size_t)O_XKVL * EM;
    hf* ATTH = hb + (size_t)O_ATTH * EM; hf* ATTL = hb + (size_t)O_ATTL * EM;
    hf* X2H = hb + (size_t)O_X2H * EM;   hf* X2L = hb + (size_t)O_X2L * EM;
    hf* Hh  = hb + (size_t)O_HH * EM;    hf* Hl  = hb + (size_t)O_HL * EM;
    hf* WQh = hb + (size_t)O_WQ * EM;
    hf* WKh = hb + (size_t)O_WK * EM;
    hf* WVh = hb + (size_t)O_WV * EM;
    hf* WOh = hb + (size_t)O_WO * EM;
    hf* W1h = hb + (size_t)O_W1 * EM;
    hf* W2h = hb + (size_t)O_W2 * EM;
    hf* QH  = hb + (size_t)O_QH * EM;    hf* QL  = hb + (size_t)O_QL * EM;
    hf* KK  = hb + (size_t)O_KK * EM;
    hf* VV  = hb + (size_t)O_VV * EM;

    cudaFuncSetAttribute(gemm_mma<1>, cudaFuncAttributeMaxDynamicSharedMemorySize, GEMM_SMEM);
    cudaFuncSetAttribute(gemm_mma<2>, cudaFuncAttributeMaxDynamicSharedMemorySize, GEMM_SMEM);
    cudaFuncSetAttribute(gemm_mma<3>, cudaFuncAttributeMaxDynamicSharedMemorySize, GEMM_SMEM);
    cudaFuncSetAttribute(gemm_qkv, cudaFuncAttributeMaxDynamicSharedMemorySize, GEMM_SMEM);
    cudaFuncSetAttribute(attn_mma, cudaFuncAttributeMaxDynamicSharedMemorySize, ATTN_SMEM);

    // 1: all weight converts (single fp16; 3M float4 -> 12288 blocks)
    convert_all_kernel<<<12288, 256>>>(Wq, Wk, Wv, Wo, W1, W2, hb);

    // 2: both input LNs fused
    ln2x_kernel<<<2 * MROWS, 256>>>(x_q, qn_g, qn_b, XQH, XQL,
                                    x_kv, kvn_g, kvn_b, XKVH, XKVL);

    // 3: fused Q+K+V projection (scale folded into Q)
    gemm_qkv<<<dim3(24, MROWS / 128), 256, GEMM_SMEM>>>(
        XQH, XQL, XKVH, XKVL, WQh, WKh, WVh, bq, bk, bv, QH, QL, KK, VV);

    // 4: tensor-core attention (ncu-profiled launch)
    attn_mma<<<dim3(NN / 64, HH, BB), 128, ATTN_SMEM>>>(
        QH, QL, KK, VV, ATTH, ATTL);

    // 5: out projection + residual with x_q
    gemm_mma<1><<<dim3(DQ / 128, MROWS / 128), 256, GEMM_SMEM>>>(
        ATTH, ATTL, WOh, bo, x_q, out, nullptr, nullptr, DQ, DQ, 1.0f);

    // 6: LN2
    ln_kernel<<<MROWS, 256>>>(out, n2_g, n2_b, X2H, X2L);

    // 7: MLP up + GELU -> fp16 hi/lo
    gemm_mma<2><<<dim3(DFF / 128, MROWS / 128), 256, GEMM_SMEM>>>(
        X2H, X2L, W1h, b1, nullptr, nullptr, Hh, Hl, DFF, DQ, 1.0f);

    // 8: MLP down + residual accumulate into d_out
    gemm_mma<3><<<dim3(DQ / 128, MROWS / 128), 256, GEMM_SMEM>>>(
        Hh, Hl, W2h, b2, nullptr, out, nullptr, nullptr, DQ, DFF, 1.0f);
}

// round 13
// speedup vs baseline: 7.1597x; 1.6182x over previous
#include <cuda_runtime.h>
#include <cuda_fp16.h>
#include <math.h>
#include <stdint.h>

#define BB   2
#define NN   2048
#define LL   2048
#define DQ   1024
#define HH   16
#define HD   64
#define MROWS 4096
#define DFF  4096

typedef __half hf;

// ---------------------------------------------------------------------------
// Static scratch (fp16), offsets in EM elements.
// ---------------------------------------------------------------------------
#define EM (1024u*1024u)
__device__ __align__(256) hf g_hf[60u * EM];

#define O_XQ  0
#define O_XKV 4
#define O_ATT 8
#define O_X2  12
#define O_H   16
#define O_WQ  32
#define O_WK  33
#define O_WV  34
#define O_WO  35
#define O_W1  36
#define O_W2  40
#define O_Q   44
#define O_K   48
#define O_V   52

// ---------------------------------------------------------------------------
// helpers
// ---------------------------------------------------------------------------
__device__ __forceinline__ uint32_t smem_u32(const void* p) {
    uint32_t a;
    asm("{ .reg .u64 t; cvta.to.shared.u64 t, %1; cvt.u32.u64 %0, t; }" : "=r"(a) : "l"(p));
    return a;
}
__device__ __forceinline__ void ldmx4(uint32_t& r0, uint32_t& r1, uint32_t& r2,
                                      uint32_t& r3, uint32_t a) {
    asm volatile("ldmatrix.sync.aligned.m8n8.x4.shared.b16 {%0,%1,%2,%3}, [%4];"
                 : "=r"(r0), "=r"(r1), "=r"(r2), "=r"(r3) : "r"(a));
}
__device__ __forceinline__ void ldmx2(uint32_t& r0, uint32_t& r1, uint32_t a) {
    asm volatile("ldmatrix.sync.aligned.m8n8.x2.shared.b16 {%0,%1}, [%2];"
                 : "=r"(r0), "=r"(r1) : "r"(a));
}
__device__ __forceinline__ void ldmx2t(uint32_t& r0, uint32_t& r1, uint32_t a) {
    asm volatile("ldmatrix.sync.aligned.m8n8.x2.trans.shared.b16 {%0,%1}, [%2];"
                 : "=r"(r0), "=r"(r1) : "r"(a));
}
__device__ __forceinline__ void mma16816(float* d, const uint32_t* a,
                                         uint32_t b0, uint32_t b1) {
    asm volatile(
        "mma.sync.aligned.m16n8k16.row.col.f32.f16.f16.f32 "
        "{%0,%1,%2,%3}, {%4,%5,%6,%7}, {%8,%9}, {%0,%1,%2,%3};"
        : "+f"(d[0]), "+f"(d[1]), "+f"(d[2]), "+f"(d[3])
        : "r"(a[0]), "r"(a[1]), "r"(a[2]), "r"(a[3]), "r"(b0), "r"(b1));
}
__device__ __forceinline__ void cp16(uint32_t dst, const void* src) {
    asm volatile("cp.async.cg.shared.global [%0], [%1], 16;" :: "r"(dst), "l"(src));
}
#define CP_COMMIT() asm volatile("cp.async.commit_group;" ::: "memory")
#define CP_WAIT0()  asm volatile("cp.async.wait_group 0;" ::: "memory")
#define CP_WAIT1()  asm volatile("cp.async.wait_group 1;" ::: "memory")

__device__ __forceinline__ float gelu_exact(float x) {
    return 0.5f * x * (1.f + erff(x * 0.7071067811865476f));
}
__device__ __forceinline__ uint32_t pack2(float a, float b) {
    __half2 H = __halves2half2(__float2half_rn(a), __float2half_rn(b));
    return *(uint32_t*)&H;
}

// GEMM smem swizzle: pitch 64B, 16B chunk XORed with (row>>1)&3.
__device__ __forceinline__ uint32_t swz(uint32_t row, uint32_t colbyte) {
    return row * 64 + ((((colbyte >> 4) ^ (row >> 1)) & 3u) << 4);
}

// ---------------------------------------------------------------------------
// Fused LayerNorm (two tensors) -> single fp16
// ---------------------------------------------------------------------------
__global__ void ln2x_kernel(const float* __restrict__ xA,
                            const float* __restrict__ gA,
                            const float* __restrict__ bA,
                            hf* __restrict__ yA,
                            const float* __restrict__ xB,
                            const float* __restrict__ gB,
                            const float* __restrict__ bB,
                            hf* __restrict__ yB) {
    int row = blockIdx.x;
    const float* x; const float* g; const float* b; hf* y;
    if (row < MROWS) { x = xA; g = gA; b = bA; y = yA; }
    else { x = xB; g = gB; b = bB; y = yB; row -= MROWS; }

    const float* xr = x + (size_t)row * DQ;
    float v[4];
    float s = 0.f, s2 = 0.f;
#pragma unroll
    for (int i = 0; i < 4; i++) {
        float t = xr[threadIdx.x + i * 256];
        v[i] = t; s += t; s2 += t * t;
    }
#pragma unroll
    for (int o = 16; o > 0; o >>= 1) {
        s  += __shfl_xor_sync(0xffffffffu, s,  o);
        s2 += __shfl_xor_sync(0xffffffffu, s2, o);
    }
    __shared__ float ws[8], ws2[8];
    int w = threadIdx.x >> 5, lane = threadIdx.x & 31;
    if (lane == 0) { ws[w] = s; ws2[w] = s2; }
    __syncthreads();
    if (w == 0) {
        s  = (lane < 8) ? ws[lane]  : 0.f;
        s2 = (lane < 8) ? ws2[lane] : 0.f;
#pragma unroll
        for (int o = 4; o > 0; o >>= 1) {
            s  += __shfl_xor_sync(0xffffffffu, s,  o);
            s2 += __shfl_xor_sync(0xffffffffu, s2, o);
        }
        if (lane == 0) { ws[0] = s; ws2[0] = s2; }
    }
    __syncthreads();
    float mean = ws[0] * (1.f / DQ);
    float var  = ws2[0] * (1.f / DQ) - mean * mean;
    float rstd = rsqrtf(var + 1e-5f);
    size_t base = (size_t)row * DQ;
#pragma unroll
    for (int i = 0; i < 4; i++) {
        int c = threadIdx.x + i * 256;
        float yv = (v[i] - mean) * rstd * g[c] + b[c];
        y[base + c] = __float2half_rn(yv);
    }
}

// single-tensor LN (for LN2)
__global__ void ln_kernel(const float* __restrict__ x,
                          const float* __restrict__ g,
                          const float* __restrict__ b,
                          hf* __restrict__ y) {
    int row = blockIdx.x;
    const float* xr = x + (size_t)row * DQ;
    float v[4];
    float s = 0.f, s2 = 0.f;
#pragma unroll
    for (int i = 0; i < 4; i++) {
        float t = xr[threadIdx.x + i * 256];
        v[i] = t; s += t; s2 += t * t;
    }
#pragma unroll
    for (int o = 16; o > 0; o >>= 1) {
        s  += __shfl_xor_sync(0xffffffffu, s,  o);
        s2 += __shfl_xor_sync(0xffffffffu, s2, o);
    }
    __shared__ float ws[8], ws2[8];
    int w = threadIdx.x >> 5, lane = threadIdx.x & 31;
    if (lane == 0) { ws[w] = s; ws2[w] = s2; }
    __syncthreads();
    if (w == 0) {
        s  = (lane < 8) ? ws[lane]  : 0.f;
        s2 = (lane < 8) ? ws2[lane] : 0.f;
#pragma unroll
        for (int o = 4; o > 0; o >>= 1) {
            s  += __shfl_xor_sync(0xffffffffu, s,  o);
            s2 += __shfl_xor_sync(0xffffffffu, s2, o);
        }
        if (lane == 0) { ws[0] = s; ws2[0] = s2; }
    }
    __syncthreads();
    float mean = ws[0] * (1.f / DQ);
    float var  = ws2[0] * (1.f / DQ) - mean * mean;
    float rstd = rsqrtf(var + 1e-5f);
    size_t base = (size_t)row * DQ;
#pragma unroll
    for (int i = 0; i < 4; i++) {
        int c = threadIdx.x + i * 256;
        float yv = (v[i] - mean) * rstd * g[c] + b[c];
        y[base + c] = __float2half_rn(yv);
    }
}

// ---------------------------------------------------------------------------
// Single fused weight convert: all 6 weights -> fp16. 3M float4 entries.
// ---------------------------------------------------------------------------
__global__ void convert_all_kernel(
    const float* __restrict__ wq, const float* __restrict__ wk,
    const float* __restrict__ wv, const float* __restrict__ wo,
    const float* __restrict__ w1, const float* __restrict__ w2,
    hf* __restrict__ base) {
    int i = blockIdx.x * blockDim.x + threadIdx.x;   // 0 .. 3M-1
    const float* w; hf* h; int off;
    if (i < (1 << 20)) {
        int seg = i >> 18;
        off = i & 0x3FFFF;
        w = seg == 0 ? wq : seg == 1 ? wk : seg == 2 ? wv : wo;
        h = base + (size_t)(O_WQ + seg) * EM;
    } else {
        int j = i - (1 << 20);
        int seg = j >> 20;
        off = j & 0xFFFFF;
        w = seg == 0 ? w1 : w2;
        h = base + (size_t)(seg == 0 ? O_W1 : O_W2) * EM;
    }
    float4 v = ((const float4*)w)[off];
    __half2* hp = (__half2*)(h + (size_t)off * 4);
    hp[0] = __halves2half2(__float2half_rn(v.x), __float2half_rn(v.y));
    hp[1] = __halves2half2(__float2half_rn(v.z), __float2half_rn(v.w));
}

// ---------------------------------------------------------------------------
// HMMA GEMM core: pure fp16 operands, fp32 accumulate. 1 MMA per tile-term.
// 3-stage cp.async pipeline, pitch-64 XOR swizzle.
// EPI: 1 bias+res->fp32; 2 gelu->fp16; 3 bias+C rmw; 5 (acc+bias)*alpha->fp16
// ---------------------------------------------------------------------------
#define MAT_BYTES (128 * 64)
#define STAGE_BYTES (2 * MAT_BYTES)   // 16384
#define GEMM_SMEM (3 * STAGE_BYTES)   // 49152

template <int EPI>
__device__ __forceinline__ void gemm_core(
    const hf* __restrict__ A, const hf* __restrict__ B,
    const float* __restrict__ bias, const float* __restrict__ res,
    float* __restrict__ C, hf* __restrict__ Ho,
    int N, int K, float alpha, size_t m0, size_t n0, char* smc) {
    const int tid = threadIdx.x, lane = tid & 31, wid = tid >> 5;
    const int wm = wid & 1, wn = wid >> 1;
    const uint32_t sbase = smem_u32(smc);

    const hf* gsrc0 = A + m0 * K;
    const hf* gsrc1 = B + n0 * K;

    auto load_stage = [&](int s, int kt) {
        uint32_t base = sbase + s * STAGE_BYTES;
#pragma unroll
        for (int i = 0; i < 4; i++) {
            const int t = i >> 1;
            int idx = tid + (i & 1) * 256;
            int row = idx >> 2, seg = idx & 3;
            const hf* src = (t == 0 ? gsrc0 : gsrc1);
            cp16(base + t * MAT_BYTES + swz((uint32_t)row, (uint32_t)(seg * 16)),
                 src + (size_t)row * K + kt + seg * 8);
        }
    };

    float acc[4][4][4];
#pragma unroll
    for (int a = 0; a < 4; a++)
#pragma unroll
        for (int b = 0; b < 4; b++)
#pragma unroll
            for (int c = 0; c < 4; c++) acc[a][b][c] = 0.f;

    const int nk = K >> 5;
    load_stage(0, 0);
    CP_COMMIT();
    load_stage(1, 32);
    CP_COMMIT();

    const uint32_t brow = (uint32_t)(wn * 32 + ((lane >> 4) & 1) * 8 + (lane & 7));
    const uint32_t bcolh = (uint32_t)(((lane >> 3) & 1) * 16);
    const uint32_t arow = (uint32_t)(wm * 64 + (lane & 15));
    const uint32_t acolh = (uint32_t)((lane >> 4) * 16);

    int stage = 0;
    for (int cc = 0; cc < nk; cc++) {
        if (cc + 1 < nk) CP_WAIT1(); else CP_WAIT0();
        __syncthreads();
        if (cc + 2 < nk) {
            int ns = stage + 2; if (ns >= 3) ns -= 3;
            load_stage(ns, (cc + 2) << 5);
            CP_COMMIT();
        }

        uint32_t st = sbase + stage * STAGE_BYTES;
        uint32_t sA = st, sB = st + MAT_BYTES;

        uint32_t Bv[2][8];
#pragma unroll
        for (int k16 = 0; k16 < 2; k16++) {
            uint32_t bcol = (uint32_t)(k16 * 32) + bcolh;
#pragma unroll
            for (int pr = 0; pr < 2; pr++) {
                uint32_t bo = swz(brow + pr * 16, bcol);
                ldmx4(Bv[k16][pr * 4 + 0], Bv[k16][pr * 4 + 1],
                      Bv[k16][pr * 4 + 2], Bv[k16][pr * 4 + 3], sB + bo);
            }
        }

#pragma unroll
        for (int mt = 0; mt < 4; mt++) {
#pragma unroll
            for (int k16 = 0; k16 < 2; k16++) {
                uint32_t ao = swz(arow + mt * 16, (uint32_t)(k16 * 32) + acolh);
                uint32_t av[4];
                ldmx4(av[0], av[1], av[2], av[3], sA + ao);
#pragma unroll
                for (int nt = 0; nt < 4; nt++)
                    mma16816(acc[mt][nt], av, Bv[k16][nt * 2], Bv[k16][nt * 2 + 1]);
            }
        }
        stage++; if (stage >= 3) stage -= 3;
    }

#pragma unroll
    for (int mt = 0; mt < 4; mt++) {
        int r0 = wm * 64 + mt * 16 + (lane >> 2);
#pragma unroll
        for (int nt = 0; nt < 4; nt++) {
            size_t gcol = n0 + wn * 32 + nt * 8 + (lane & 3) * 2;
            float2 bb = *(const float2*)(bias + gcol);
#pragma unroll
            for (int h = 0; h < 2; h++) {
                size_t grow = m0 + r0 + h * 8;
                size_t idx = grow * (size_t)N + gcol;
                float v0 = acc[mt][nt][h * 2 + 0] + bb.x;
                float v1 = acc[mt][nt][h * 2 + 1] + bb.y;
                if (EPI == 1) {
                    float2 rr = *(const float2*)(res + idx);
                    v0 += rr.x; v1 += rr.y;
                }
                if (EPI == 3) {
                    float2 rr = *(const float2*)(C + idx);
                    v0 += rr.x; v1 += rr.y;
                }
                if (EPI == 2) {
                    v0 = gelu_exact(v0); v1 = gelu_exact(v1);
                    *(__half2*)(Ho + idx) =
                        __halves2half2(__float2half_rn(v0), __float2half_rn(v1));
                } else if (EPI == 5) {
                    v0 *= alpha; v1 *= alpha;
                    *(__half2*)(Ho + idx) =
                        __halves2half2(__float2half_rn(v0), __float2half_rn(v1));
                } else {
                    float2 o; o.x = v0; o.y = v1;
                    *(float2*)(C + idx) = o;
                }
            }
        }
    }
}

template <int EPI>
__global__ void __launch_bounds__(256, 2)
gemm_mma(const hf* __restrict__ A, const hf* __restrict__ B,
         const float* __restrict__ bias, const float* __restrict__ res,
         float* __restrict__ C, hf* __restrict__ Ho,
         int N, int K, float alpha) {
    extern __shared__ char smc[];
    gemm_core<EPI>(A, B, bias, res, C, Ho, N, K, alpha,
                   (size_t)blockIdx.y * 128, (size_t)blockIdx.x * 128, smc);
}

// Fused Q/K/V projection
__global__ void __launch_bounds__(256, 2)
gemm_qkv(const hf* __restrict__ XQ, const hf* __restrict__ XKV,
         const hf* __restrict__ WQ, const hf* __restrict__ WK,
         const hf* __restrict__ WV,
         const float* __restrict__ bq, const float* __restrict__ bk,
         const float* __restrict__ bv,
         hf* __restrict__ Q, hf* __restrict__ K, hf* __restrict__ V) {
    extern __shared__ char smc[];
    size_t m0 = (size_t)blockIdx.y * 128;
    int xb = blockIdx.x;
    if (xb < 8) {
        gemm_core<5>(XQ, WQ, bq, nullptr, nullptr, Q,
                     DQ, DQ, 0.125f, m0, (size_t)xb * 128, smc);
    } else if (xb < 16) {
        gemm_core<5>(XKV, WK, bk, nullptr, nullptr, K,
                     DQ, DQ, 1.0f, m0, (size_t)(xb - 8) * 128, smc);
    } else {
        gemm_core<5>(XKV, WV, bv, nullptr, nullptr, V,
                     DQ, DQ, 1.0f, m0, (size_t)(xb - 16) * 128, smc);
    }
}

// ---------------------------------------------------------------------------
// Tensor-core flash attention, softmax-1, pure fp16 operands.
// 128 threads x 64 q-rows, 4 CTAs/SM co-resident.
// ---------------------------------------------------------------------------
#define APB 144
#define KV_MAT (64 * APB)            // 9216
#define KV_STAGE (2 * KV_MAT)        // 18432
#define ATTN_SMEM (2 * KV_STAGE)     // 36864

__global__ void __launch_bounds__(128, 4)
attn_mma(const hf* __restrict__ Qp, const hf* __restrict__ Kp,
         const hf* __restrict__ Vp, hf* __restrict__ Op) {
    extern __shared__ char smc[];
    const uint32_t sb = smem_u32(smc);
    const int tid = threadIdx.x, lane = tid & 31, wid = tid >> 5;
    const int b = blockIdx.z, h = blockIdx.y;
    const int n0 = blockIdx.x * 64;
    const size_t qrow0 = (size_t)b * NN + n0;
    const size_t col0 = (size_t)h * HD;

    // stage Q (64 rows) into A-fragments
    {
        const hf* s0 = Qp + qrow0 * DQ + col0;
#pragma unroll
        for (int it = 0; it < 4; it++) {
            int g = it * 128 + tid;            // 0..511
            int r = g >> 3, c = g & 7;
            cp16(sb + r * APB + c * 16, s0 + (size_t)r * DQ + c * 8);
        }
    }
    CP_COMMIT();
    CP_WAIT0();
    __syncthreads();

    uint32_t qv[4][4];
#pragma unroll
    for (int k16 = 0; k16 < 4; k16++) {
        uint32_t ao = (uint32_t)(wid * 16 + (lane & 15)) * APB
                    + (uint32_t)(k16 * 16 + (lane >> 4) * 8) * 2;
        ldmx4(qv[k16][0], qv[k16][1], qv[k16][2], qv[k16][3], sb + ao);
    }
    __syncthreads();

    const hf* ksrc = Kp + ((size_t)b * LL) * DQ + col0;
    const hf* vsrc = Vp + ((size_t)b * LL) * DQ + col0;
    auto load_kv = [&](int blk, int s) {
        uint32_t base = sb + s * KV_STAGE;
        size_t roff = (size_t)blk * 64;
#pragma unroll
        for (int it = 0; it < 8; it++) {
            int g = it * 128 + tid;            // 0..1023
            int m = g >> 9;                    // 0 K, 1 V
            int r = (g & 511) >> 3, c = g & 7;
            const hf* src = m == 0 ? ksrc : vsrc;
            cp16(base + m * KV_MAT + r * APB + c * 16,
                 src + (roff + r) * DQ + c * 8);
        }
    };

    float m_[2] = {0.f, 0.f}, l_[2] = {1.f, 1.f};
    float o_[8][4];
#pragma unroll
    for (int d = 0; d < 8; d++)
#pragma unroll
        for (int j = 0; j < 4; j++) o_[d][j] = 0.f;

    load_kv(0, 0);
    CP_COMMIT();

    const int NBLK = LL / 64;
    for (int i = 0; i < NBLK; i++) {
        if (i + 1 < NBLK) { load_kv(i + 1, (i + 1) & 1); CP_COMMIT(); CP_WAIT1(); }
        else CP_WAIT0();
        __syncthreads();

        uint32_t stg = sb + (i & 1) * KV_STAGE;

        float s_[8][4];
#pragma unroll
        for (int nt = 0; nt < 8; nt++)
#pragma unroll
            for (int j = 0; j < 4; j++) s_[nt][j] = 0.f;

#pragma unroll
        for (int k16 = 0; k16 < 4; k16++) {
            uint32_t bcol = (uint32_t)(k16 * 16 + ((lane >> 3) & 1) * 8) * 2;
            uint32_t brow = (uint32_t)(lane & 7);
#pragma unroll
            for (int ntp = 0; ntp < 4; ntp++) {
                int nt0 = 2 * ntp, nt1 = nt0 + 1;
                uint32_t ka0, ka1, kb0, kb1;
                ldmx2(ka0, ka1, stg + (brow + nt0 * 8) * APB + bcol);
                ldmx2(kb0, kb1, stg + (brow + nt1 * 8) * APB + bcol);
                mma16816(s_[nt0], qv[k16], ka0, ka1);
                mma16816(s_[nt1], qv[k16], kb0, kb1);
            }
        }

#pragma unroll
        for (int hh = 0; hh < 2; hh++) {
            float mx = s_[0][hh * 2];
#pragma unroll
            for (int nt = 0; nt < 8; nt++)
                mx = fmaxf(mx, fmaxf(s_[nt][hh * 2], s_[nt][hh * 2 + 1]));
            mx = fmaxf(mx, __shfl_xor_sync(0xffffffffu, mx, 1));
            mx = fmaxf(mx, __shfl_xor_sync(0xffffffffu, mx, 2));
            float mn = fmaxf(m_[hh], mx);
            float corr = __expf(m_[hh] - mn);
            m_[hh] = mn;
            float sum = 0.f;
#pragma unroll
            for (int nt = 0; nt < 8; nt++) {
                float p0 = __expf(s_[nt][hh * 2] - mn);
                float p1 = __expf(s_[nt][hh * 2 + 1] - mn);
                s_[nt][hh * 2] = p0; s_[nt][hh * 2 + 1] = p1;
                sum += p0 + p1;
            }
            sum += __shfl_xor_sync(0xffffffffu, sum, 1);
            sum += __shfl_xor_sync(0xffffffffu, sum, 2);
            l_[hh] = l_[hh] * corr + sum;
#pragma unroll
            for (int d = 0; d < 8; d++) {
                o_[d][hh * 2] *= corr; o_[d][hh * 2 + 1] *= corr;
            }
        }

        // pack P (single fp16)
        uint32_t ph[4][4];
#pragma unroll
        for (int j = 0; j < 4; j++) {
            ph[j][0] = pack2(s_[2 * j][0], s_[2 * j][1]);
            ph[j][1] = pack2(s_[2 * j][2], s_[2 * j][3]);
            ph[j][2] = pack2(s_[2 * j + 1][0], s_[2 * j + 1][1]);
            ph[j][3] = pack2(s_[2 * j + 1][2], s_[2 * j + 1][3]);
        }

        uint32_t vbase = stg + KV_MAT;
#pragma unroll
        for (int j = 0; j < 4; j++) {
            uint32_t vrow = (uint32_t)(j * 16 + (lane & 15)) * APB;
#pragma unroll
            for (int dtp = 0; dtp < 4; dtp++) {
                int dt0 = 2 * dtp, dt1 = dt0 + 1;
                uint32_t va0, va1, vb0, vb1;
                ldmx2t(va0, va1, vbase + vrow + dt0 * 16);
                ldmx2t(vb0, vb1, vbase + vrow + dt1 * 16);
                mma16816(o_[dt0], ph[j], va0, va1);
                mma16816(o_[dt1], ph[j], vb0, vb1);
            }
        }
        __syncthreads();
    }

    float inv0 = 1.f / l_[0], inv1 = 1.f / l_[1];
#pragma unroll
    for (int hh = 0; hh < 2; hh++) {
        float inv = hh == 0 ? inv0 : inv1;
        size_t grow = qrow0 + wid * 16 + (lane >> 2) + hh * 8;
#pragma unroll
        for (int dt = 0; dt < 8; dt++) {
            size_t idx = grow * DQ + col0 + dt * 8 + (lane & 3) * 2;
            *(__half2*)(Op + idx) =
                __halves2half2(__float2half_rn(o_[dt][hh * 2] * inv),
                               __float2half_rn(o_[dt][hh * 2 + 1] * inv));
        }
    }
}

// ---------------------------------------------------------------------------
// kernel_launch
// ---------------------------------------------------------------------------
extern "C" void kernel_launch(void* const* d_in, const int* in_sizes, int n_in,
                              void* d_out, int out_size) {
    const float* x_q   = (const float*)d_in[0];
    const float* x_kv  = (const float*)d_in[1];
    const float* qn_g  = (const float*)d_in[2];
    const float* qn_b  = (const float*)d_in[3];
    const float* kvn_g = (const float*)d_in[4];
    const float* kvn_b = (const float*)d_in[5];
    const float* Wq    = (const float*)d_in[6];
    const float* bq    = (const float*)d_in[7];
    const float* Wk    = (const float*)d_in[8];
    const float* bk    = (const float*)d_in[9];
    const float* Wv    = (const float*)d_in[10];
    const float* bv    = (const float*)d_in[11];
    const float* Wo    = (const float*)d_in[12];
    const float* bo    = (const float*)d_in[13];
    const float* n2_g  = (const float*)d_in[14];
    const float* n2_b  = (const float*)d_in[15];
    const float* W1    = (const float*)d_in[16];
    const float* b1    = (const float*)d_in[17];
    const float* W2    = (const float*)d_in[18];
    const float* b2    = (const float*)d_in[19];
    float* out = (float*)d_out;

    hf* hb = nullptr;
    cudaGetSymbolAddress((void**)&hb, g_hf);

    hf* XQ  = hb + (size_t)O_XQ * EM;
    hf* XKV = hb + (size_t)O_XKV * EM;
    hf* ATT = hb + (size_t)O_ATT * EM;
    hf* X2  = hb + (size_t)O_X2 * EM;
    hf* Hb  = hb + (size_t)O_H * EM;
    hf* WQh = hb + (size_t)O_WQ * EM;
    hf* WKh = hb + (size_t)O_WK * EM;
    hf* WVh = hb + (size_t)O_WV * EM;
    hf* WOh = hb + (size_t)O_WO * EM;
    hf* W1h = hb + (size_t)O_W1 * EM;
    hf* W2h = hb + (size_t)O_W2 * EM;
    hf* Qb  = hb + (size_t)O_Q * EM;
    hf* Kb  = hb + (size_t)O_K * EM;
    hf* Vb  = hb + (size_t)O_V * EM;

    cudaFuncSetAttribute(gemm_mma<1>, cudaFuncAttributeMaxDynamicSharedMemorySize, GEMM_SMEM);
    cudaFuncSetAttribute(gemm_mma<2>, cudaFuncAttributeMaxDynamicSharedMemorySize, GEMM_SMEM);
    cudaFuncSetAttribute(gemm_mma<3>, cudaFuncAttributeMaxDynamicSharedMemorySize, GEMM_SMEM);
    cudaFuncSetAttribute(gemm_qkv, cudaFuncAttributeMaxDynamicSharedMemorySize, GEMM_SMEM);
    cudaFuncSetAttribute(attn_mma, cudaFuncAttributeMaxDynamicSharedMemorySize, ATTN_SMEM);

    // 1: all weight converts (3M float4 -> 12288 blocks)
    convert_all_kernel<<<12288, 256>>>(Wq, Wk, Wv, Wo, W1, W2, hb);

    // 2: both input LNs fused
    ln2x_kernel<<<2 * MROWS, 256>>>(x_q, qn_g, qn_b, XQ,
                                    x_kv, kvn_g, kvn_b, XKV);

    // 3: fused Q+K+V projection (scale folded into Q)
    gemm_qkv<<<dim3(24, MROWS / 128), 256, GEMM_SMEM>>>(
        XQ, XKV, WQh, WKh, WVh, bq, bk, bv, Qb, Kb, Vb);

    // 4: tensor-core attention (ncu-profiled launch)
    attn_mma<<<dim3(NN / 64, HH, BB), 128, ATTN_SMEM>>>(Qb, Kb, Vb, ATT);

    // 5: out projection + residual with x_q
    gemm_mma<1><<<dim3(DQ / 128, MROWS / 128), 256, GEMM_SMEM>>>(
        ATT, WOh, bo, x_q, out, nullptr, DQ, DQ, 1.0f);

    // 6: LN2
    ln_kernel<<<MROWS, 256>>>(out, n2_g, n2_b, X2);

    // 7: MLP up + GELU -> fp16
    gemm_mma<2><<<dim3(DFF / 128, MROWS / 128), 256, GEMM_SMEM>>>(
        X2, W1h, b1, nullptr, nullptr, Hb, DFF, DQ, 1.0f);

    // 8: MLP down + residual accumulate into d_out
    gemm_mma<3><<<dim3(DQ / 128, MROWS / 128), 256, GEMM_SMEM>>>(
        Hb, W2h, b2, nullptr, out, nullptr, DQ, DFF, 1.0f);
}